// round 5
// baseline (speedup 1.0000x reference)
#include <cuda_runtime.h>
#include <cuda_bf16.h>
#include <math.h>

#define TT 2048
#define DD 1024
#define HH 1024
#define NBLK 16
#define LYR 4
#define RANKK 64
#define NMEM 64
#define VV 50304
#define RMS_EPS 1.1920929e-7f
#define SEGLEN 32
#define NSEG 64

// ---------------- scratch (static device arrays; no allocation) ----------------
__device__ float g_x[TT * DD];
__device__ float g_e[TT * DD];
__device__ float g_h[TT * DD];     // drive_seq -> h_seq (scan in place)
__device__ float g_ud[TT * DD];    // depth drive
__device__ float g_c[TT * 3 * DD]; // concat [hn, e, shifted]
__device__ float g_r[TT * DD];
__device__ float g_tmp[TT * RANKK];
__device__ float g_xn[TT * DD];
__device__ float g_seg[NSEG * DD];

// ---------------- helpers ----------------
__device__ __forceinline__ float silu_f(float x) { return x / (1.0f + expf(-x)); }

__device__ __forceinline__ float tf32r(float x) {
    unsigned u;
    asm("cvt.rna.tf32.f32 %0, %1;" : "=r"(u) : "f"(x));
    return __uint_as_float(u);
}

// ---------------- embedding ----------------
__global__ void embed_kernel(const int* __restrict__ idx, const float* __restrict__ wte,
                             const float* __restrict__ wpe, float* __restrict__ x) {
    int t = blockIdx.x;
    int row = idx[t];
    const float4* wrow = (const float4*)(wte + (long)row * DD);
    const float4* prow = (const float4*)(wpe + (long)t * DD);
    float4* xo = (float4*)(x + t * DD);
    for (int d = threadIdx.x; d < DD / 4; d += blockDim.x) {
        float4 a = wrow[d], b = prow[d];
        xo[d] = make_float4(a.x + b.x, a.y + b.y, a.z + b.z, a.w + b.w);
    }
}

// ---------------- rmsnorm ----------------
__global__ void rmsnorm_kernel(const float* __restrict__ in, float* __restrict__ out) {
    int t = blockIdx.x;
    int tid = threadIdx.x;
    float4 v = ((const float4*)(in + t * DD))[tid];
    float ss = v.x * v.x + v.y * v.y + v.z * v.z + v.w * v.w;
    __shared__ float red[256];
    red[tid] = ss;
    __syncthreads();
    for (int s = 128; s > 0; s >>= 1) {
        if (tid < s) red[tid] += red[tid + s];
        __syncthreads();
    }
    float sc = rsqrtf(red[0] / (float)DD + RMS_EPS);
    ((float4*)(out + t * DD))[tid] = make_float4(v.x * sc, v.y * sc, v.z * sc, v.w * sc);
}

// ============ dual block-diagonal GEMM, K=64, silu: h=silu(e@W1^T), ud=silu(e@W2^T) =======
// grid (TT/64, NBLK), block 256. Output tile [64 t][64 o] for block n, for BOTH weights.
__global__ void __launch_bounds__(256)
bd64_dual_kernel(const float* __restrict__ in, const float* __restrict__ W1,
                 const float* __restrict__ W2, float* __restrict__ out1,
                 float* __restrict__ out2) {
    __shared__ float As[64 * 64];   // [t][k]
    __shared__ float Ws1[64 * 64];  // [k][o]
    __shared__ float Ws2[64 * 64];
    const int t0 = blockIdx.x * 64;
    const int n = blockIdx.y;
    const int tid = threadIdx.x;
    const int tx = tid & 15, ty = tid >> 4;

    for (int i = tid; i < 1024; i += 256) {
        int t = i >> 4, kc = (i & 15) << 2;
        *(float4*)&As[t * 64 + kc] = *(const float4*)&in[(t0 + t) * DD + n * 64 + kc];
    }
    for (int i = tid; i < 1024; i += 256) {
        int o = i >> 4, kc = (i & 15) << 2;
        float4 w = *(const float4*)&W1[(n * 64 + o) * 64 + kc];
        Ws1[(kc + 0) * 64 + o] = w.x; Ws1[(kc + 1) * 64 + o] = w.y;
        Ws1[(kc + 2) * 64 + o] = w.z; Ws1[(kc + 3) * 64 + o] = w.w;
        float4 u = *(const float4*)&W2[(n * 64 + o) * 64 + kc];
        Ws2[(kc + 0) * 64 + o] = u.x; Ws2[(kc + 1) * 64 + o] = u.y;
        Ws2[(kc + 2) * 64 + o] = u.z; Ws2[(kc + 3) * 64 + o] = u.w;
    }
    __syncthreads();

    float acc1[4][4] = {}, acc2[4][4] = {};
#pragma unroll 4
    for (int k = 0; k < 64; k++) {
        float a[4];
#pragma unroll
        for (int q = 0; q < 4; q++) a[q] = As[(ty * 4 + q) * 64 + k];
        float4 b1 = *(float4*)&Ws1[k * 64 + tx * 4];
        float4 b2 = *(float4*)&Ws2[k * 64 + tx * 4];
#pragma unroll
        for (int q = 0; q < 4; q++) {
            acc1[q][0] += a[q] * b1.x; acc1[q][1] += a[q] * b1.y;
            acc1[q][2] += a[q] * b1.z; acc1[q][3] += a[q] * b1.w;
            acc2[q][0] += a[q] * b2.x; acc2[q][1] += a[q] * b2.y;
            acc2[q][2] += a[q] * b2.z; acc2[q][3] += a[q] * b2.w;
        }
    }
#pragma unroll
    for (int q = 0; q < 4; q++) {
        int row = t0 + ty * 4 + q;
        float4 v1 = make_float4(silu_f(acc1[q][0]), silu_f(acc1[q][1]),
                                silu_f(acc1[q][2]), silu_f(acc1[q][3]));
        float4 v2 = make_float4(silu_f(acc2[q][0]), silu_f(acc2[q][1]),
                                silu_f(acc2[q][2]), silu_f(acc2[q][3]));
        *(float4*)&out1[row * HH + n * 64 + tx * 4] = v1;
        *(float4*)&out2[row * HH + n * 64 + tx * 4] = v2;
    }
}

// ============ block-diagonal GEMM, K=192 (wpost), silu ============
__global__ void __launch_bounds__(256)
bd192_kernel(const float* __restrict__ in, const float* __restrict__ W,
             float* __restrict__ out) {
    __shared__ float As[64 * 64];
    __shared__ float Ws[64 * 64];
    const int t0 = blockIdx.x * 64;
    const int n = blockIdx.y;
    const int tid = threadIdx.x;
    const int tx = tid & 15, ty = tid >> 4;

    float acc[4][4] = {};
    for (int c = 0; c < 3; c++) {
        for (int i = tid; i < 1024; i += 256) {
            int t = i >> 4, kc = (i & 15) << 2;
            *(float4*)&As[t * 64 + kc] =
                *(const float4*)&in[(t0 + t) * 3 * DD + n * 192 + c * 64 + kc];
        }
        for (int i = tid; i < 1024; i += 256) {
            int o = i >> 4, kc = (i & 15) << 2;
            float4 w = *(const float4*)&W[(n * 64 + o) * 192 + c * 64 + kc];
            Ws[(kc + 0) * 64 + o] = w.x; Ws[(kc + 1) * 64 + o] = w.y;
            Ws[(kc + 2) * 64 + o] = w.z; Ws[(kc + 3) * 64 + o] = w.w;
        }
        __syncthreads();
#pragma unroll 4
        for (int k = 0; k < 64; k++) {
            float a[4];
#pragma unroll
            for (int q = 0; q < 4; q++) a[q] = As[(ty * 4 + q) * 64 + k];
            float4 b = *(float4*)&Ws[k * 64 + tx * 4];
#pragma unroll
            for (int q = 0; q < 4; q++) {
                acc[q][0] += a[q] * b.x; acc[q][1] += a[q] * b.y;
                acc[q][2] += a[q] * b.z; acc[q][3] += a[q] * b.w;
            }
        }
        __syncthreads();
    }
#pragma unroll
    for (int q = 0; q < 4; q++) {
        int row = t0 + ty * 4 + q;
        float4 v = make_float4(silu_f(acc[q][0]), silu_f(acc[q][1]),
                               silu_f(acc[q][2]), silu_f(acc[q][3]));
        *(float4*)&out[row * HH + n * 64 + tx * 4] = v;
    }
}

// ============ residual update: x += blockdiag(r, wlocal) + tmp @ lowA^T ============
__global__ void __launch_bounds__(256)
update_kernel(float* __restrict__ x, const float* __restrict__ r,
              const float* __restrict__ tmp, const float* __restrict__ wlocal,
              const float* __restrict__ lowA) {
    __shared__ float As[64 * 64];
    __shared__ float Ws[64 * 64];
    const int t0 = blockIdx.x * 64;
    const int n = blockIdx.y;
    const int tid = threadIdx.x;
    const int tx = tid & 15, ty = tid >> 4;

    float acc[4][4] = {};
    // phase 1: wlocal (K=64 over r block n)
    for (int i = tid; i < 1024; i += 256) {
        int t = i >> 4, kc = (i & 15) << 2;
        *(float4*)&As[t * 64 + kc] = *(const float4*)&r[(t0 + t) * HH + n * 64 + kc];
    }
    for (int i = tid; i < 1024; i += 256) {
        int o = i >> 4, kc = (i & 15) << 2;
        float4 w = *(const float4*)&wlocal[(n * 64 + o) * 64 + kc];
        Ws[(kc + 0) * 64 + o] = w.x; Ws[(kc + 1) * 64 + o] = w.y;
        Ws[(kc + 2) * 64 + o] = w.z; Ws[(kc + 3) * 64 + o] = w.w;
    }
    __syncthreads();
#pragma unroll 4
    for (int k = 0; k < 64; k++) {
        float a[4];
#pragma unroll
        for (int q = 0; q < 4; q++) a[q] = As[(ty * 4 + q) * 64 + k];
        float4 b = *(float4*)&Ws[k * 64 + tx * 4];
#pragma unroll
        for (int q = 0; q < 4; q++) {
            acc[q][0] += a[q] * b.x; acc[q][1] += a[q] * b.y;
            acc[q][2] += a[q] * b.z; acc[q][3] += a[q] * b.w;
        }
    }
    __syncthreads();
    // phase 2: lowA (K=64 over tmp)
    for (int i = tid; i < 1024; i += 256) {
        int t = i >> 4, kc = (i & 15) << 2;
        *(float4*)&As[t * 64 + kc] = *(const float4*)&tmp[(t0 + t) * RANKK + kc];
    }
    for (int i = tid; i < 1024; i += 256) {
        int o = i >> 4, kc = (i & 15) << 2;
        float4 w = *(const float4*)&lowA[(n * 64 + o) * RANKK + kc];
        Ws[(kc + 0) * 64 + o] = w.x; Ws[(kc + 1) * 64 + o] = w.y;
        Ws[(kc + 2) * 64 + o] = w.z; Ws[(kc + 3) * 64 + o] = w.w;
    }
    __syncthreads();
#pragma unroll 4
    for (int k = 0; k < 64; k++) {
        float a[4];
#pragma unroll
        for (int q = 0; q < 4; q++) a[q] = As[(ty * 4 + q) * 64 + k];
        float4 b = *(float4*)&Ws[k * 64 + tx * 4];
#pragma unroll
        for (int q = 0; q < 4; q++) {
            acc[q][0] += a[q] * b.x; acc[q][1] += a[q] * b.y;
            acc[q][2] += a[q] * b.z; acc[q][3] += a[q] * b.w;
        }
    }
#pragma unroll
    for (int q = 0; q < 4; q++) {
        int row = t0 + ty * 4 + q;
        float4* px = (float4*)&x[row * DD + n * 64 + tx * 4];
        float4 v = *px;
        v.x += acc[q][0]; v.y += acc[q][1]; v.z += acc[q][2]; v.w += acc[q][3];
        *px = v;
    }
}

// ============ lowrank stage 1: tmp[2048,64] = r[2048,1024] @ lowB^T ============
// grid TT/16, block 256. Thread: 1 t-row, 4 outputs.
__global__ void __launch_bounds__(256)
lowrank1_kernel(const float* __restrict__ r, const float* __restrict__ lowB,
                float* __restrict__ tmp) {
    __shared__ float As[16 * 64];
    __shared__ float Ws[64 * 64];
    const int t0 = blockIdx.x * 16;
    const int tid = threadIdx.x;
    const int tx = tid & 15, ty = tid >> 4;  // ty = t (0..15), tx*4 = o
    float acc[4] = {};
    for (int c = 0; c < 16; c++) {
        {
            int t = tid >> 4, kc = (tid & 15) << 2;
            *(float4*)&As[t * 64 + kc] = *(const float4*)&r[(t0 + t) * HH + c * 64 + kc];
        }
        for (int i = tid; i < 1024; i += 256) {
            int o = i >> 4, kc = (i & 15) << 2;
            float4 w = *(const float4*)&lowB[o * HH + c * 64 + kc];
            Ws[(kc + 0) * 64 + o] = w.x; Ws[(kc + 1) * 64 + o] = w.y;
            Ws[(kc + 2) * 64 + o] = w.z; Ws[(kc + 3) * 64 + o] = w.w;
        }
        __syncthreads();
#pragma unroll 8
        for (int k = 0; k < 64; k++) {
            float a = As[ty * 64 + k];
            float4 b = *(float4*)&Ws[k * 64 + tx * 4];
            acc[0] += a * b.x; acc[1] += a * b.y; acc[2] += a * b.z; acc[3] += a * b.w;
        }
        __syncthreads();
    }
    *(float4*)&tmp[(t0 + ty) * RANKK + tx * 4] = make_float4(acc[0], acc[1], acc[2], acc[3]);
}

// ============ causal scan, 3-phase chunked ============
__global__ void scanA_kernel(float* __restrict__ buf, const float* __restrict__ logA,
                             const float* __restrict__ logdt, float* __restrict__ seg) {
    int d = blockIdx.x * 32 + threadIdx.x;
    int s = blockIdx.y * 8 + threadIdx.y;
    float a = expf(-expf(logA[d]) * expf(logdt[d]));
    float y = 0.f;
    int t0 = s * SEGLEN;
#pragma unroll 8
    for (int tt = 0; tt < SEGLEN; tt++) {
        int i = (t0 + tt) * DD + d;
        y = a * y + buf[i];
        buf[i] = y;
    }
    seg[s * DD + d] = y;
}

__global__ void scanB_kernel(float* __restrict__ seg, const float* __restrict__ logA,
                             const float* __restrict__ logdt) {
    int d = blockIdx.x * 16 + threadIdx.x;
    int j = threadIdx.y;  // 0..63
    float a = expf(-expf(logA[d]) * expf(logdt[d]));
    float a32 = a;
#pragma unroll
    for (int q = 0; q < 5; q++) a32 *= a32;
    __shared__ float s[NSEG][17];
    float cur = seg[j * DD + d];
    s[j][threadIdx.x] = cur;
    float m = a32;
    for (int st = 1; st < NSEG; st <<= 1) {
        __syncthreads();
        float prev = (j >= st) ? s[j - st][threadIdx.x] : 0.f;
        __syncthreads();
        cur += m * prev;
        s[j][threadIdx.x] = cur;
        m = m * m;
    }
    seg[j * DD + d] = cur;
}

__global__ void scanC_kernel(float* __restrict__ buf, const float* __restrict__ logA,
                             const float* __restrict__ logdt, const float* __restrict__ seg) {
    int d = blockIdx.x * 32 + threadIdx.x;
    int s = blockIdx.y * 8 + threadIdx.y;
    if (s == 0) return;
    float a = expf(-expf(logA[d]) * expf(logdt[d]));
    float carry = seg[(s - 1) * DD + d];
    float f = a;
    int t0 = s * SEGLEN;
#pragma unroll 8
    for (int tt = 0; tt < SEGLEN; tt++) {
        int i = (t0 + tt) * DD + d;
        buf[i] += f * carry;
        f *= a;
    }
}

// ---------------- h = h_seq + gain*u_dep ; rmsnorm(h) ; build concat ----------------
__global__ void combine_prep_kernel(const float* __restrict__ hseq, const float* __restrict__ udep,
                                    const float* __restrict__ e, const float* __restrict__ logAd,
                                    const float* __restrict__ logdtd, const int* __restrict__ pK,
                                    float* __restrict__ c) {
    int t = blockIdx.x;
    int tid = threadIdx.x;
    int K = *pK;
    float hv[4];
    float ss = 0.f;
#pragma unroll
    for (int r = 0; r < 4; r++) {
        int d = tid + r * 256;
        float g;
        if (d < NMEM) {
            g = (float)K;
        } else {
            float aD = expf(-expf(logAd[d - NMEM]) * expf(logdtd[d - NMEM]));
            float om = 1.f - aD;
            float safe = fmaxf(om, 1e-8f);
            float p = 1.f;
            for (int k = 0; k < K; k++) p *= aD;
            g = (fabsf(om) < 1e-6f) ? (float)K : (1.f - p) / safe;
        }
        float h = hseq[t * DD + d] + g * udep[t * DD + d];
        hv[r] = h;
        ss += h * h;
    }
    __shared__ float red[256];
    red[tid] = ss;
    __syncthreads();
    for (int s = 128; s > 0; s >>= 1) {
        if (tid < s) red[tid] += red[tid + s];
        __syncthreads();
    }
    float sc = rsqrtf(red[0] / (float)DD + RMS_EPS);
#pragma unroll
    for (int r = 0; r < 4; r++) {
        int d = tid + r * 256;
        c[t * 3 * DD + d] = hv[r] * sc;
        c[t * 3 * DD + DD + d] = e[t * DD + d];
        c[t * 3 * DD + 2 * DD + d] = (t > 0) ? e[(t - 1) * DD + d] : 0.f;
    }
}

// ---------------- LM head GEMM: C[2048,50304] = A[2048,1024] * B[50304,1024]^T ----------------
#define MMA_TF32(c, a, b)                                                              \
    asm volatile(                                                                      \
        "mma.sync.aligned.m16n8k8.row.col.f32.tf32.tf32.f32 "                          \
        "{%0,%1,%2,%3},{%4,%5,%6,%7},{%8,%9},{%0,%1,%2,%3};\n"                         \
        : "+f"(c[0]), "+f"(c[1]), "+f"(c[2]), "+f"(c[3])                               \
        : "r"(a[0]), "r"(a[1]), "r"(a[2]), "r"(a[3]), "r"(b[0]), "r"(b[1]))

__global__ void __launch_bounds__(256, 2)
lmhead_gemm(const float* __restrict__ A, const float* __restrict__ B, float* __restrict__ C) {
    __shared__ float As[2][16][132];
    __shared__ float Bs[2][16][132];
    const int bm = blockIdx.y * 128;
    const int bn = blockIdx.x * 128;
    const int tid = threadIdx.x;
    const int lane = tid & 31;
    const int warp = tid >> 5;
    const int wm = (warp >> 2) * 64;
    const int wn = (warp & 3) * 32;

    float acc[4][4][4];
#pragma unroll
    for (int i = 0; i < 4; i++)
#pragma unroll
        for (int j = 0; j < 4; j++)
#pragma unroll
            for (int k = 0; k < 4; k++) acc[i][j][k] = 0.f;

    const int lin0 = tid, lin1 = tid + 256;
    const int m0 = lin0 >> 2, kk0 = (lin0 & 3) << 2;
    const int m1 = lin1 >> 2, kk1 = (lin1 & 3) << 2;

    float4 la0, la1, lb0, lb1;
#define G_LOAD(kt)                                                            \
    {                                                                         \
        la0 = *(const float4*)(A + (bm + m0) * DD + (kt) * 16 + kk0);         \
        la1 = *(const float4*)(A + (bm + m1) * DD + (kt) * 16 + kk1);         \
        lb0 = *(const float4*)(B + (size_t)(bn + m0) * DD + (kt) * 16 + kk0); \
        lb1 = *(const float4*)(B + (size_t)(bn + m1) * DD + (kt) * 16 + kk1); \
    }
#define S_STORE(buf)                                                          \
    {                                                                         \
        As[buf][kk0 + 0][m0] = tf32r(la0.x); As[buf][kk0 + 1][m0] = tf32r(la0.y); \
        As[buf][kk0 + 2][m0] = tf32r(la0.z); As[buf][kk0 + 3][m0] = tf32r(la0.w); \
        As[buf][kk1 + 0][m1] = tf32r(la1.x); As[buf][kk1 + 1][m1] = tf32r(la1.y); \
        As[buf][kk1 + 2][m1] = tf32r(la1.z); As[buf][kk1 + 3][m1] = tf32r(la1.w); \
        Bs[buf][kk0 + 0][m0] = tf32r(lb0.x); Bs[buf][kk0 + 1][m0] = tf32r(lb0.y); \
        Bs[buf][kk0 + 2][m0] = tf32r(lb0.z); Bs[buf][kk0 + 3][m0] = tf32r(lb0.w); \
        Bs[buf][kk1 + 0][m1] = tf32r(lb1.x); Bs[buf][kk1 + 1][m1] = tf32r(lb1.y); \
        Bs[buf][kk1 + 2][m1] = tf32r(lb1.z); Bs[buf][kk1 + 3][m1] = tf32r(lb1.w); \
    }

    G_LOAD(0);
    S_STORE(0);
    __syncthreads();

    const int rr = lane >> 2;
    const int kc = lane & 3;
    const int NK = DD / 16;

    for (int kt = 0; kt < NK; kt++) {
        int cur = kt & 1;
        if (kt + 1 < NK) G_LOAD(kt + 1);
#pragma unroll
        for (int ks = 0; ks < 16; ks += 8) {
            unsigned af[4][4], bf[4][2];
#pragma unroll
            for (int mi = 0; mi < 4; mi++) {
                af[mi][0] = __float_as_uint(As[cur][ks + kc][wm + mi * 16 + rr]);
                af[mi][1] = __float_as_uint(As[cur][ks + kc][wm + mi * 16 + rr + 8]);
                af[mi][2] = __float_as_uint(As[cur][ks + kc + 4][wm + mi * 16 + rr]);
                af[mi][3] = __float_as_uint(As[cur][ks + kc + 4][wm + mi * 16 + rr + 8]);
            }
#pragma unroll
            for (int nj = 0; nj < 4; nj++) {
                bf[nj][0] = __float_as_uint(Bs[cur][ks + kc][wn + nj * 8 + rr]);
                bf[nj][1] = __float_as_uint(Bs[cur][ks + kc + 4][wn + nj * 8 + rr]);
            }
#pragma unroll
            for (int mi = 0; mi < 4; mi++)
#pragma unroll
                for (int nj = 0; nj < 4; nj++) MMA_TF32(acc[mi][nj], af[mi], bf[nj]);
        }
        if (kt + 1 < NK) {
            S_STORE(cur ^ 1);
            __syncthreads();
        }
    }

#pragma unroll
    for (int mi = 0; mi < 4; mi++) {
#pragma unroll
        for (int nj = 0; nj < 4; nj++) {
            int r0 = bm + wm + mi * 16 + rr;
            int c0 = bn + wn + nj * 8 + (kc << 1);
            float2 v0 = make_float2(acc[mi][nj][0], acc[mi][nj][1]);
            float2 v1 = make_float2(acc[mi][nj][2], acc[mi][nj][3]);
            *(float2*)(C + (size_t)r0 * VV + c0) = v0;
            *(float2*)(C + (size_t)(r0 + 8) * VV + c0) = v1;
        }
    }
}

// ---------------- launcher ----------------
extern "C" void kernel_launch(void* const* d_in, const int* in_sizes, int n_in,
                              void* d_out, int out_size) {
    const int* idx = (const int*)d_in[0];
    const int* pK = (const int*)d_in[1];
    const float* wte = (const float*)d_in[2];
    const float* wpe = (const float*)d_in[3];
    const float* bseq_w = (const float*)d_in[4];
    const float* logA_seq = (const float*)d_in[5];
    const float* logdt_seq = (const float*)d_in[6];
    const float* bdepth_w = (const float*)d_in[7];
    const float* logA_depth = (const float*)d_in[8];
    const float* logdt_depth = (const float*)d_in[9];
    const float* wpost_w = (const float*)d_in[10];
    const float* wlocal_w = (const float*)d_in[11];
    const float* lowA = (const float*)d_in[12];
    const float* lowB = (const float*)d_in[13];
    const float* lm_head_w = (const float*)d_in[14];
    float* out = (float*)d_out;

    float *x, *e, *h, *ud, *c, *r, *tmp, *xn, *seg;
    cudaGetSymbolAddress((void**)&x, g_x);
    cudaGetSymbolAddress((void**)&e, g_e);
    cudaGetSymbolAddress((void**)&h, g_h);
    cudaGetSymbolAddress((void**)&ud, g_ud);
    cudaGetSymbolAddress((void**)&c, g_c);
    cudaGetSymbolAddress((void**)&r, g_r);
    cudaGetSymbolAddress((void**)&tmp, g_tmp);
    cudaGetSymbolAddress((void**)&xn, g_xn);
    cudaGetSymbolAddress((void**)&seg, g_seg);

    embed_kernel<<<TT, 256>>>(idx, wte, wpe, x);

    for (int l = 0; l < LYR; l++) {
        const float* bseq_l = bseq_w + l * NBLK * 64 * 64;
        const float* lAs = logA_seq + l * HH;
        const float* lDs = logdt_seq + l * HH;
        const float* bdep_l = bdepth_w + l * NBLK * 64 * 64;
        const float* lAd = logA_depth + l * (HH - NMEM);
        const float* lDd = logdt_depth + l * (HH - NMEM);
        const float* wpost_l = wpost_w + l * NBLK * 64 * 192;
        const float* wlocal_l = wlocal_w + l * NBLK * 64 * 64;
        const float* lowA_l = lowA + l * DD * RANKK;
        const float* lowB_l = lowB + l * RANKK * HH;

        rmsnorm_kernel<<<TT, 256>>>(x, e);
        bd64_dual_kernel<<<dim3(TT / 64, NBLK), 256>>>(e, bseq_l, bdep_l, h, ud);
        scanA_kernel<<<dim3(32, 8), dim3(32, 8)>>>(h, lAs, lDs, seg);
        scanB_kernel<<<DD / 16, dim3(16, NSEG)>>>(seg, lAs, lDs);
        scanC_kernel<<<dim3(32, 8), dim3(32, 8)>>>(h, lAs, lDs, seg);
        combine_prep_kernel<<<TT, 256>>>(h, ud, e, lAd, lDd, pK, c);
        bd192_kernel<<<dim3(TT / 64, NBLK), 256>>>(c, wpost_l, r);
        lowrank1_kernel<<<TT / 16, 256>>>(r, lowB_l, tmp);
        update_kernel<<<dim3(TT / 64, NBLK), 256>>>(x, r, tmp, wlocal_l, lowA_l);
    }

    rmsnorm_kernel<<<TT, 256>>>(x, xn);
    lmhead_gemm<<<dim3(VV / 128, TT / 128), 256>>>(xn, lm_head_w, out);
}

// round 6
// speedup vs baseline: 1.0013x; 1.0013x over previous
#include <cuda_runtime.h>
#include <cuda_bf16.h>
#include <math.h>

#define TT 2048
#define DD 1024
#define HH 1024
#define NBLK 16
#define LYR 4
#define RANKK 64
#define NMEM 64
#define VV 50304
#define RMS_EPS 1.1920929e-7f
#define SEGLEN 32
#define NSEG 64

// ---------------- scratch (static device arrays; no allocation) ----------------
__device__ float g_x[TT * DD];
__device__ float g_e[TT * DD];
__device__ float g_h[TT * DD];     // drive_seq -> h_seq (scan in place)
__device__ float g_ud[TT * DD];    // depth drive
__device__ float g_c[TT * 3 * DD]; // concat [hn, e, shifted]
__device__ float g_r[TT * DD];
__device__ float g_tmp[TT * RANKK];
__device__ float g_xn[TT * DD];
__device__ float g_seg[NSEG * DD];

// ---------------- helpers ----------------
__device__ __forceinline__ float silu_f(float x) { return x / (1.0f + expf(-x)); }

__device__ __forceinline__ float tf32r(float x) {
    unsigned u;
    asm("cvt.rna.tf32.f32 %0, %1;" : "=r"(u) : "f"(x));
    return __uint_as_float(u);
}

// ---------------- embedding ----------------
__global__ void embed_kernel(const int* __restrict__ idx, const float* __restrict__ wte,
                             const float* __restrict__ wpe, float* __restrict__ x) {
    int t = blockIdx.x;
    int row = idx[t];
    const float4* wrow = (const float4*)(wte + (long)row * DD);
    const float4* prow = (const float4*)(wpe + (long)t * DD);
    float4* xo = (float4*)(x + t * DD);
    for (int d = threadIdx.x; d < DD / 4; d += blockDim.x) {
        float4 a = wrow[d], b = prow[d];
        xo[d] = make_float4(a.x + b.x, a.y + b.y, a.z + b.z, a.w + b.w);
    }
}

// ---------------- rmsnorm ----------------
__global__ void rmsnorm_kernel(const float* __restrict__ in, float* __restrict__ out) {
    int t = blockIdx.x;
    int tid = threadIdx.x;
    float4 v = ((const float4*)(in + t * DD))[tid];
    float ss = v.x * v.x + v.y * v.y + v.z * v.z + v.w * v.w;
    __shared__ float red[256];
    red[tid] = ss;
    __syncthreads();
    for (int s = 128; s > 0; s >>= 1) {
        if (tid < s) red[tid] += red[tid + s];
        __syncthreads();
    }
    float sc = rsqrtf(red[0] / (float)DD + RMS_EPS);
    ((float4*)(out + t * DD))[tid] = make_float4(v.x * sc, v.y * sc, v.z * sc, v.w * sc);
}

// ============ dual block-diagonal GEMM, K=64, silu: h=silu(e@W1^T), ud=silu(e@W2^T) =======
// grid (TT/64, NBLK), block 256. Output tile [64 t][64 o] for block n, for BOTH weights.
__global__ void __launch_bounds__(256)
bd64_dual_kernel(const float* __restrict__ in, const float* __restrict__ W1,
                 const float* __restrict__ W2, float* __restrict__ out1,
                 float* __restrict__ out2) {
    __shared__ float As[64 * 64];   // [t][k]
    __shared__ float Ws1[64 * 64];  // [k][o]
    __shared__ float Ws2[64 * 64];
    const int t0 = blockIdx.x * 64;
    const int n = blockIdx.y;
    const int tid = threadIdx.x;
    const int tx = tid & 15, ty = tid >> 4;

    for (int i = tid; i < 1024; i += 256) {
        int t = i >> 4, kc = (i & 15) << 2;
        *(float4*)&As[t * 64 + kc] = *(const float4*)&in[(t0 + t) * DD + n * 64 + kc];
    }
    for (int i = tid; i < 1024; i += 256) {
        int o = i >> 4, kc = (i & 15) << 2;
        float4 w = *(const float4*)&W1[(n * 64 + o) * 64 + kc];
        Ws1[(kc + 0) * 64 + o] = w.x; Ws1[(kc + 1) * 64 + o] = w.y;
        Ws1[(kc + 2) * 64 + o] = w.z; Ws1[(kc + 3) * 64 + o] = w.w;
        float4 u = *(const float4*)&W2[(n * 64 + o) * 64 + kc];
        Ws2[(kc + 0) * 64 + o] = u.x; Ws2[(kc + 1) * 64 + o] = u.y;
        Ws2[(kc + 2) * 64 + o] = u.z; Ws2[(kc + 3) * 64 + o] = u.w;
    }
    __syncthreads();

    float acc1[4][4] = {}, acc2[4][4] = {};
#pragma unroll 4
    for (int k = 0; k < 64; k++) {
        float a[4];
#pragma unroll
        for (int q = 0; q < 4; q++) a[q] = As[(ty * 4 + q) * 64 + k];
        float4 b1 = *(float4*)&Ws1[k * 64 + tx * 4];
        float4 b2 = *(float4*)&Ws2[k * 64 + tx * 4];
#pragma unroll
        for (int q = 0; q < 4; q++) {
            acc1[q][0] += a[q] * b1.x; acc1[q][1] += a[q] * b1.y;
            acc1[q][2] += a[q] * b1.z; acc1[q][3] += a[q] * b1.w;
            acc2[q][0] += a[q] * b2.x; acc2[q][1] += a[q] * b2.y;
            acc2[q][2] += a[q] * b2.z; acc2[q][3] += a[q] * b2.w;
        }
    }
#pragma unroll
    for (int q = 0; q < 4; q++) {
        int row = t0 + ty * 4 + q;
        float4 v1 = make_float4(silu_f(acc1[q][0]), silu_f(acc1[q][1]),
                                silu_f(acc1[q][2]), silu_f(acc1[q][3]));
        float4 v2 = make_float4(silu_f(acc2[q][0]), silu_f(acc2[q][1]),
                                silu_f(acc2[q][2]), silu_f(acc2[q][3]));
        *(float4*)&out1[row * HH + n * 64 + tx * 4] = v1;
        *(float4*)&out2[row * HH + n * 64 + tx * 4] = v2;
    }
}

// ============ block-diagonal GEMM, K=192 (wpost), silu ============
__global__ void __launch_bounds__(256)
bd192_kernel(const float* __restrict__ in, const float* __restrict__ W,
             float* __restrict__ out) {
    __shared__ float As[64 * 64];
    __shared__ float Ws[64 * 64];
    const int t0 = blockIdx.x * 64;
    const int n = blockIdx.y;
    const int tid = threadIdx.x;
    const int tx = tid & 15, ty = tid >> 4;

    float acc[4][4] = {};
    for (int c = 0; c < 3; c++) {
        for (int i = tid; i < 1024; i += 256) {
            int t = i >> 4, kc = (i & 15) << 2;
            *(float4*)&As[t * 64 + kc] =
                *(const float4*)&in[(t0 + t) * 3 * DD + n * 192 + c * 64 + kc];
        }
        for (int i = tid; i < 1024; i += 256) {
            int o = i >> 4, kc = (i & 15) << 2;
            float4 w = *(const float4*)&W[(n * 64 + o) * 192 + c * 64 + kc];
            Ws[(kc + 0) * 64 + o] = w.x; Ws[(kc + 1) * 64 + o] = w.y;
            Ws[(kc + 2) * 64 + o] = w.z; Ws[(kc + 3) * 64 + o] = w.w;
        }
        __syncthreads();
#pragma unroll 4
        for (int k = 0; k < 64; k++) {
            float a[4];
#pragma unroll
            for (int q = 0; q < 4; q++) a[q] = As[(ty * 4 + q) * 64 + k];
            float4 b = *(float4*)&Ws[k * 64 + tx * 4];
#pragma unroll
            for (int q = 0; q < 4; q++) {
                acc[q][0] += a[q] * b.x; acc[q][1] += a[q] * b.y;
                acc[q][2] += a[q] * b.z; acc[q][3] += a[q] * b.w;
            }
        }
        __syncthreads();
    }
#pragma unroll
    for (int q = 0; q < 4; q++) {
        int row = t0 + ty * 4 + q;
        float4 v = make_float4(silu_f(acc[q][0]), silu_f(acc[q][1]),
                               silu_f(acc[q][2]), silu_f(acc[q][3]));
        *(float4*)&out[row * HH + n * 64 + tx * 4] = v;
    }
}

// ============ residual update: x += blockdiag(r, wlocal) + tmp @ lowA^T ============
__global__ void __launch_bounds__(256)
update_kernel(float* __restrict__ x, const float* __restrict__ r,
              const float* __restrict__ tmp, const float* __restrict__ wlocal,
              const float* __restrict__ lowA) {
    __shared__ float As[64 * 64];
    __shared__ float Ws[64 * 64];
    const int t0 = blockIdx.x * 64;
    const int n = blockIdx.y;
    const int tid = threadIdx.x;
    const int tx = tid & 15, ty = tid >> 4;

    float acc[4][4] = {};
    // phase 1: wlocal (K=64 over r block n)
    for (int i = tid; i < 1024; i += 256) {
        int t = i >> 4, kc = (i & 15) << 2;
        *(float4*)&As[t * 64 + kc] = *(const float4*)&r[(t0 + t) * HH + n * 64 + kc];
    }
    for (int i = tid; i < 1024; i += 256) {
        int o = i >> 4, kc = (i & 15) << 2;
        float4 w = *(const float4*)&wlocal[(n * 64 + o) * 64 + kc];
        Ws[(kc + 0) * 64 + o] = w.x; Ws[(kc + 1) * 64 + o] = w.y;
        Ws[(kc + 2) * 64 + o] = w.z; Ws[(kc + 3) * 64 + o] = w.w;
    }
    __syncthreads();
#pragma unroll 4
    for (int k = 0; k < 64; k++) {
        float a[4];
#pragma unroll
        for (int q = 0; q < 4; q++) a[q] = As[(ty * 4 + q) * 64 + k];
        float4 b = *(float4*)&Ws[k * 64 + tx * 4];
#pragma unroll
        for (int q = 0; q < 4; q++) {
            acc[q][0] += a[q] * b.x; acc[q][1] += a[q] * b.y;
            acc[q][2] += a[q] * b.z; acc[q][3] += a[q] * b.w;
        }
    }
    __syncthreads();
    // phase 2: lowA (K=64 over tmp)
    for (int i = tid; i < 1024; i += 256) {
        int t = i >> 4, kc = (i & 15) << 2;
        *(float4*)&As[t * 64 + kc] = *(const float4*)&tmp[(t0 + t) * RANKK + kc];
    }
    for (int i = tid; i < 1024; i += 256) {
        int o = i >> 4, kc = (i & 15) << 2;
        float4 w = *(const float4*)&lowA[(n * 64 + o) * RANKK + kc];
        Ws[(kc + 0) * 64 + o] = w.x; Ws[(kc + 1) * 64 + o] = w.y;
        Ws[(kc + 2) * 64 + o] = w.z; Ws[(kc + 3) * 64 + o] = w.w;
    }
    __syncthreads();
#pragma unroll 4
    for (int k = 0; k < 64; k++) {
        float a[4];
#pragma unroll
        for (int q = 0; q < 4; q++) a[q] = As[(ty * 4 + q) * 64 + k];
        float4 b = *(float4*)&Ws[k * 64 + tx * 4];
#pragma unroll
        for (int q = 0; q < 4; q++) {
            acc[q][0] += a[q] * b.x; acc[q][1] += a[q] * b.y;
            acc[q][2] += a[q] * b.z; acc[q][3] += a[q] * b.w;
        }
    }
#pragma unroll
    for (int q = 0; q < 4; q++) {
        int row = t0 + ty * 4 + q;
        float4* px = (float4*)&x[row * DD + n * 64 + tx * 4];
        float4 v = *px;
        v.x += acc[q][0]; v.y += acc[q][1]; v.z += acc[q][2]; v.w += acc[q][3];
        *px = v;
    }
}

// ============ lowrank stage 1: tmp[2048,64] = r[2048,1024] @ lowB^T ============
// grid TT/16, block 256. Thread: 1 t-row, 4 outputs.
__global__ void __launch_bounds__(256)
lowrank1_kernel(const float* __restrict__ r, const float* __restrict__ lowB,
                float* __restrict__ tmp) {
    __shared__ float As[16 * 64];
    __shared__ float Ws[64 * 64];
    const int t0 = blockIdx.x * 16;
    const int tid = threadIdx.x;
    const int tx = tid & 15, ty = tid >> 4;  // ty = t (0..15), tx*4 = o
    float acc[4] = {};
    for (int c = 0; c < 16; c++) {
        {
            int t = tid >> 4, kc = (tid & 15) << 2;
            *(float4*)&As[t * 64 + kc] = *(const float4*)&r[(t0 + t) * HH + c * 64 + kc];
        }
        for (int i = tid; i < 1024; i += 256) {
            int o = i >> 4, kc = (i & 15) << 2;
            float4 w = *(const float4*)&lowB[o * HH + c * 64 + kc];
            Ws[(kc + 0) * 64 + o] = w.x; Ws[(kc + 1) * 64 + o] = w.y;
            Ws[(kc + 2) * 64 + o] = w.z; Ws[(kc + 3) * 64 + o] = w.w;
        }
        __syncthreads();
#pragma unroll 8
        for (int k = 0; k < 64; k++) {
            float a = As[ty * 64 + k];
            float4 b = *(float4*)&Ws[k * 64 + tx * 4];
            acc[0] += a * b.x; acc[1] += a * b.y; acc[2] += a * b.z; acc[3] += a * b.w;
        }
        __syncthreads();
    }
    *(float4*)&tmp[(t0 + ty) * RANKK + tx * 4] = make_float4(acc[0], acc[1], acc[2], acc[3]);
}

// ============ causal scan, 3-phase chunked ============
__global__ void scanA_kernel(float* __restrict__ buf, const float* __restrict__ logA,
                             const float* __restrict__ logdt, float* __restrict__ seg) {
    int d = blockIdx.x * 32 + threadIdx.x;
    int s = blockIdx.y * 8 + threadIdx.y;
    float a = expf(-expf(logA[d]) * expf(logdt[d]));
    float y = 0.f;
    int t0 = s * SEGLEN;
#pragma unroll 8
    for (int tt = 0; tt < SEGLEN; tt++) {
        int i = (t0 + tt) * DD + d;
        y = a * y + buf[i];
        buf[i] = y;
    }
    seg[s * DD + d] = y;
}

__global__ void scanB_kernel(float* __restrict__ seg, const float* __restrict__ logA,
                             const float* __restrict__ logdt) {
    int d = blockIdx.x * 16 + threadIdx.x;
    int j = threadIdx.y;  // 0..63
    float a = expf(-expf(logA[d]) * expf(logdt[d]));
    float a32 = a;
#pragma unroll
    for (int q = 0; q < 5; q++) a32 *= a32;
    __shared__ float s[NSEG][17];
    float cur = seg[j * DD + d];
    s[j][threadIdx.x] = cur;
    float m = a32;
    for (int st = 1; st < NSEG; st <<= 1) {
        __syncthreads();
        float prev = (j >= st) ? s[j - st][threadIdx.x] : 0.f;
        __syncthreads();
        cur += m * prev;
        s[j][threadIdx.x] = cur;
        m = m * m;
    }
    seg[j * DD + d] = cur;
}

__global__ void scanC_kernel(float* __restrict__ buf, const float* __restrict__ logA,
                             const float* __restrict__ logdt, const float* __restrict__ seg) {
    int d = blockIdx.x * 32 + threadIdx.x;
    int s = blockIdx.y * 8 + threadIdx.y;
    if (s == 0) return;
    float a = expf(-expf(logA[d]) * expf(logdt[d]));
    float carry = seg[(s - 1) * DD + d];
    float f = a;
    int t0 = s * SEGLEN;
#pragma unroll 8
    for (int tt = 0; tt < SEGLEN; tt++) {
        int i = (t0 + tt) * DD + d;
        buf[i] += f * carry;
        f *= a;
    }
}

// ---------------- h = h_seq + gain*u_dep ; rmsnorm(h) ; build concat ----------------
__global__ void combine_prep_kernel(const float* __restrict__ hseq, const float* __restrict__ udep,
                                    const float* __restrict__ e, const float* __restrict__ logAd,
                                    const float* __restrict__ logdtd, const int* __restrict__ pK,
                                    float* __restrict__ c) {
    int t = blockIdx.x;
    int tid = threadIdx.x;
    int K = *pK;
    float hv[4];
    float ss = 0.f;
#pragma unroll
    for (int r = 0; r < 4; r++) {
        int d = tid + r * 256;
        float g;
        if (d < NMEM) {
            g = (float)K;
        } else {
            float aD = expf(-expf(logAd[d - NMEM]) * expf(logdtd[d - NMEM]));
            float om = 1.f - aD;
            float safe = fmaxf(om, 1e-8f);
            float p = 1.f;
            for (int k = 0; k < K; k++) p *= aD;
            g = (fabsf(om) < 1e-6f) ? (float)K : (1.f - p) / safe;
        }
        float h = hseq[t * DD + d] + g * udep[t * DD + d];
        hv[r] = h;
        ss += h * h;
    }
    __shared__ float red[256];
    red[tid] = ss;
    __syncthreads();
    for (int s = 128; s > 0; s >>= 1) {
        if (tid < s) red[tid] += red[tid + s];
        __syncthreads();
    }
    float sc = rsqrtf(red[0] / (float)DD + RMS_EPS);
#pragma unroll
    for (int r = 0; r < 4; r++) {
        int d = tid + r * 256;
        c[t * 3 * DD + d] = hv[r] * sc;
        c[t * 3 * DD + DD + d] = e[t * DD + d];
        c[t * 3 * DD + 2 * DD + d] = (t > 0) ? e[(t - 1) * DD + d] : 0.f;
    }
}

// ---------------- LM head GEMM: C[2048,50304] = A[2048,1024] * B[50304,1024]^T ----------------
#define MMA_TF32(c, a, b)                                                              \
    asm volatile(                                                                      \
        "mma.sync.aligned.m16n8k8.row.col.f32.tf32.tf32.f32 "                          \
        "{%0,%1,%2,%3},{%4,%5,%6,%7},{%8,%9},{%0,%1,%2,%3};\n"                         \
        : "+f"(c[0]), "+f"(c[1]), "+f"(c[2]), "+f"(c[3])                               \
        : "r"(a[0]), "r"(a[1]), "r"(a[2]), "r"(a[3]), "r"(b[0]), "r"(b[1]))

__global__ void __launch_bounds__(256, 2)
lmhead_gemm(const float* __restrict__ A, const float* __restrict__ B, float* __restrict__ C) {
    __shared__ float As[2][16][132];
    __shared__ float Bs[2][16][132];
    const int bm = blockIdx.y * 128;
    const int bn = blockIdx.x * 128;
    const int tid = threadIdx.x;
    const int lane = tid & 31;
    const int warp = tid >> 5;
    const int wm = (warp >> 2) * 64;
    const int wn = (warp & 3) * 32;

    float acc[4][4][4];
#pragma unroll
    for (int i = 0; i < 4; i++)
#pragma unroll
        for (int j = 0; j < 4; j++)
#pragma unroll
            for (int k = 0; k < 4; k++) acc[i][j][k] = 0.f;

    const int lin0 = tid, lin1 = tid + 256;
    const int m0 = lin0 >> 2, kk0 = (lin0 & 3) << 2;
    const int m1 = lin1 >> 2, kk1 = (lin1 & 3) << 2;

    float4 la0, la1, lb0, lb1;
#define G_LOAD(kt)                                                            \
    {                                                                         \
        la0 = *(const float4*)(A + (bm + m0) * DD + (kt) * 16 + kk0);         \
        la1 = *(const float4*)(A + (bm + m1) * DD + (kt) * 16 + kk1);         \
        lb0 = *(const float4*)(B + (size_t)(bn + m0) * DD + (kt) * 16 + kk0); \
        lb1 = *(const float4*)(B + (size_t)(bn + m1) * DD + (kt) * 16 + kk1); \
    }
#define S_STORE(buf)                                                          \
    {                                                                         \
        As[buf][kk0 + 0][m0] = tf32r(la0.x); As[buf][kk0 + 1][m0] = tf32r(la0.y); \
        As[buf][kk0 + 2][m0] = tf32r(la0.z); As[buf][kk0 + 3][m0] = tf32r(la0.w); \
        As[buf][kk1 + 0][m1] = tf32r(la1.x); As[buf][kk1 + 1][m1] = tf32r(la1.y); \
        As[buf][kk1 + 2][m1] = tf32r(la1.z); As[buf][kk1 + 3][m1] = tf32r(la1.w); \
        Bs[buf][kk0 + 0][m0] = tf32r(lb0.x); Bs[buf][kk0 + 1][m0] = tf32r(lb0.y); \
        Bs[buf][kk0 + 2][m0] = tf32r(lb0.z); Bs[buf][kk0 + 3][m0] = tf32r(lb0.w); \
        Bs[buf][kk1 + 0][m1] = tf32r(lb1.x); Bs[buf][kk1 + 1][m1] = tf32r(lb1.y); \
        Bs[buf][kk1 + 2][m1] = tf32r(lb1.z); Bs[buf][kk1 + 3][m1] = tf32r(lb1.w); \
    }

    G_LOAD(0);
    S_STORE(0);
    __syncthreads();

    const int rr = lane >> 2;
    const int kc = lane & 3;
    const int NK = DD / 16;

    for (int kt = 0; kt < NK; kt++) {
        int cur = kt & 1;
        if (kt + 1 < NK) G_LOAD(kt + 1);
#pragma unroll
        for (int ks = 0; ks < 16; ks += 8) {
            unsigned af[4][4], bf[4][2];
#pragma unroll
            for (int mi = 0; mi < 4; mi++) {
                af[mi][0] = __float_as_uint(As[cur][ks + kc][wm + mi * 16 + rr]);
                af[mi][1] = __float_as_uint(As[cur][ks + kc][wm + mi * 16 + rr + 8]);
                af[mi][2] = __float_as_uint(As[cur][ks + kc + 4][wm + mi * 16 + rr]);
                af[mi][3] = __float_as_uint(As[cur][ks + kc + 4][wm + mi * 16 + rr + 8]);
            }
#pragma unroll
            for (int nj = 0; nj < 4; nj++) {
                bf[nj][0] = __float_as_uint(Bs[cur][ks + kc][wn + nj * 8 + rr]);
                bf[nj][1] = __float_as_uint(Bs[cur][ks + kc + 4][wn + nj * 8 + rr]);
            }
#pragma unroll
            for (int mi = 0; mi < 4; mi++)
#pragma unroll
                for (int nj = 0; nj < 4; nj++) MMA_TF32(acc[mi][nj], af[mi], bf[nj]);
        }
        if (kt + 1 < NK) {
            S_STORE(cur ^ 1);
            __syncthreads();
        }
    }

#pragma unroll
    for (int mi = 0; mi < 4; mi++) {
#pragma unroll
        for (int nj = 0; nj < 4; nj++) {
            int r0 = bm + wm + mi * 16 + rr;
            int c0 = bn + wn + nj * 8 + (kc << 1);
            float2 v0 = make_float2(acc[mi][nj][0], acc[mi][nj][1]);
            float2 v1 = make_float2(acc[mi][nj][2], acc[mi][nj][3]);
            *(float2*)(C + (size_t)r0 * VV + c0) = v0;
            *(float2*)(C + (size_t)(r0 + 8) * VV + c0) = v1;
        }
    }
}

// ---------------- launcher ----------------
extern "C" void kernel_launch(void* const* d_in, const int* in_sizes, int n_in,
                              void* d_out, int out_size) {
    const int* idx = (const int*)d_in[0];
    const int* pK = (const int*)d_in[1];
    const float* wte = (const float*)d_in[2];
    const float* wpe = (const float*)d_in[3];
    const float* bseq_w = (const float*)d_in[4];
    const float* logA_seq = (const float*)d_in[5];
    const float* logdt_seq = (const float*)d_in[6];
    const float* bdepth_w = (const float*)d_in[7];
    const float* logA_depth = (const float*)d_in[8];
    const float* logdt_depth = (const float*)d_in[9];
    const float* wpost_w = (const float*)d_in[10];
    const float* wlocal_w = (const float*)d_in[11];
    const float* lowA = (const float*)d_in[12];
    const float* lowB = (const float*)d_in[13];
    const float* lm_head_w = (const float*)d_in[14];
    float* out = (float*)d_out;

    float *x, *e, *h, *ud, *c, *r, *tmp, *xn, *seg;
    cudaGetSymbolAddress((void**)&x, g_x);
    cudaGetSymbolAddress((void**)&e, g_e);
    cudaGetSymbolAddress((void**)&h, g_h);
    cudaGetSymbolAddress((void**)&ud, g_ud);
    cudaGetSymbolAddress((void**)&c, g_c);
    cudaGetSymbolAddress((void**)&r, g_r);
    cudaGetSymbolAddress((void**)&tmp, g_tmp);
    cudaGetSymbolAddress((void**)&xn, g_xn);
    cudaGetSymbolAddress((void**)&seg, g_seg);

    embed_kernel<<<TT, 256>>>(idx, wte, wpe, x);

    for (int l = 0; l < LYR; l++) {
        const float* bseq_l = bseq_w + l * NBLK * 64 * 64;
        const float* lAs = logA_seq + l * HH;
        const float* lDs = logdt_seq + l * HH;
        const float* bdep_l = bdepth_w + l * NBLK * 64 * 64;
        const float* lAd = logA_depth + l * (HH - NMEM);
        const float* lDd = logdt_depth + l * (HH - NMEM);
        const float* wpost_l = wpost_w + l * NBLK * 64 * 192;
        const float* wlocal_l = wlocal_w + l * NBLK * 64 * 64;
        const float* lowA_l = lowA + l * DD * RANKK;
        const float* lowB_l = lowB + l * RANKK * HH;

        rmsnorm_kernel<<<TT, 256>>>(x, e);
        bd64_dual_kernel<<<dim3(TT / 64, NBLK), 256>>>(e, bseq_l, bdep_l, h, ud);
        scanA_kernel<<<dim3(32, 8), dim3(32, 8)>>>(h, lAs, lDs, seg);
        scanB_kernel<<<DD / 16, dim3(16, NSEG)>>>(seg, lAs, lDs);
        scanC_kernel<<<dim3(32, 8), dim3(32, 8)>>>(h, lAs, lDs, seg);
        combine_prep_kernel<<<TT, 256>>>(h, ud, e, lAd, lDd, pK, c);
        bd192_kernel<<<dim3(TT / 64, NBLK), 256>>>(c, wpost_l, r);
        lowrank1_kernel<<<TT / 16, 256>>>(r, lowB_l, tmp);
        update_kernel<<<dim3(TT / 64, NBLK), 256>>>(x, r, tmp, wlocal_l, lowA_l);
    }

    rmsnorm_kernel<<<TT, 256>>>(x, xn);
    lmhead_gemm<<<dim3(VV / 128, TT / 128), 256>>>(xn, lm_head_w, out);
}

// round 8
// speedup vs baseline: 1.3450x; 1.3433x over previous
#include <cuda_runtime.h>
#include <cuda_bf16.h>
#include <math.h>
#include <stdint.h>

#define TT 2048
#define DD 1024
#define HH 1024
#define NBLK 16
#define LYR 4
#define RANKK 64
#define NMEM 64
#define VV 50304
#define RMS_EPS 1.1920929e-7f
#define SEGLEN 32
#define NSEG 64

// ---------------- scratch (static device arrays; no allocation) ----------------
__device__ float g_x[TT * DD];
__device__ float g_e[TT * DD];
__device__ float g_h[TT * DD];
__device__ float g_ud[TT * DD];
__device__ float g_c[TT * 3 * DD];
__device__ float g_r[TT * DD];
__device__ float g_tmp[TT * RANKK];
__device__ float g_xn[TT * DD];      // final rmsnorm output, tf32-rounded
__device__ float g_seg[NSEG * DD];
__device__ float g_Btf[(size_t)VV * DD];  // tf32-rounded lm_head weights

// ---------------- helpers ----------------
__device__ __forceinline__ float silu_f(float x) { return x / (1.0f + expf(-x)); }

__device__ __forceinline__ float tf32r(float x) {
    unsigned u;
    asm("cvt.rna.tf32.f32 %0, %1;" : "=r"(u) : "f"(x));
    return __uint_as_float(u);
}

__device__ __forceinline__ uint32_t smem_u32(const void* p) {
    uint32_t a;
    asm("{ .reg .u64 t; cvta.to.shared.u64 t, %1; cvt.u32.u64 %0, t; }" : "=r"(a) : "l"(p));
    return a;
}

__device__ __forceinline__ void cp16(uint32_t dst, const void* src, int sz) {
    asm volatile("cp.async.cg.shared.global [%0], [%1], 16, %2;"
                 :: "r"(dst), "l"(src), "r"(sz) : "memory");
}
#define CP_COMMIT() asm volatile("cp.async.commit_group;" ::: "memory")

// ---------------- embedding ----------------
__global__ void embed_kernel(const int* __restrict__ idx, const float* __restrict__ wte,
                             const float* __restrict__ wpe, float* __restrict__ x) {
    int t = blockIdx.x;
    int row = idx[t];
    const float4* wrow = (const float4*)(wte + (long)row * DD);
    const float4* prow = (const float4*)(wpe + (long)t * DD);
    float4* xo = (float4*)(x + t * DD);
    for (int d = threadIdx.x; d < DD / 4; d += blockDim.x) {
        float4 a = wrow[d], b = prow[d];
        xo[d] = make_float4(a.x + b.x, a.y + b.y, a.z + b.z, a.w + b.w);
    }
}

// ---------------- rmsnorm ----------------
__global__ void rmsnorm_kernel(const float* __restrict__ in, float* __restrict__ out) {
    int t = blockIdx.x;
    int tid = threadIdx.x;
    float4 v = ((const float4*)(in + t * DD))[tid];
    float ss = v.x * v.x + v.y * v.y + v.z * v.z + v.w * v.w;
    __shared__ float red[256];
    red[tid] = ss;
    __syncthreads();
    for (int s = 128; s > 0; s >>= 1) {
        if (tid < s) red[tid] += red[tid + s];
        __syncthreads();
    }
    float sc = rsqrtf(red[0] / (float)DD + RMS_EPS);
    ((float4*)(out + t * DD))[tid] = make_float4(v.x * sc, v.y * sc, v.z * sc, v.w * sc);
}

// final rmsnorm: emit tf32-rounded values (feeds the tensor-core GEMM)
__global__ void rmsnorm_tf32_kernel(const float* __restrict__ in, float* __restrict__ out) {
    int t = blockIdx.x;
    int tid = threadIdx.x;
    float4 v = ((const float4*)(in + t * DD))[tid];
    float ss = v.x * v.x + v.y * v.y + v.z * v.z + v.w * v.w;
    __shared__ float red[256];
    red[tid] = ss;
    __syncthreads();
    for (int s = 128; s > 0; s >>= 1) {
        if (tid < s) red[tid] += red[tid + s];
        __syncthreads();
    }
    float sc = rsqrtf(red[0] / (float)DD + RMS_EPS);
    ((float4*)(out + t * DD))[tid] = make_float4(tf32r(v.x * sc), tf32r(v.y * sc),
                                                 tf32r(v.z * sc), tf32r(v.w * sc));
}

// tf32-round a big fp32 array (lm_head weights)
__global__ void tf32_convert_kernel(const float* __restrict__ in, float* __restrict__ out) {
    int i = blockIdx.x * blockDim.x + threadIdx.x;
    float4 v = ((const float4*)in)[i];
    ((float4*)out)[i] = make_float4(tf32r(v.x), tf32r(v.y), tf32r(v.z), tf32r(v.w));
}

// ============ dual block-diagonal GEMM, K=64, silu ============
__global__ void __launch_bounds__(256)
bd64_dual_kernel(const float* __restrict__ in, const float* __restrict__ W1,
                 const float* __restrict__ W2, float* __restrict__ out1,
                 float* __restrict__ out2) {
    __shared__ float As[64 * 64];
    __shared__ float Ws1[64 * 64];
    __shared__ float Ws2[64 * 64];
    const int t0 = blockIdx.x * 64;
    const int n = blockIdx.y;
    const int tid = threadIdx.x;
    const int tx = tid & 15, ty = tid >> 4;

    for (int i = tid; i < 1024; i += 256) {
        int t = i >> 4, kc = (i & 15) << 2;
        *(float4*)&As[t * 64 + kc] = *(const float4*)&in[(t0 + t) * DD + n * 64 + kc];
    }
    for (int i = tid; i < 1024; i += 256) {
        int o = i >> 4, kc = (i & 15) << 2;
        float4 w = *(const float4*)&W1[(n * 64 + o) * 64 + kc];
        Ws1[(kc + 0) * 64 + o] = w.x; Ws1[(kc + 1) * 64 + o] = w.y;
        Ws1[(kc + 2) * 64 + o] = w.z; Ws1[(kc + 3) * 64 + o] = w.w;
        float4 u = *(const float4*)&W2[(n * 64 + o) * 64 + kc];
        Ws2[(kc + 0) * 64 + o] = u.x; Ws2[(kc + 1) * 64 + o] = u.y;
        Ws2[(kc + 2) * 64 + o] = u.z; Ws2[(kc + 3) * 64 + o] = u.w;
    }
    __syncthreads();

    float acc1[4][4] = {}, acc2[4][4] = {};
#pragma unroll 4
    for (int k = 0; k < 64; k++) {
        float a[4];
#pragma unroll
        for (int q = 0; q < 4; q++) a[q] = As[(ty * 4 + q) * 64 + k];
        float4 b1 = *(float4*)&Ws1[k * 64 + tx * 4];
        float4 b2 = *(float4*)&Ws2[k * 64 + tx * 4];
#pragma unroll
        for (int q = 0; q < 4; q++) {
            acc1[q][0] += a[q] * b1.x; acc1[q][1] += a[q] * b1.y;
            acc1[q][2] += a[q] * b1.z; acc1[q][3] += a[q] * b1.w;
            acc2[q][0] += a[q] * b2.x; acc2[q][1] += a[q] * b2.y;
            acc2[q][2] += a[q] * b2.z; acc2[q][3] += a[q] * b2.w;
        }
    }
#pragma unroll
    for (int q = 0; q < 4; q++) {
        int row = t0 + ty * 4 + q;
        float4 v1 = make_float4(silu_f(acc1[q][0]), silu_f(acc1[q][1]),
                                silu_f(acc1[q][2]), silu_f(acc1[q][3]));
        float4 v2 = make_float4(silu_f(acc2[q][0]), silu_f(acc2[q][1]),
                                silu_f(acc2[q][2]), silu_f(acc2[q][3]));
        *(float4*)&out1[row * HH + n * 64 + tx * 4] = v1;
        *(float4*)&out2[row * HH + n * 64 + tx * 4] = v2;
    }
}

// ============ block-diagonal GEMM, K=192 (wpost), silu ============
__global__ void __launch_bounds__(256)
bd192_kernel(const float* __restrict__ in, const float* __restrict__ W,
             float* __restrict__ out) {
    __shared__ float As[64 * 64];
    __shared__ float Ws[64 * 64];
    const int t0 = blockIdx.x * 64;
    const int n = blockIdx.y;
    const int tid = threadIdx.x;
    const int tx = tid & 15, ty = tid >> 4;

    float acc[4][4] = {};
    for (int c = 0; c < 3; c++) {
        for (int i = tid; i < 1024; i += 256) {
            int t = i >> 4, kc = (i & 15) << 2;
            *(float4*)&As[t * 64 + kc] =
                *(const float4*)&in[(t0 + t) * 3 * DD + n * 192 + c * 64 + kc];
        }
        for (int i = tid; i < 1024; i += 256) {
            int o = i >> 4, kc = (i & 15) << 2;
            float4 w = *(const float4*)&W[(n * 64 + o) * 192 + c * 64 + kc];
            Ws[(kc + 0) * 64 + o] = w.x; Ws[(kc + 1) * 64 + o] = w.y;
            Ws[(kc + 2) * 64 + o] = w.z; Ws[(kc + 3) * 64 + o] = w.w;
        }
        __syncthreads();
#pragma unroll 4
        for (int k = 0; k < 64; k++) {
            float a[4];
#pragma unroll
            for (int q = 0; q < 4; q++) a[q] = As[(ty * 4 + q) * 64 + k];
            float4 b = *(float4*)&Ws[k * 64 + tx * 4];
#pragma unroll
            for (int q = 0; q < 4; q++) {
                acc[q][0] += a[q] * b.x; acc[q][1] += a[q] * b.y;
                acc[q][2] += a[q] * b.z; acc[q][3] += a[q] * b.w;
            }
        }
        __syncthreads();
    }
#pragma unroll
    for (int q = 0; q < 4; q++) {
        int row = t0 + ty * 4 + q;
        float4 v = make_float4(silu_f(acc[q][0]), silu_f(acc[q][1]),
                               silu_f(acc[q][2]), silu_f(acc[q][3]));
        *(float4*)&out[row * HH + n * 64 + tx * 4] = v;
    }
}

// ============ residual update ============
__global__ void __launch_bounds__(256)
update_kernel(float* __restrict__ x, const float* __restrict__ r,
              const float* __restrict__ tmp, const float* __restrict__ wlocal,
              const float* __restrict__ lowA) {
    __shared__ float As[64 * 64];
    __shared__ float Ws[64 * 64];
    const int t0 = blockIdx.x * 64;
    const int n = blockIdx.y;
    const int tid = threadIdx.x;
    const int tx = tid & 15, ty = tid >> 4;

    float acc[4][4] = {};
    for (int i = tid; i < 1024; i += 256) {
        int t = i >> 4, kc = (i & 15) << 2;
        *(float4*)&As[t * 64 + kc] = *(const float4*)&r[(t0 + t) * HH + n * 64 + kc];
    }
    for (int i = tid; i < 1024; i += 256) {
        int o = i >> 4, kc = (i & 15) << 2;
        float4 w = *(const float4*)&wlocal[(n * 64 + o) * 64 + kc];
        Ws[(kc + 0) * 64 + o] = w.x; Ws[(kc + 1) * 64 + o] = w.y;
        Ws[(kc + 2) * 64 + o] = w.z; Ws[(kc + 3) * 64 + o] = w.w;
    }
    __syncthreads();
#pragma unroll 4
    for (int k = 0; k < 64; k++) {
        float a[4];
#pragma unroll
        for (int q = 0; q < 4; q++) a[q] = As[(ty * 4 + q) * 64 + k];
        float4 b = *(float4*)&Ws[k * 64 + tx * 4];
#pragma unroll
        for (int q = 0; q < 4; q++) {
            acc[q][0] += a[q] * b.x; acc[q][1] += a[q] * b.y;
            acc[q][2] += a[q] * b.z; acc[q][3] += a[q] * b.w;
        }
    }
    __syncthreads();
    for (int i = tid; i < 1024; i += 256) {
        int t = i >> 4, kc = (i & 15) << 2;
        *(float4*)&As[t * 64 + kc] = *(const float4*)&tmp[(t0 + t) * RANKK + kc];
    }
    for (int i = tid; i < 1024; i += 256) {
        int o = i >> 4, kc = (i & 15) << 2;
        float4 w = *(const float4*)&lowA[(n * 64 + o) * RANKK + kc];
        Ws[(kc + 0) * 64 + o] = w.x; Ws[(kc + 1) * 64 + o] = w.y;
        Ws[(kc + 2) * 64 + o] = w.z; Ws[(kc + 3) * 64 + o] = w.w;
    }
    __syncthreads();
#pragma unroll 4
    for (int k = 0; k < 64; k++) {
        float a[4];
#pragma unroll
        for (int q = 0; q < 4; q++) a[q] = As[(ty * 4 + q) * 64 + k];
        float4 b = *(float4*)&Ws[k * 64 + tx * 4];
#pragma unroll
        for (int q = 0; q < 4; q++) {
            acc[q][0] += a[q] * b.x; acc[q][1] += a[q] * b.y;
            acc[q][2] += a[q] * b.z; acc[q][3] += a[q] * b.w;
        }
    }
#pragma unroll
    for (int q = 0; q < 4; q++) {
        int row = t0 + ty * 4 + q;
        float4* px = (float4*)&x[row * DD + n * 64 + tx * 4];
        float4 v = *px;
        v.x += acc[q][0]; v.y += acc[q][1]; v.z += acc[q][2]; v.w += acc[q][3];
        *px = v;
    }
}

// ============ lowrank stage 1 ============
__global__ void __launch_bounds__(256)
lowrank1_kernel(const float* __restrict__ r, const float* __restrict__ lowB,
                float* __restrict__ tmp) {
    __shared__ float As[16 * 64];
    __shared__ float Ws[64 * 64];
    const int t0 = blockIdx.x * 16;
    const int tid = threadIdx.x;
    const int tx = tid & 15, ty = tid >> 4;
    float acc[4] = {};
    for (int c = 0; c < 16; c++) {
        {
            int t = tid >> 4, kc = (tid & 15) << 2;
            *(float4*)&As[t * 64 + kc] = *(const float4*)&r[(t0 + t) * HH + c * 64 + kc];
        }
        for (int i = tid; i < 1024; i += 256) {
            int o = i >> 4, kc = (i & 15) << 2;
            float4 w = *(const float4*)&lowB[o * HH + c * 64 + kc];
            Ws[(kc + 0) * 64 + o] = w.x; Ws[(kc + 1) * 64 + o] = w.y;
            Ws[(kc + 2) * 64 + o] = w.z; Ws[(kc + 3) * 64 + o] = w.w;
        }
        __syncthreads();
#pragma unroll 8
        for (int k = 0; k < 64; k++) {
            float a = As[ty * 64 + k];
            float4 b = *(float4*)&Ws[k * 64 + tx * 4];
            acc[0] += a * b.x; acc[1] += a * b.y; acc[2] += a * b.z; acc[3] += a * b.w;
        }
        __syncthreads();
    }
    *(float4*)&tmp[(t0 + ty) * RANKK + tx * 4] = make_float4(acc[0], acc[1], acc[2], acc[3]);
}

// ============ causal scan, 3-phase chunked ============
__global__ void scanA_kernel(float* __restrict__ buf, const float* __restrict__ logA,
                             const float* __restrict__ logdt, float* __restrict__ seg) {
    int d = blockIdx.x * 32 + threadIdx.x;
    int s = blockIdx.y * 8 + threadIdx.y;
    float a = expf(-expf(logA[d]) * expf(logdt[d]));
    float y = 0.f;
    int t0 = s * SEGLEN;
#pragma unroll 8
    for (int tt = 0; tt < SEGLEN; tt++) {
        int i = (t0 + tt) * DD + d;
        y = a * y + buf[i];
        buf[i] = y;
    }
    seg[s * DD + d] = y;
}

__global__ void scanB_kernel(float* __restrict__ seg, const float* __restrict__ logA,
                             const float* __restrict__ logdt) {
    int d = blockIdx.x * 16 + threadIdx.x;
    int j = threadIdx.y;
    float a = expf(-expf(logA[d]) * expf(logdt[d]));
    float a32 = a;
#pragma unroll
    for (int q = 0; q < 5; q++) a32 *= a32;
    __shared__ float s[NSEG][17];
    float cur = seg[j * DD + d];
    s[j][threadIdx.x] = cur;
    float m = a32;
    for (int st = 1; st < NSEG; st <<= 1) {
        __syncthreads();
        float prev = (j >= st) ? s[j - st][threadIdx.x] : 0.f;
        __syncthreads();
        cur += m * prev;
        s[j][threadIdx.x] = cur;
        m = m * m;
    }
    seg[j * DD + d] = cur;
}

__global__ void scanC_kernel(float* __restrict__ buf, const float* __restrict__ logA,
                             const float* __restrict__ logdt, const float* __restrict__ seg) {
    int d = blockIdx.x * 32 + threadIdx.x;
    int s = blockIdx.y * 8 + threadIdx.y;
    if (s == 0) return;
    float a = expf(-expf(logA[d]) * expf(logdt[d]));
    float carry = seg[(s - 1) * DD + d];
    float f = a;
    int t0 = s * SEGLEN;
#pragma unroll 8
    for (int tt = 0; tt < SEGLEN; tt++) {
        int i = (t0 + tt) * DD + d;
        buf[i] += f * carry;
        f *= a;
    }
}

// ---------------- combine + rmsnorm + concat ----------------
__global__ void combine_prep_kernel(const float* __restrict__ hseq, const float* __restrict__ udep,
                                    const float* __restrict__ e, const float* __restrict__ logAd,
                                    const float* __restrict__ logdtd, const int* __restrict__ pK,
                                    float* __restrict__ c) {
    int t = blockIdx.x;
    int tid = threadIdx.x;
    int K = *pK;
    float hv[4];
    float ss = 0.f;
#pragma unroll
    for (int r = 0; r < 4; r++) {
        int d = tid + r * 256;
        float g;
        if (d < NMEM) {
            g = (float)K;
        } else {
            float aD = expf(-expf(logAd[d - NMEM]) * expf(logdtd[d - NMEM]));
            float om = 1.f - aD;
            float safe = fmaxf(om, 1e-8f);
            float p = 1.f;
            for (int k = 0; k < K; k++) p *= aD;
            g = (fabsf(om) < 1e-6f) ? (float)K : (1.f - p) / safe;
        }
        float h = hseq[t * DD + d] + g * udep[t * DD + d];
        hv[r] = h;
        ss += h * h;
    }
    __shared__ float red[256];
    red[tid] = ss;
    __syncthreads();
    for (int s = 128; s > 0; s >>= 1) {
        if (tid < s) red[tid] += red[tid + s];
        __syncthreads();
    }
    float sc = rsqrtf(red[0] / (float)DD + RMS_EPS);
#pragma unroll
    for (int r = 0; r < 4; r++) {
        int d = tid + r * 256;
        c[t * 3 * DD + d] = hv[r] * sc;
        c[t * 3 * DD + DD + d] = e[t * DD + d];
        c[t * 3 * DD + 2 * DD + d] = (t > 0) ? e[(t - 1) * DD + d] : 0.f;
    }
}

// ================= LM head GEMM (legacy mma.sync tf32, cp.async pipeline) =================
// C[2048,50304] = A[2048,1024] @ B[50304,1024]^T. A,B pre-rounded to tf32.
// CTA tile 128(M) x 256(N), BK=32, double-buffered cp.async.
// 8 warps: 2(M) x 4(N), warp tile 64x64 -> 4x8 m16n8k8 MMAs per k8-step.
// smem layout: A [m][k] stride 36 floats, B [n][k] stride 36 (conflict-free frags).
#define GSTRIDE 36
#define A_STAGE_B (128 * GSTRIDE * 4)  // 18432
#define B_STAGE_B (256 * GSTRIDE * 4)  // 36864
#define LM_SMEM (2 * A_STAGE_B + 2 * B_STAGE_B)  // 110592

#define MMA_TF32(c, a, b)                                                              \
    asm volatile(                                                                      \
        "mma.sync.aligned.m16n8k8.row.col.f32.tf32.tf32.f32 "                          \
        "{%0,%1,%2,%3},{%4,%5,%6,%7},{%8,%9},{%0,%1,%2,%3};\n"                         \
        : "+f"(c[0]), "+f"(c[1]), "+f"(c[2]), "+f"(c[3])                               \
        : "r"(a[0]), "r"(a[1]), "r"(a[2]), "r"(a[3]), "r"(b[0]), "r"(b[1]))

__global__ void __launch_bounds__(256, 1)
lmhead_gemm(const float* __restrict__ A, const float* __restrict__ B, float* __restrict__ C) {
    extern __shared__ __align__(16) float smf[];
    const uint32_t smb = smem_u32(smf);
    const int tid = threadIdx.x;
    const int lane = tid & 31;
    const int warp = tid >> 5;
    const int M0 = blockIdx.x * 128;
    const int N0 = blockIdx.y * 256;
    const int nVal = (VV - N0 < 256) ? (VV - N0) : 256;
    const int wm = (warp >> 2) * 64;   // 0 or 64
    const int wn = (warp & 3) * 64;    // 0,64,128,192
    const int rr = lane >> 2;          // 0..7
    const int kc = lane & 3;           // 0..3

    // per-thread cp.async chunk coords
    const int am = tid >> 1, aq = (tid & 1) << 2;          // A: 2 threads per m-row? no:
    // A: 1024 16B-chunks (m 0..127, q 0..7). thread handles chunks tid, tid+256, tid+512, tid+768.
    // B: 2048 chunks (n 0..255, q 0..7), 8 per thread.
    (void)am; (void)aq;

    float acc[4][8][4];
#pragma unroll
    for (int i = 0; i < 4; i++)
#pragma unroll
        for (int j = 0; j < 8; j++)
#pragma unroll
            for (int k = 0; k < 4; k++) acc[i][j][k] = 0.f;

#define LOAD_STAGE(s, kb)                                                              \
    {                                                                                  \
        _Pragma("unroll") for (int i = 0; i < 4; i++) {                                \
            int cch = tid + i * 256;                                                   \
            int m = cch >> 3, q = cch & 7;                                             \
            uint32_t dst = smb + (s) * A_STAGE_B + (uint32_t)(m * GSTRIDE + q * 4) * 4;\
            const float* src = A + (size_t)(M0 + m) * DD + (kb) * 32 + q * 4;          \
            cp16(dst, src, 16);                                                        \
        }                                                                              \
        _Pragma("unroll") for (int i = 0; i < 8; i++) {                                \
            int cch = tid + i * 256;                                                   \
            int n = cch >> 3, q = cch & 7;                                             \
            uint32_t dst = smb + 2 * A_STAGE_B + (s) * B_STAGE_B +                     \
                           (uint32_t)(n * GSTRIDE + q * 4) * 4;                        \
            int ok = (n < nVal);                                                       \
            const float* src = B + (size_t)(N0 + (ok ? n : 0)) * DD + (kb) * 32 + q * 4;\
            cp16(dst, src, ok ? 16 : 0);                                               \
        }                                                                              \
        CP_COMMIT();                                                                   \
    }

    LOAD_STAGE(0, 0);
    LOAD_STAGE(1, 1);

    const int NKB = DD / 32;  // 32
    for (int kb = 0; kb < NKB; kb++) {
        const int s = kb & 1;
        if (kb >= NKB - 2) {
            asm volatile("cp.async.wait_group 0;" ::: "memory");
        } else {
            asm volatile("cp.async.wait_group 1;" ::: "memory");
        }
        __syncthreads();

        const float* As = smf + s * (A_STAGE_B / 4);
        const float* Bs = smf + 2 * (A_STAGE_B / 4) + s * (B_STAGE_B / 4);

#pragma unroll
        for (int ks = 0; ks < 32; ks += 8) {
            unsigned af[4][4], bf[8][2];
#pragma unroll
            for (int mi = 0; mi < 4; mi++) {
                int base = (wm + mi * 16 + rr) * GSTRIDE + ks + kc;
                af[mi][0] = __float_as_uint(As[base]);
                af[mi][1] = __float_as_uint(As[base + 8 * GSTRIDE]);
                af[mi][2] = __float_as_uint(As[base + 4]);
                af[mi][3] = __float_as_uint(As[base + 8 * GSTRIDE + 4]);
            }
#pragma unroll
            for (int nj = 0; nj < 8; nj++) {
                int base = (wn + nj * 8 + rr) * GSTRIDE + ks + kc;
                bf[nj][0] = __float_as_uint(Bs[base]);
                bf[nj][1] = __float_as_uint(Bs[base + 4]);
            }
#pragma unroll
            for (int mi = 0; mi < 4; mi++)
#pragma unroll
                for (int nj = 0; nj < 8; nj++) MMA_TF32(acc[mi][nj], af[mi], bf[nj]);
        }
        __syncthreads();
        if (kb + 2 < NKB) LOAD_STAGE(s, kb + 2);
    }

    // epilogue
#pragma unroll
    for (int mi = 0; mi < 4; mi++) {
#pragma unroll
        for (int nj = 0; nj < 8; nj++) {
            int c0 = N0 + wn + nj * 8 + (kc << 1);
            if (c0 < VV) {
                size_t r0 = (size_t)(M0 + wm + mi * 16 + rr);
                *(float2*)(C + r0 * VV + c0) = make_float2(acc[mi][nj][0], acc[mi][nj][1]);
                *(float2*)(C + (r0 + 8) * VV + c0) = make_float2(acc[mi][nj][2], acc[mi][nj][3]);
            }
        }
    }
}

// ---------------- launcher ----------------
extern "C" void kernel_launch(void* const* d_in, const int* in_sizes, int n_in,
                              void* d_out, int out_size) {
    const int* idx = (const int*)d_in[0];
    const int* pK = (const int*)d_in[1];
    const float* wte = (const float*)d_in[2];
    const float* wpe = (const float*)d_in[3];
    const float* bseq_w = (const float*)d_in[4];
    const float* logA_seq = (const float*)d_in[5];
    const float* logdt_seq = (const float*)d_in[6];
    const float* bdepth_w = (const float*)d_in[7];
    const float* logA_depth = (const float*)d_in[8];
    const float* logdt_depth = (const float*)d_in[9];
    const float* wpost_w = (const float*)d_in[10];
    const float* wlocal_w = (const float*)d_in[11];
    const float* lowA = (const float*)d_in[12];
    const float* lowB = (const float*)d_in[13];
    const float* lm_head_w = (const float*)d_in[14];
    float* out = (float*)d_out;

    float *x, *e, *h, *ud, *c, *r, *tmp, *xn, *seg, *Btf;
    cudaGetSymbolAddress((void**)&x, g_x);
    cudaGetSymbolAddress((void**)&e, g_e);
    cudaGetSymbolAddress((void**)&h, g_h);
    cudaGetSymbolAddress((void**)&ud, g_ud);
    cudaGetSymbolAddress((void**)&c, g_c);
    cudaGetSymbolAddress((void**)&r, g_r);
    cudaGetSymbolAddress((void**)&tmp, g_tmp);
    cudaGetSymbolAddress((void**)&xn, g_xn);
    cudaGetSymbolAddress((void**)&seg, g_seg);
    cudaGetSymbolAddress((void**)&Btf, g_Btf);

    cudaFuncSetAttribute(lmhead_gemm, cudaFuncAttributeMaxDynamicSharedMemorySize, LM_SMEM);

    // pre-round lm_head weights to tf32 (runs concurrently with layer stack on GPU)
    tf32_convert_kernel<<<(VV * DD) / 1024, 256>>>(lm_head_w, Btf);

    embed_kernel<<<TT, 256>>>(idx, wte, wpe, x);

    for (int l = 0; l < LYR; l++) {
        const float* bseq_l = bseq_w + l * NBLK * 64 * 64;
        const float* lAs = logA_seq + l * HH;
        const float* lDs = logdt_seq + l * HH;
        const float* bdep_l = bdepth_w + l * NBLK * 64 * 64;
        const float* lAd = logA_depth + l * (HH - NMEM);
        const float* lDd = logdt_depth + l * (HH - NMEM);
        const float* wpost_l = wpost_w + l * NBLK * 64 * 192;
        const float* wlocal_l = wlocal_w + l * NBLK * 64 * 64;
        const float* lowA_l = lowA + l * DD * RANKK;
        const float* lowB_l = lowB + l * RANKK * HH;

        rmsnorm_kernel<<<TT, 256>>>(x, e);
        bd64_dual_kernel<<<dim3(TT / 64, NBLK), 256>>>(e, bseq_l, bdep_l, h, ud);
        scanA_kernel<<<dim3(32, 8), dim3(32, 8)>>>(h, lAs, lDs, seg);
        scanB_kernel<<<DD / 16, dim3(16, NSEG)>>>(seg, lAs, lDs);
        scanC_kernel<<<dim3(32, 8), dim3(32, 8)>>>(h, lAs, lDs, seg);
        combine_prep_kernel<<<TT, 256>>>(h, ud, e, lAd, lDd, pK, c);
        bd192_kernel<<<dim3(TT / 64, NBLK), 256>>>(c, wpost_l, r);
        lowrank1_kernel<<<TT / 16, 256>>>(r, lowB_l, tmp);
        update_kernel<<<dim3(TT / 64, NBLK), 256>>>(x, r, tmp, wlocal_l, lowA_l);
    }

    rmsnorm_tf32_kernel<<<TT, 256>>>(x, xn);
    // grid: x = M tiles (fast-varying) so concurrent CTAs share B tiles via L2
    lmhead_gemm<<<dim3(TT / 128, (VV + 255) / 256), 256, LM_SMEM>>>(xn, Btf, out);
}

// round 9
// speedup vs baseline: 1.4328x; 1.0652x over previous
#include <cuda_runtime.h>
#include <cuda_bf16.h>
#include <math.h>
#include <stdint.h>

#define TT 2048
#define DD 1024
#define HH 1024
#define NBLK 16
#define LYR 4
#define RANKK 64
#define NMEM 64
#define VV 50304
#define RMS_EPS 1.1920929e-7f
#define SEGLEN 32
#define NSEG 64

// ---------------- scratch (static device arrays; no allocation) ----------------
__device__ float g_x[TT * DD];
__device__ float g_e[TT * DD];
__device__ float g_h[TT * DD];
__device__ float g_ud[TT * DD];
__device__ float g_c[TT * 3 * DD];
__device__ float g_r[TT * DD];
__device__ float g_tmp[TT * RANKK];
__device__ float g_xn[TT * DD];
__device__ float g_seg[NSEG * DD];
__device__ float g_Btf[(size_t)VV * DD];

// ---------------- helpers ----------------
__device__ __forceinline__ float silu_f(float x) { return x / (1.0f + expf(-x)); }

__device__ __forceinline__ float tf32r(float x) {
    unsigned u;
    asm("cvt.rna.tf32.f32 %0, %1;" : "=r"(u) : "f"(x));
    return __uint_as_float(u);
}

__device__ __forceinline__ uint32_t smem_u32(const void* p) {
    uint32_t a;
    asm("{ .reg .u64 t; cvta.to.shared.u64 t, %1; cvt.u32.u64 %0, t; }" : "=r"(a) : "l"(p));
    return a;
}

__device__ __forceinline__ void cp16(uint32_t dst, const void* src, int sz) {
    asm volatile("cp.async.cg.shared.global [%0], [%1], 16, %2;"
                 :: "r"(dst), "l"(src), "r"(sz) : "memory");
}
#define CP_COMMIT() asm volatile("cp.async.commit_group;" ::: "memory")

// packed f32x2 helpers
__device__ __forceinline__ uint64_t pk2(float x, float y) {
    uint64_t r;
    asm("mov.b64 %0, {%1,%2};" : "=l"(r) : "f"(x), "f"(y));
    return r;
}
__device__ __forceinline__ void up2(float& x, float& y, uint64_t p) {
    asm("mov.b64 {%0,%1}, %2;" : "=f"(x), "=f"(y) : "l"(p));
}
__device__ __forceinline__ uint64_t fma2(uint64_t a, uint64_t b, uint64_t c) {
    uint64_t d;
    asm("fma.rn.f32x2 %0, %1, %2, %3;" : "=l"(d) : "l"(a), "l"(b), "l"(c));
    return d;
}
__device__ __forceinline__ void lds_b64x2(uint64_t& lo, uint64_t& hi, uint32_t addr) {
    asm volatile("ld.shared.v2.b64 {%0,%1}, [%2];" : "=l"(lo), "=l"(hi) : "r"(addr));
}
__device__ __forceinline__ void lds_f32x4(float4& v, uint32_t addr) {
    asm volatile("ld.shared.v4.f32 {%0,%1,%2,%3}, [%4];"
                 : "=f"(v.x), "=f"(v.y), "=f"(v.z), "=f"(v.w) : "r"(addr));
}

// XOR swizzle: column o within a 64-wide [k][o] tile; XOR bits [2:5) with k bits [2:5)
__device__ __forceinline__ int swz(int k, int o) {
    return k * 64 + (o ^ (((k >> 2) & 7) << 2));
}

// ---------------- embedding ----------------
__global__ void embed_kernel(const int* __restrict__ idx, const float* __restrict__ wte,
                             const float* __restrict__ wpe, float* __restrict__ x) {
    int t = blockIdx.x;
    int row = idx[t];
    const float4* wrow = (const float4*)(wte + (long)row * DD);
    const float4* prow = (const float4*)(wpe + (long)t * DD);
    float4* xo = (float4*)(x + t * DD);
    for (int d = threadIdx.x; d < DD / 4; d += blockDim.x) {
        float4 a = wrow[d], b = prow[d];
        xo[d] = make_float4(a.x + b.x, a.y + b.y, a.z + b.z, a.w + b.w);
    }
}

// ---------------- rmsnorm ----------------
__global__ void rmsnorm_kernel(const float* __restrict__ in, float* __restrict__ out) {
    int t = blockIdx.x;
    int tid = threadIdx.x;
    float4 v = ((const float4*)(in + t * DD))[tid];
    float ss = v.x * v.x + v.y * v.y + v.z * v.z + v.w * v.w;
    __shared__ float red[256];
    red[tid] = ss;
    __syncthreads();
    for (int s = 128; s > 0; s >>= 1) {
        if (tid < s) red[tid] += red[tid + s];
        __syncthreads();
    }
    float sc = rsqrtf(red[0] / (float)DD + RMS_EPS);
    ((float4*)(out + t * DD))[tid] = make_float4(v.x * sc, v.y * sc, v.z * sc, v.w * sc);
}

__global__ void rmsnorm_tf32_kernel(const float* __restrict__ in, float* __restrict__ out) {
    int t = blockIdx.x;
    int tid = threadIdx.x;
    float4 v = ((const float4*)(in + t * DD))[tid];
    float ss = v.x * v.x + v.y * v.y + v.z * v.z + v.w * v.w;
    __shared__ float red[256];
    red[tid] = ss;
    __syncthreads();
    for (int s = 128; s > 0; s >>= 1) {
        if (tid < s) red[tid] += red[tid + s];
        __syncthreads();
    }
    float sc = rsqrtf(red[0] / (float)DD + RMS_EPS);
    ((float4*)(out + t * DD))[tid] = make_float4(tf32r(v.x * sc), tf32r(v.y * sc),
                                                 tf32r(v.z * sc), tf32r(v.w * sc));
}

__global__ void tf32_convert_kernel(const float* __restrict__ in, float* __restrict__ out) {
    int i = blockIdx.x * blockDim.x + threadIdx.x;
    float4 v = ((const float4*)in)[i];
    ((float4*)out)[i] = make_float4(tf32r(v.x), tf32r(v.y), tf32r(v.z), tf32r(v.w));
}

// ============ dual block-diagonal GEMM, K=64, silu (f32x2, swizzled smem) ============
__global__ void __launch_bounds__(256)
bd64_dual_kernel(const float* __restrict__ in, const float* __restrict__ W1,
                 const float* __restrict__ W2, float* __restrict__ out1,
                 float* __restrict__ out2) {
    __shared__ float As[64 * 64];   // [k][t] swizzled
    __shared__ float Ws1[64 * 64];  // [k][o] swizzled
    __shared__ float Ws2[64 * 64];
    const int t0 = blockIdx.x * 64;
    const int n = blockIdx.y;
    const int tid = threadIdx.x;
    const int tx = tid & 15, ty = tid >> 4;
    const uint32_t asb = smem_u32(As), w1b = smem_u32(Ws1), w2b = smem_u32(Ws2);

    for (int i = tid; i < 1024; i += 256) {
        int t = i >> 4, kc = (i & 15) << 2;
        float4 v = *(const float4*)&in[(t0 + t) * DD + n * 64 + kc];
        As[swz(kc + 0, t)] = v.x; As[swz(kc + 1, t)] = v.y;
        As[swz(kc + 2, t)] = v.z; As[swz(kc + 3, t)] = v.w;
        float4 w = *(const float4*)&W1[(n * 64 + t) * 64 + kc];
        Ws1[swz(kc + 0, t)] = w.x; Ws1[swz(kc + 1, t)] = w.y;
        Ws1[swz(kc + 2, t)] = w.z; Ws1[swz(kc + 3, t)] = w.w;
        float4 u = *(const float4*)&W2[(n * 64 + t) * 64 + kc];
        Ws2[swz(kc + 0, t)] = u.x; Ws2[swz(kc + 1, t)] = u.y;
        Ws2[swz(kc + 2, t)] = u.z; Ws2[swz(kc + 3, t)] = u.w;
    }
    __syncthreads();

    uint64_t acc1[4][2] = {}, acc2[4][2] = {};
    const int ty4 = ty * 4, tx4 = tx * 4;
#pragma unroll 4
    for (int k = 0; k < 64; k++) {
        const int co = ((k >> 2) & 7) << 2;
        float4 av;
        lds_f32x4(av, asb + (uint32_t)(k * 64 + (ty4 ^ co)) * 4);
        uint64_t a0 = pk2(av.x, av.x), a1 = pk2(av.y, av.y);
        uint64_t a2 = pk2(av.z, av.z), a3 = pk2(av.w, av.w);
        uint64_t b1l, b1h, b2l, b2h;
        lds_b64x2(b1l, b1h, w1b + (uint32_t)(k * 64 + (tx4 ^ co)) * 4);
        lds_b64x2(b2l, b2h, w2b + (uint32_t)(k * 64 + (tx4 ^ co)) * 4);
        acc1[0][0] = fma2(a0, b1l, acc1[0][0]); acc1[0][1] = fma2(a0, b1h, acc1[0][1]);
        acc1[1][0] = fma2(a1, b1l, acc1[1][0]); acc1[1][1] = fma2(a1, b1h, acc1[1][1]);
        acc1[2][0] = fma2(a2, b1l, acc1[2][0]); acc1[2][1] = fma2(a2, b1h, acc1[2][1]);
        acc1[3][0] = fma2(a3, b1l, acc1[3][0]); acc1[3][1] = fma2(a3, b1h, acc1[3][1]);
        acc2[0][0] = fma2(a0, b2l, acc2[0][0]); acc2[0][1] = fma2(a0, b2h, acc2[0][1]);
        acc2[1][0] = fma2(a1, b2l, acc2[1][0]); acc2[1][1] = fma2(a1, b2h, acc2[1][1]);
        acc2[2][0] = fma2(a2, b2l, acc2[2][0]); acc2[2][1] = fma2(a2, b2h, acc2[2][1]);
        acc2[3][0] = fma2(a3, b2l, acc2[3][0]); acc2[3][1] = fma2(a3, b2h, acc2[3][1]);
    }
#pragma unroll
    for (int q = 0; q < 4; q++) {
        int row = t0 + ty4 + q;
        float x0, x1, x2, x3;
        up2(x0, x1, acc1[q][0]); up2(x2, x3, acc1[q][1]);
        *(float4*)&out1[row * HH + n * 64 + tx4] =
            make_float4(silu_f(x0), silu_f(x1), silu_f(x2), silu_f(x3));
        up2(x0, x1, acc2[q][0]); up2(x2, x3, acc2[q][1]);
        *(float4*)&out2[row * HH + n * 64 + tx4] =
            make_float4(silu_f(x0), silu_f(x1), silu_f(x2), silu_f(x3));
    }
}

// ============ block-diagonal GEMM, K=192 (wpost), silu ============
__global__ void __launch_bounds__(256)
bd192_kernel(const float* __restrict__ in, const float* __restrict__ W,
             float* __restrict__ out) {
    __shared__ float As[64 * 64];
    __shared__ float Ws[64 * 64];
    const int t0 = blockIdx.x * 64;
    const int n = blockIdx.y;
    const int tid = threadIdx.x;
    const int tx = tid & 15, ty = tid >> 4;
    const uint32_t asb = smem_u32(As), wsb = smem_u32(Ws);
    const int ty4 = ty * 4, tx4 = tx * 4;

    uint64_t acc[4][2] = {};
    for (int c = 0; c < 3; c++) {
        for (int i = tid; i < 1024; i += 256) {
            int t = i >> 4, kc = (i & 15) << 2;
            float4 v = *(const float4*)&in[(t0 + t) * 3 * DD + n * 192 + c * 64 + kc];
            As[swz(kc + 0, t)] = v.x; As[swz(kc + 1, t)] = v.y;
            As[swz(kc + 2, t)] = v.z; As[swz(kc + 3, t)] = v.w;
            float4 w = *(const float4*)&W[(n * 64 + t) * 192 + c * 64 + kc];
            Ws[swz(kc + 0, t)] = w.x; Ws[swz(kc + 1, t)] = w.y;
            Ws[swz(kc + 2, t)] = w.z; Ws[swz(kc + 3, t)] = w.w;
        }
        __syncthreads();
#pragma unroll 4
        for (int k = 0; k < 64; k++) {
            const int co = ((k >> 2) & 7) << 2;
            float4 av;
            lds_f32x4(av, asb + (uint32_t)(k * 64 + (ty4 ^ co)) * 4);
            uint64_t a0 = pk2(av.x, av.x), a1 = pk2(av.y, av.y);
            uint64_t a2 = pk2(av.z, av.z), a3 = pk2(av.w, av.w);
            uint64_t bl, bh;
            lds_b64x2(bl, bh, wsb + (uint32_t)(k * 64 + (tx4 ^ co)) * 4);
            acc[0][0] = fma2(a0, bl, acc[0][0]); acc[0][1] = fma2(a0, bh, acc[0][1]);
            acc[1][0] = fma2(a1, bl, acc[1][0]); acc[1][1] = fma2(a1, bh, acc[1][1]);
            acc[2][0] = fma2(a2, bl, acc[2][0]); acc[2][1] = fma2(a2, bh, acc[2][1]);
            acc[3][0] = fma2(a3, bl, acc[3][0]); acc[3][1] = fma2(a3, bh, acc[3][1]);
        }
        __syncthreads();
    }
#pragma unroll
    for (int q = 0; q < 4; q++) {
        int row = t0 + ty4 + q;
        float x0, x1, x2, x3;
        up2(x0, x1, acc[q][0]); up2(x2, x3, acc[q][1]);
        *(float4*)&out[row * HH + n * 64 + tx4] =
            make_float4(silu_f(x0), silu_f(x1), silu_f(x2), silu_f(x3));
    }
}

// ============ residual update: x += blockdiag(r, wlocal) + tmp @ lowA^T ============
__global__ void __launch_bounds__(256)
update_kernel(float* __restrict__ x, const float* __restrict__ r,
              const float* __restrict__ tmp, const float* __restrict__ wlocal,
              const float* __restrict__ lowA) {
    __shared__ float As[64 * 64];
    __shared__ float Ws[64 * 64];
    const int t0 = blockIdx.x * 64;
    const int n = blockIdx.y;
    const int tid = threadIdx.x;
    const int tx = tid & 15, ty = tid >> 4;
    const uint32_t asb = smem_u32(As), wsb = smem_u32(Ws);
    const int ty4 = ty * 4, tx4 = tx * 4;

    uint64_t acc[4][2] = {};
    for (int ph = 0; ph < 2; ph++) {
        for (int i = tid; i < 1024; i += 256) {
            int t = i >> 4, kc = (i & 15) << 2;
            float4 v = (ph == 0)
                           ? *(const float4*)&r[(t0 + t) * HH + n * 64 + kc]
                           : *(const float4*)&tmp[(t0 + t) * RANKK + kc];
            As[swz(kc + 0, t)] = v.x; As[swz(kc + 1, t)] = v.y;
            As[swz(kc + 2, t)] = v.z; As[swz(kc + 3, t)] = v.w;
            float4 w = (ph == 0)
                           ? *(const float4*)&wlocal[(n * 64 + t) * 64 + kc]
                           : *(const float4*)&lowA[(n * 64 + t) * RANKK + kc];
            Ws[swz(kc + 0, t)] = w.x; Ws[swz(kc + 1, t)] = w.y;
            Ws[swz(kc + 2, t)] = w.z; Ws[swz(kc + 3, t)] = w.w;
        }
        __syncthreads();
#pragma unroll 4
        for (int k = 0; k < 64; k++) {
            const int co = ((k >> 2) & 7) << 2;
            float4 av;
            lds_f32x4(av, asb + (uint32_t)(k * 64 + (ty4 ^ co)) * 4);
            uint64_t a0 = pk2(av.x, av.x), a1 = pk2(av.y, av.y);
            uint64_t a2 = pk2(av.z, av.z), a3 = pk2(av.w, av.w);
            uint64_t bl, bh;
            lds_b64x2(bl, bh, wsb + (uint32_t)(k * 64 + (tx4 ^ co)) * 4);
            acc[0][0] = fma2(a0, bl, acc[0][0]); acc[0][1] = fma2(a0, bh, acc[0][1]);
            acc[1][0] = fma2(a1, bl, acc[1][0]); acc[1][1] = fma2(a1, bh, acc[1][1]);
            acc[2][0] = fma2(a2, bl, acc[2][0]); acc[2][1] = fma2(a2, bh, acc[2][1]);
            acc[3][0] = fma2(a3, bl, acc[3][0]); acc[3][1] = fma2(a3, bh, acc[3][1]);
        }
        __syncthreads();
    }
#pragma unroll
    for (int q = 0; q < 4; q++) {
        int row = t0 + ty4 + q;
        float x0, x1, x2, x3;
        up2(x0, x1, acc[q][0]); up2(x2, x3, acc[q][1]);
        float4* px = (float4*)&x[row * DD + n * 64 + tx4];
        float4 v = *px;
        v.x += x0; v.y += x1; v.z += x2; v.w += x3;
        *px = v;
    }
}

// ============ lowrank stage 1: tmp[2048,64] = r @ lowB^T ============
__global__ void __launch_bounds__(256)
lowrank1_kernel(const float* __restrict__ r, const float* __restrict__ lowB,
                float* __restrict__ tmp) {
    __shared__ float As[16 * 64];
    __shared__ float Ws[64 * 64];
    const int t0 = blockIdx.x * 16;
    const int tid = threadIdx.x;
    const int tx = tid & 15, ty = tid >> 4;
    const uint32_t wsb = smem_u32(Ws);
    const int tx4 = tx * 4;
    uint64_t acc[2] = {};
    for (int c = 0; c < 16; c++) {
        {
            int t = tid >> 4, kc = (tid & 15) << 2;
            *(float4*)&As[t * 64 + kc] = *(const float4*)&r[(t0 + t) * HH + c * 64 + kc];
        }
        for (int i = tid; i < 1024; i += 256) {
            int o = i >> 4, kc = (i & 15) << 2;
            float4 w = *(const float4*)&lowB[o * HH + c * 64 + kc];
            Ws[swz(kc + 0, o)] = w.x; Ws[swz(kc + 1, o)] = w.y;
            Ws[swz(kc + 2, o)] = w.z; Ws[swz(kc + 3, o)] = w.w;
        }
        __syncthreads();
#pragma unroll 8
        for (int k = 0; k < 64; k++) {
            const int co = ((k >> 2) & 7) << 2;
            float a = As[ty * 64 + k];
            uint64_t ap = pk2(a, a);
            uint64_t bl, bh;
            lds_b64x2(bl, bh, wsb + (uint32_t)(k * 64 + (tx4 ^ co)) * 4);
            acc[0] = fma2(ap, bl, acc[0]);
            acc[1] = fma2(ap, bh, acc[1]);
        }
        __syncthreads();
    }
    float x0, x1, x2, x3;
    up2(x0, x1, acc[0]); up2(x2, x3, acc[1]);
    *(float4*)&tmp[(t0 + ty) * RANKK + tx4] = make_float4(x0, x1, x2, x3);
}

// ============ causal scan, 3-phase chunked ============
__global__ void scanA_kernel(float* __restrict__ buf, const float* __restrict__ logA,
                             const float* __restrict__ logdt, float* __restrict__ seg) {
    int d = blockIdx.x * 32 + threadIdx.x;
    int s = blockIdx.y * 8 + threadIdx.y;
    float a = expf(-expf(logA[d]) * expf(logdt[d]));
    float y = 0.f;
    int t0 = s * SEGLEN;
#pragma unroll 8
    for (int tt = 0; tt < SEGLEN; tt++) {
        int i = (t0 + tt) * DD + d;
        y = a * y + buf[i];
        buf[i] = y;
    }
    seg[s * DD + d] = y;
}

__global__ void scanB_kernel(float* __restrict__ seg, const float* __restrict__ logA,
                             const float* __restrict__ logdt) {
    int d = blockIdx.x * 16 + threadIdx.x;
    int j = threadIdx.y;
    float a = expf(-expf(logA[d]) * expf(logdt[d]));
    float a32 = a;
#pragma unroll
    for (int q = 0; q < 5; q++) a32 *= a32;
    __shared__ float s[NSEG][17];
    float cur = seg[j * DD + d];
    s[j][threadIdx.x] = cur;
    float m = a32;
    for (int st = 1; st < NSEG; st <<= 1) {
        __syncthreads();
        float prev = (j >= st) ? s[j - st][threadIdx.x] : 0.f;
        __syncthreads();
        cur += m * prev;
        s[j][threadIdx.x] = cur;
        m = m * m;
    }
    seg[j * DD + d] = cur;
}

__global__ void scanC_kernel(float* __restrict__ buf, const float* __restrict__ logA,
                             const float* __restrict__ logdt, const float* __restrict__ seg) {
    int d = blockIdx.x * 32 + threadIdx.x;
    int s = blockIdx.y * 8 + threadIdx.y;
    if (s == 0) return;
    float a = expf(-expf(logA[d]) * expf(logdt[d]));
    float carry = seg[(s - 1) * DD + d];
    float f = a;
    int t0 = s * SEGLEN;
#pragma unroll 8
    for (int tt = 0; tt < SEGLEN; tt++) {
        int i = (t0 + tt) * DD + d;
        buf[i] += f * carry;
        f *= a;
    }
}

// ---------------- combine + rmsnorm + concat ----------------
__global__ void combine_prep_kernel(const float* __restrict__ hseq, const float* __restrict__ udep,
                                    const float* __restrict__ e, const float* __restrict__ logAd,
                                    const float* __restrict__ logdtd, const int* __restrict__ pK,
                                    float* __restrict__ c) {
    int t = blockIdx.x;
    int tid = threadIdx.x;
    int K = *pK;
    float hv[4];
    float ss = 0.f;
#pragma unroll
    for (int r = 0; r < 4; r++) {
        int d = tid + r * 256;
        float g;
        if (d < NMEM) {
            g = (float)K;
        } else {
            float aD = expf(-expf(logAd[d - NMEM]) * expf(logdtd[d - NMEM]));
            float om = 1.f - aD;
            float safe = fmaxf(om, 1e-8f);
            float p = 1.f;
            for (int k = 0; k < K; k++) p *= aD;
            g = (fabsf(om) < 1e-6f) ? (float)K : (1.f - p) / safe;
        }
        float h = hseq[t * DD + d] + g * udep[t * DD + d];
        hv[r] = h;
        ss += h * h;
    }
    __shared__ float red[256];
    red[tid] = ss;
    __syncthreads();
    for (int s = 128; s > 0; s >>= 1) {
        if (tid < s) red[tid] += red[tid + s];
        __syncthreads();
    }
    float sc = rsqrtf(red[0] / (float)DD + RMS_EPS);
#pragma unroll
    for (int r = 0; r < 4; r++) {
        int d = tid + r * 256;
        c[t * 3 * DD + d] = hv[r] * sc;
        c[t * 3 * DD + DD + d] = e[t * DD + d];
        c[t * 3 * DD + 2 * DD + d] = (t > 0) ? e[(t - 1) * DD + d] : 0.f;
    }
}

// ================= LM head GEMM (mma.sync tf32, 3-stage cp.async) =================
#define GSTRIDE 36
#define A_STAGE_B (128 * GSTRIDE * 4)
#define B_STAGE_B (256 * GSTRIDE * 4)
#define NSTG 3
#define LM_SMEM (NSTG * (A_STAGE_B + B_STAGE_B))  // 165888

#define MMA_TF32(c, a, b)                                                              \
    asm volatile(                                                                      \
        "mma.sync.aligned.m16n8k8.row.col.f32.tf32.tf32.f32 "                          \
        "{%0,%1,%2,%3},{%4,%5,%6,%7},{%8,%9},{%0,%1,%2,%3};\n"                         \
        : "+f"(c[0]), "+f"(c[1]), "+f"(c[2]), "+f"(c[3])                               \
        : "r"(a[0]), "r"(a[1]), "r"(a[2]), "r"(a[3]), "r"(b[0]), "r"(b[1]))

__global__ void __launch_bounds__(256, 1)
lmhead_gemm(const float* __restrict__ A, const float* __restrict__ B, float* __restrict__ C) {
    extern __shared__ __align__(16) float smf[];
    const uint32_t smb = smem_u32(smf);
    const int tid = threadIdx.x;
    const int lane = tid & 31;
    const int warp = tid >> 5;
    const int M0 = blockIdx.x * 128;
    const int N0 = blockIdx.y * 256;
    const int nVal = (VV - N0 < 256) ? (VV - N0) : 256;
    const int wm = (warp >> 2) * 64;
    const int wn = (warp & 3) * 64;
    const int rr = lane >> 2;
    const int kc = lane & 3;

    float acc[4][8][4];
#pragma unroll
    for (int i = 0; i < 4; i++)
#pragma unroll
        for (int j = 0; j < 8; j++)
#pragma unroll
            for (int k = 0; k < 4; k++) acc[i][j][k] = 0.f;

#define LOAD_STAGE(s, kb)                                                              \
    {                                                                                  \
        _Pragma("unroll") for (int i = 0; i < 4; i++) {                                \
            int cch = tid + i * 256;                                                   \
            int m = cch >> 3, q = cch & 7;                                             \
            uint32_t dst = smb + (s) * A_STAGE_B + (uint32_t)(m * GSTRIDE + q * 4) * 4;\
            const float* src = A + (size_t)(M0 + m) * DD + (kb) * 32 + q * 4;          \
            cp16(dst, src, 16);                                                        \
        }                                                                              \
        _Pragma("unroll") for (int i = 0; i < 8; i++) {                                \
            int cch = tid + i * 256;                                                   \
            int n = cch >> 3, q = cch & 7;                                             \
            uint32_t dst = smb + NSTG * A_STAGE_B + (s) * B_STAGE_B +                  \
                           (uint32_t)(n * GSTRIDE + q * 4) * 4;                        \
            int ok = (n < nVal);                                                       \
            const float* src = B + (size_t)(N0 + (ok ? n : 0)) * DD + (kb) * 32 + q * 4;\
            cp16(dst, src, ok ? 16 : 0);                                               \
        }                                                                              \
        CP_COMMIT();                                                                   \
    }

    LOAD_STAGE(0, 0);
    LOAD_STAGE(1, 1);

    const int NKB = DD / 32;  // 32
    for (int kb = 0; kb < NKB; kb++) {
        const int s = kb % NSTG;
        if (kb + 1 < NKB) {
            asm volatile("cp.async.wait_group 1;" ::: "memory");
        } else {
            asm volatile("cp.async.wait_group 0;" ::: "memory");
        }
        __syncthreads();
        if (kb + 2 < NKB) LOAD_STAGE((kb + 2) % NSTG, kb + 2);

        const float* As = smf + s * (A_STAGE_B / 4);
        const float* Bs = smf + NSTG * (A_STAGE_B / 4) + s * (B_STAGE_B / 4);

#pragma unroll
        for (int ks = 0; ks < 32; ks += 8) {
            unsigned af[4][4], bf[8][2];
#pragma unroll
            for (int mi = 0; mi < 4; mi++) {
                int base = (wm + mi * 16 + rr) * GSTRIDE + ks + kc;
                af[mi][0] = __float_as_uint(As[base]);
                af[mi][1] = __float_as_uint(As[base + 8 * GSTRIDE]);
                af[mi][2] = __float_as_uint(As[base + 4]);
                af[mi][3] = __float_as_uint(As[base + 8 * GSTRIDE + 4]);
            }
#pragma unroll
            for (int nj = 0; nj < 8; nj++) {
                int base = (wn + nj * 8 + rr) * GSTRIDE + ks + kc;
                bf[nj][0] = __float_as_uint(Bs[base]);
                bf[nj][1] = __float_as_uint(Bs[base + 4]);
            }
#pragma unroll
            for (int mi = 0; mi < 4; mi++)
#pragma unroll
                for (int nj = 0; nj < 8; nj++) MMA_TF32(acc[mi][nj], af[mi], bf[nj]);
        }
    }

    // epilogue
#pragma unroll
    for (int mi = 0; mi < 4; mi++) {
#pragma unroll
        for (int nj = 0; nj < 8; nj++) {
            int c0 = N0 + wn + nj * 8 + (kc << 1);
            if (c0 < VV) {
                size_t r0 = (size_t)(M0 + wm + mi * 16 + rr);
                *(float2*)(C + r0 * VV + c0) = make_float2(acc[mi][nj][0], acc[mi][nj][1]);
                *(float2*)(C + (r0 + 8) * VV + c0) = make_float2(acc[mi][nj][2], acc[mi][nj][3]);
            }
        }
    }
}

// ---------------- launcher ----------------
extern "C" void kernel_launch(void* const* d_in, const int* in_sizes, int n_in,
                              void* d_out, int out_size) {
    const int* idx = (const int*)d_in[0];
    const int* pK = (const int*)d_in[1];
    const float* wte = (const float*)d_in[2];
    const float* wpe = (const float*)d_in[3];
    const float* bseq_w = (const float*)d_in[4];
    const float* logA_seq = (const float*)d_in[5];
    const float* logdt_seq = (const float*)d_in[6];
    const float* bdepth_w = (const float*)d_in[7];
    const float* logA_depth = (const float*)d_in[8];
    const float* logdt_depth = (const float*)d_in[9];
    const float* wpost_w = (const float*)d_in[10];
    const float* wlocal_w = (const float*)d_in[11];
    const float* lowA = (const float*)d_in[12];
    const float* lowB = (const float*)d_in[13];
    const float* lm_head_w = (const float*)d_in[14];
    float* out = (float*)d_out;

    float *x, *e, *h, *ud, *c, *r, *tmp, *xn, *seg, *Btf;
    cudaGetSymbolAddress((void**)&x, g_x);
    cudaGetSymbolAddress((void**)&e, g_e);
    cudaGetSymbolAddress((void**)&h, g_h);
    cudaGetSymbolAddress((void**)&ud, g_ud);
    cudaGetSymbolAddress((void**)&c, g_c);
    cudaGetSymbolAddress((void**)&r, g_r);
    cudaGetSymbolAddress((void**)&tmp, g_tmp);
    cudaGetSymbolAddress((void**)&xn, g_xn);
    cudaGetSymbolAddress((void**)&seg, g_seg);
    cudaGetSymbolAddress((void**)&Btf, g_Btf);

    cudaFuncSetAttribute(lmhead_gemm, cudaFuncAttributeMaxDynamicSharedMemorySize, LM_SMEM);

    tf32_convert_kernel<<<(VV * DD) / 1024, 256>>>(lm_head_w, Btf);

    embed_kernel<<<TT, 256>>>(idx, wte, wpe, x);

    for (int l = 0; l < LYR; l++) {
        const float* bseq_l = bseq_w + l * NBLK * 64 * 64;
        const float* lAs = logA_seq + l * HH;
        const float* lDs = logdt_seq + l * HH;
        const float* bdep_l = bdepth_w + l * NBLK * 64 * 64;
        const float* lAd = logA_depth + l * (HH - NMEM);
        const float* lDd = logdt_depth + l * (HH - NMEM);
        const float* wpost_l = wpost_w + l * NBLK * 64 * 192;
        const float* wlocal_l = wlocal_w + l * NBLK * 64 * 64;
        const float* lowA_l = lowA + l * DD * RANKK;
        const float* lowB_l = lowB + l * RANKK * HH;

        rmsnorm_kernel<<<TT, 256>>>(x, e);
        bd64_dual_kernel<<<dim3(TT / 64, NBLK), 256>>>(e, bseq_l, bdep_l, h, ud);
        scanA_kernel<<<dim3(32, 8), dim3(32, 8)>>>(h, lAs, lDs, seg);
        scanB_kernel<<<DD / 16, dim3(16, NSEG)>>>(seg, lAs, lDs);
        scanC_kernel<<<dim3(32, 8), dim3(32, 8)>>>(h, lAs, lDs, seg);
        combine_prep_kernel<<<TT, 256>>>(h, ud, e, lAd, lDd, pK, c);
        bd192_kernel<<<dim3(TT / 64, NBLK), 256>>>(c, wpost_l, r);
        lowrank1_kernel<<<TT / 16, 256>>>(r, lowB_l, tmp);
        update_kernel<<<dim3(TT / 64, NBLK), 256>>>(x, r, tmp, wlocal_l, lowA_l);
    }

    rmsnorm_tf32_kernel<<<TT, 256>>>(x, xn);
    lmhead_gemm<<<dim3(TT / 128, (VV + 255) / 256), 256, LM_SMEM>>>(xn, Btf, out);
}

// round 10
// speedup vs baseline: 1.4969x; 1.0448x over previous
#include <cuda_runtime.h>
#include <cuda_bf16.h>
#include <math.h>
#include <stdint.h>

#define TT 2048
#define DD 1024
#define HH 1024
#define NBLK 16
#define LYR 4
#define RANKK 64
#define NMEM 64
#define VV 50304
#define RMS_EPS 1.1920929e-7f
#define SEGLEN 32
#define NSEG 64

// ---------------- scratch (static device arrays; no allocation) ----------------
__device__ float g_x[TT * DD];
__device__ float g_e[TT * DD];
__device__ float g_h[TT * DD];
__device__ float g_ud[TT * DD];
__device__ float g_c[TT * 3 * DD];
__device__ float g_r[TT * DD];
__device__ float g_tmp[TT * RANKK];
__device__ float g_xn[TT * DD];           // final rmsnorm, tf32-rounded, k-pair-permuted
__device__ float g_seg[NSEG * DD];
__device__ float g_Btf[(size_t)VV * DD];  // lm_head weights, tf32-rounded, k-pair-permuted

// ---------------- helpers ----------------
__device__ __forceinline__ float silu_f(float x) { return x / (1.0f + expf(-x)); }

__device__ __forceinline__ float tf32r(float x) {
    unsigned u;
    asm("cvt.rna.tf32.f32 %0, %1;" : "=r"(u) : "f"(x));
    return __uint_as_float(u);
}

__device__ __forceinline__ uint32_t smem_u32(const void* p) {
    uint32_t a;
    asm("{ .reg .u64 t; cvta.to.shared.u64 t, %1; cvt.u32.u64 %0, t; }" : "=r"(a) : "l"(p));
    return a;
}

__device__ __forceinline__ void cp16(uint32_t dst, const void* src, int sz) {
    asm volatile("cp.async.cg.shared.global [%0], [%1], 16, %2;"
                 :: "r"(dst), "l"(src), "r"(sz) : "memory");
}
#define CP_COMMIT() asm volatile("cp.async.commit_group;" ::: "memory")

// packed f32x2 helpers
__device__ __forceinline__ uint64_t pk2(float x, float y) {
    uint64_t r;
    asm("mov.b64 %0, {%1,%2};" : "=l"(r) : "f"(x), "f"(y));
    return r;
}
__device__ __forceinline__ void up2(float& x, float& y, uint64_t p) {
    asm("mov.b64 {%0,%1}, %2;" : "=f"(x), "=f"(y) : "l"(p));
}
__device__ __forceinline__ uint64_t fma2(uint64_t a, uint64_t b, uint64_t c) {
    uint64_t d;
    asm("fma.rn.f32x2 %0, %1, %2, %3;" : "=l"(d) : "l"(a), "l"(b), "l"(c));
    return d;
}
__device__ __forceinline__ void lds_b64x2(uint64_t& lo, uint64_t& hi, uint32_t addr) {
    asm volatile("ld.shared.v2.b64 {%0,%1}, [%2];" : "=l"(lo), "=l"(hi) : "r"(addr));
}
__device__ __forceinline__ void lds_f32x4(float4& v, uint32_t addr) {
    asm volatile("ld.shared.v4.f32 {%0,%1,%2,%3}, [%4];"
                 : "=f"(v.x), "=f"(v.y), "=f"(v.z), "=f"(v.w) : "r"(addr));
}

// XOR swizzle for layer kernels
__device__ __forceinline__ int swz(int k, int o) {
    return k * 64 + (o ^ (((k >> 2) & 7) << 2));
}

// ---------------- embedding ----------------
__global__ void embed_kernel(const int* __restrict__ idx, const float* __restrict__ wte,
                             const float* __restrict__ wpe, float* __restrict__ x) {
    int t = blockIdx.x;
    int row = idx[t];
    const float4* wrow = (const float4*)(wte + (long)row * DD);
    const float4* prow = (const float4*)(wpe + (long)t * DD);
    float4* xo = (float4*)(x + t * DD);
    for (int d = threadIdx.x; d < DD / 4; d += blockDim.x) {
        float4 a = wrow[d], b = prow[d];
        xo[d] = make_float4(a.x + b.x, a.y + b.y, a.z + b.z, a.w + b.w);
    }
}

// ---------------- rmsnorm ----------------
__global__ void rmsnorm_kernel(const float* __restrict__ in, float* __restrict__ out) {
    int t = blockIdx.x;
    int tid = threadIdx.x;
    float4 v = ((const float4*)(in + t * DD))[tid];
    float ss = v.x * v.x + v.y * v.y + v.z * v.z + v.w * v.w;
    __shared__ float red[256];
    red[tid] = ss;
    __syncthreads();
    for (int s = 128; s > 0; s >>= 1) {
        if (tid < s) red[tid] += red[tid + s];
        __syncthreads();
    }
    float sc = rsqrtf(red[0] / (float)DD + RMS_EPS);
    ((float4*)(out + t * DD))[tid] = make_float4(v.x * sc, v.y * sc, v.z * sc, v.w * sc);
}

// final rmsnorm: tf32-rounded AND k-pair-permuted (zip of each 8-group: (k, k+4) adjacent)
__global__ void rmsnorm_tf32_kernel(const float* __restrict__ in, float* __restrict__ out) {
    int t = blockIdx.x;
    int tid = threadIdx.x;
    __shared__ float4 buf[256];
    __shared__ float red[256];
    float4 v = ((const float4*)(in + t * DD))[tid];
    buf[tid] = v;
    red[tid] = v.x * v.x + v.y * v.y + v.z * v.z + v.w * v.w;
    __syncthreads();
    for (int s = 128; s > 0; s >>= 1) {
        if (tid < s) red[tid] += red[tid + s];
        __syncthreads();
    }
    float sc = rsqrtf(red[0] / (float)DD + RMS_EPS);
    int g = tid >> 1, h = tid & 1;
    float4 lo = buf[g * 2], hi = buf[g * 2 + 1];
    float4 o = (h == 0) ? make_float4(lo.x, hi.x, lo.y, hi.y)
                        : make_float4(lo.z, hi.z, lo.w, hi.w);
    ((float4*)(out + t * DD))[tid] =
        make_float4(tf32r(o.x * sc), tf32r(o.y * sc), tf32r(o.z * sc), tf32r(o.w * sc));
}

// tf32-round + k-pair-permute lm_head weights. One thread per 8-float group.
__global__ void tf32_convert_kernel(const float* __restrict__ in, float* __restrict__ out) {
    int i = blockIdx.x * blockDim.x + threadIdx.x;
    const float4* in4 = (const float4*)in;
    float4 lo = in4[i * 2], hi = in4[i * 2 + 1];
    float4* out4 = (float4*)out;
    out4[i * 2] = make_float4(tf32r(lo.x), tf32r(hi.x), tf32r(lo.y), tf32r(hi.y));
    out4[i * 2 + 1] = make_float4(tf32r(lo.z), tf32r(hi.z), tf32r(lo.w), tf32r(hi.w));
}

// ============ dual block-diagonal GEMM, K=64, silu (f32x2, swizzled smem) ============
__global__ void __launch_bounds__(256)
bd64_dual_kernel(const float* __restrict__ in, const float* __restrict__ W1,
                 const float* __restrict__ W2, float* __restrict__ out1,
                 float* __restrict__ out2) {
    __shared__ float As[64 * 64];
    __shared__ float Ws1[64 * 64];
    __shared__ float Ws2[64 * 64];
    const int t0 = blockIdx.x * 64;
    const int n = blockIdx.y;
    const int tid = threadIdx.x;
    const int tx = tid & 15, ty = tid >> 4;
    const uint32_t asb = smem_u32(As), w1b = smem_u32(Ws1), w2b = smem_u32(Ws2);

    for (int i = tid; i < 1024; i += 256) {
        int t = i >> 4, kc = (i & 15) << 2;
        float4 v = *(const float4*)&in[(t0 + t) * DD + n * 64 + kc];
        As[swz(kc + 0, t)] = v.x; As[swz(kc + 1, t)] = v.y;
        As[swz(kc + 2, t)] = v.z; As[swz(kc + 3, t)] = v.w;
        float4 w = *(const float4*)&W1[(n * 64 + t) * 64 + kc];
        Ws1[swz(kc + 0, t)] = w.x; Ws1[swz(kc + 1, t)] = w.y;
        Ws1[swz(kc + 2, t)] = w.z; Ws1[swz(kc + 3, t)] = w.w;
        float4 u = *(const float4*)&W2[(n * 64 + t) * 64 + kc];
        Ws2[swz(kc + 0, t)] = u.x; Ws2[swz(kc + 1, t)] = u.y;
        Ws2[swz(kc + 2, t)] = u.z; Ws2[swz(kc + 3, t)] = u.w;
    }
    __syncthreads();

    uint64_t acc1[4][2] = {}, acc2[4][2] = {};
    const int ty4 = ty * 4, tx4 = tx * 4;
#pragma unroll 4
    for (int k = 0; k < 64; k++) {
        const int co = ((k >> 2) & 7) << 2;
        float4 av;
        lds_f32x4(av, asb + (uint32_t)(k * 64 + (ty4 ^ co)) * 4);
        uint64_t a0 = pk2(av.x, av.x), a1 = pk2(av.y, av.y);
        uint64_t a2 = pk2(av.z, av.z), a3 = pk2(av.w, av.w);
        uint64_t b1l, b1h, b2l, b2h;
        lds_b64x2(b1l, b1h, w1b + (uint32_t)(k * 64 + (tx4 ^ co)) * 4);
        lds_b64x2(b2l, b2h, w2b + (uint32_t)(k * 64 + (tx4 ^ co)) * 4);
        acc1[0][0] = fma2(a0, b1l, acc1[0][0]); acc1[0][1] = fma2(a0, b1h, acc1[0][1]);
        acc1[1][0] = fma2(a1, b1l, acc1[1][0]); acc1[1][1] = fma2(a1, b1h, acc1[1][1]);
        acc1[2][0] = fma2(a2, b1l, acc1[2][0]); acc1[2][1] = fma2(a2, b1h, acc1[2][1]);
        acc1[3][0] = fma2(a3, b1l, acc1[3][0]); acc1[3][1] = fma2(a3, b1h, acc1[3][1]);
        acc2[0][0] = fma2(a0, b2l, acc2[0][0]); acc2[0][1] = fma2(a0, b2h, acc2[0][1]);
        acc2[1][0] = fma2(a1, b2l, acc2[1][0]); acc2[1][1] = fma2(a1, b2h, acc2[1][1]);
        acc2[2][0] = fma2(a2, b2l, acc2[2][0]); acc2[2][1] = fma2(a2, b2h, acc2[2][1]);
        acc2[3][0] = fma2(a3, b2l, acc2[3][0]); acc2[3][1] = fma2(a3, b2h, acc2[3][1]);
    }
#pragma unroll
    for (int q = 0; q < 4; q++) {
        int row = t0 + ty4 + q;
        float x0, x1, x2, x3;
        up2(x0, x1, acc1[q][0]); up2(x2, x3, acc1[q][1]);
        *(float4*)&out1[row * HH + n * 64 + tx4] =
            make_float4(silu_f(x0), silu_f(x1), silu_f(x2), silu_f(x3));
        up2(x0, x1, acc2[q][0]); up2(x2, x3, acc2[q][1]);
        *(float4*)&out2[row * HH + n * 64 + tx4] =
            make_float4(silu_f(x0), silu_f(x1), silu_f(x2), silu_f(x3));
    }
}

// ============ block-diagonal GEMM, K=192 (wpost), silu ============
__global__ void __launch_bounds__(256)
bd192_kernel(const float* __restrict__ in, const float* __restrict__ W,
             float* __restrict__ out) {
    __shared__ float As[64 * 64];
    __shared__ float Ws[64 * 64];
    const int t0 = blockIdx.x * 64;
    const int n = blockIdx.y;
    const int tid = threadIdx.x;
    const int tx = tid & 15, ty = tid >> 4;
    const uint32_t asb = smem_u32(As), wsb = smem_u32(Ws);
    const int ty4 = ty * 4, tx4 = tx * 4;

    uint64_t acc[4][2] = {};
    for (int c = 0; c < 3; c++) {
        for (int i = tid; i < 1024; i += 256) {
            int t = i >> 4, kc = (i & 15) << 2;
            float4 v = *(const float4*)&in[(t0 + t) * 3 * DD + n * 192 + c * 64 + kc];
            As[swz(kc + 0, t)] = v.x; As[swz(kc + 1, t)] = v.y;
            As[swz(kc + 2, t)] = v.z; As[swz(kc + 3, t)] = v.w;
            float4 w = *(const float4*)&W[(n * 64 + t) * 192 + c * 64 + kc];
            Ws[swz(kc + 0, t)] = w.x; Ws[swz(kc + 1, t)] = w.y;
            Ws[swz(kc + 2, t)] = w.z; Ws[swz(kc + 3, t)] = w.w;
        }
        __syncthreads();
#pragma unroll 4
        for (int k = 0; k < 64; k++) {
            const int co = ((k >> 2) & 7) << 2;
            float4 av;
            lds_f32x4(av, asb + (uint32_t)(k * 64 + (ty4 ^ co)) * 4);
            uint64_t a0 = pk2(av.x, av.x), a1 = pk2(av.y, av.y);
            uint64_t a2 = pk2(av.z, av.z), a3 = pk2(av.w, av.w);
            uint64_t bl, bh;
            lds_b64x2(bl, bh, wsb + (uint32_t)(k * 64 + (tx4 ^ co)) * 4);
            acc[0][0] = fma2(a0, bl, acc[0][0]); acc[0][1] = fma2(a0, bh, acc[0][1]);
            acc[1][0] = fma2(a1, bl, acc[1][0]); acc[1][1] = fma2(a1, bh, acc[1][1]);
            acc[2][0] = fma2(a2, bl, acc[2][0]); acc[2][1] = fma2(a2, bh, acc[2][1]);
            acc[3][0] = fma2(a3, bl, acc[3][0]); acc[3][1] = fma2(a3, bh, acc[3][1]);
        }
        __syncthreads();
    }
#pragma unroll
    for (int q = 0; q < 4; q++) {
        int row = t0 + ty4 + q;
        float x0, x1, x2, x3;
        up2(x0, x1, acc[q][0]); up2(x2, x3, acc[q][1]);
        *(float4*)&out[row * HH + n * 64 + tx4] =
            make_float4(silu_f(x0), silu_f(x1), silu_f(x2), silu_f(x3));
    }
}

// ============ residual update ============
__global__ void __launch_bounds__(256)
update_kernel(float* __restrict__ x, const float* __restrict__ r,
              const float* __restrict__ tmp, const float* __restrict__ wlocal,
              const float* __restrict__ lowA) {
    __shared__ float As[64 * 64];
    __shared__ float Ws[64 * 64];
    const int t0 = blockIdx.x * 64;
    const int n = blockIdx.y;
    const int tid = threadIdx.x;
    const int tx = tid & 15, ty = tid >> 4;
    const uint32_t asb = smem_u32(As), wsb = smem_u32(Ws);
    const int ty4 = ty * 4, tx4 = tx * 4;

    uint64_t acc[4][2] = {};
    for (int ph = 0; ph < 2; ph++) {
        for (int i = tid; i < 1024; i += 256) {
            int t = i >> 4, kc = (i & 15) << 2;
            float4 v = (ph == 0)
                           ? *(const float4*)&r[(t0 + t) * HH + n * 64 + kc]
                           : *(const float4*)&tmp[(t0 + t) * RANKK + kc];
            As[swz(kc + 0, t)] = v.x; As[swz(kc + 1, t)] = v.y;
            As[swz(kc + 2, t)] = v.z; As[swz(kc + 3, t)] = v.w;
            float4 w = (ph == 0)
                           ? *(const float4*)&wlocal[(n * 64 + t) * 64 + kc]
                           : *(const float4*)&lowA[(n * 64 + t) * RANKK + kc];
            Ws[swz(kc + 0, t)] = w.x; Ws[swz(kc + 1, t)] = w.y;
            Ws[swz(kc + 2, t)] = w.z; Ws[swz(kc + 3, t)] = w.w;
        }
        __syncthreads();
#pragma unroll 4
        for (int k = 0; k < 64; k++) {
            const int co = ((k >> 2) & 7) << 2;
            float4 av;
            lds_f32x4(av, asb + (uint32_t)(k * 64 + (ty4 ^ co)) * 4);
            uint64_t a0 = pk2(av.x, av.x), a1 = pk2(av.y, av.y);
            uint64_t a2 = pk2(av.z, av.z), a3 = pk2(av.w, av.w);
            uint64_t bl, bh;
            lds_b64x2(bl, bh, wsb + (uint32_t)(k * 64 + (tx4 ^ co)) * 4);
            acc[0][0] = fma2(a0, bl, acc[0][0]); acc[0][1] = fma2(a0, bh, acc[0][1]);
            acc[1][0] = fma2(a1, bl, acc[1][0]); acc[1][1] = fma2(a1, bh, acc[1][1]);
            acc[2][0] = fma2(a2, bl, acc[2][0]); acc[2][1] = fma2(a2, bh, acc[2][1]);
            acc[3][0] = fma2(a3, bl, acc[3][0]); acc[3][1] = fma2(a3, bh, acc[3][1]);
        }
        __syncthreads();
    }
#pragma unroll
    for (int q = 0; q < 4; q++) {
        int row = t0 + ty4 + q;
        float x0, x1, x2, x3;
        up2(x0, x1, acc[q][0]); up2(x2, x3, acc[q][1]);
        float4* px = (float4*)&x[row * DD + n * 64 + tx4];
        float4 v = *px;
        v.x += x0; v.y += x1; v.z += x2; v.w += x3;
        *px = v;
    }
}

// ============ lowrank stage 1 ============
__global__ void __launch_bounds__(256)
lowrank1_kernel(const float* __restrict__ r, const float* __restrict__ lowB,
                float* __restrict__ tmp) {
    __shared__ float As[16 * 64];
    __shared__ float Ws[64 * 64];
    const int t0 = blockIdx.x * 16;
    const int tid = threadIdx.x;
    const int tx = tid & 15, ty = tid >> 4;
    const uint32_t wsb = smem_u32(Ws);
    const int tx4 = tx * 4;
    uint64_t acc[2] = {};
    for (int c = 0; c < 16; c++) {
        {
            int t = tid >> 4, kc = (tid & 15) << 2;
            *(float4*)&As[t * 64 + kc] = *(const float4*)&r[(t0 + t) * HH + c * 64 + kc];
        }
        for (int i = tid; i < 1024; i += 256) {
            int o = i >> 4, kc = (i & 15) << 2;
            float4 w = *(const float4*)&lowB[o * HH + c * 64 + kc];
            Ws[swz(kc + 0, o)] = w.x; Ws[swz(kc + 1, o)] = w.y;
            Ws[swz(kc + 2, o)] = w.z; Ws[swz(kc + 3, o)] = w.w;
        }
        __syncthreads();
#pragma unroll 8
        for (int k = 0; k < 64; k++) {
            const int co = ((k >> 2) & 7) << 2;
            float a = As[ty * 64 + k];
            uint64_t ap = pk2(a, a);
            uint64_t bl, bh;
            lds_b64x2(bl, bh, wsb + (uint32_t)(k * 64 + (tx4 ^ co)) * 4);
            acc[0] = fma2(ap, bl, acc[0]);
            acc[1] = fma2(ap, bh, acc[1]);
        }
        __syncthreads();
    }
    float x0, x1, x2, x3;
    up2(x0, x1, acc[0]); up2(x2, x3, acc[1]);
    *(float4*)&tmp[(t0 + ty) * RANKK + tx4] = make_float4(x0, x1, x2, x3);
}

// ============ causal scan, 3-phase chunked ============
__global__ void scanA_kernel(float* __restrict__ buf, const float* __restrict__ logA,
                             const float* __restrict__ logdt, float* __restrict__ seg) {
    int d = blockIdx.x * 32 + threadIdx.x;
    int s = blockIdx.y * 8 + threadIdx.y;
    float a = expf(-expf(logA[d]) * expf(logdt[d]));
    float y = 0.f;
    int t0 = s * SEGLEN;
#pragma unroll 8
    for (int tt = 0; tt < SEGLEN; tt++) {
        int i = (t0 + tt) * DD + d;
        y = a * y + buf[i];
        buf[i] = y;
    }
    seg[s * DD + d] = y;
}

__global__ void scanB_kernel(float* __restrict__ seg, const float* __restrict__ logA,
                             const float* __restrict__ logdt) {
    int d = blockIdx.x * 16 + threadIdx.x;
    int j = threadIdx.y;
    float a = expf(-expf(logA[d]) * expf(logdt[d]));
    float a32 = a;
#pragma unroll
    for (int q = 0; q < 5; q++) a32 *= a32;
    __shared__ float s[NSEG][17];
    float cur = seg[j * DD + d];
    s[j][threadIdx.x] = cur;
    float m = a32;
    for (int st = 1; st < NSEG; st <<= 1) {
        __syncthreads();
        float prev = (j >= st) ? s[j - st][threadIdx.x] : 0.f;
        __syncthreads();
        cur += m * prev;
        s[j][threadIdx.x] = cur;
        m = m * m;
    }
    seg[j * DD + d] = cur;
}

__global__ void scanC_kernel(float* __restrict__ buf, const float* __restrict__ logA,
                             const float* __restrict__ logdt, const float* __restrict__ seg) {
    int d = blockIdx.x * 32 + threadIdx.x;
    int s = blockIdx.y * 8 + threadIdx.y;
    if (s == 0) return;
    float a = expf(-expf(logA[d]) * expf(logdt[d]));
    float carry = seg[(s - 1) * DD + d];
    float f = a;
    int t0 = s * SEGLEN;
#pragma unroll 8
    for (int tt = 0; tt < SEGLEN; tt++) {
        int i = (t0 + tt) * DD + d;
        buf[i] += f * carry;
        f *= a;
    }
}

// ---------------- combine + rmsnorm + concat ----------------
__global__ void combine_prep_kernel(const float* __restrict__ hseq, const float* __restrict__ udep,
                                    const float* __restrict__ e, const float* __restrict__ logAd,
                                    const float* __restrict__ logdtd, const int* __restrict__ pK,
                                    float* __restrict__ c) {
    int t = blockIdx.x;
    int tid = threadIdx.x;
    int K = *pK;
    float hv[4];
    float ss = 0.f;
#pragma unroll
    for (int r = 0; r < 4; r++) {
        int d = tid + r * 256;
        float g;
        if (d < NMEM) {
            g = (float)K;
        } else {
            float aD = expf(-expf(logAd[d - NMEM]) * expf(logdtd[d - NMEM]));
            float om = 1.f - aD;
            float safe = fmaxf(om, 1e-8f);
            float p = 1.f;
            for (int k = 0; k < K; k++) p *= aD;
            g = (fabsf(om) < 1e-6f) ? (float)K : (1.f - p) / safe;
        }
        float h = hseq[t * DD + d] + g * udep[t * DD + d];
        hv[r] = h;
        ss += h * h;
    }
    __shared__ float red[256];
    red[tid] = ss;
    __syncthreads();
    for (int s = 128; s > 0; s >>= 1) {
        if (tid < s) red[tid] += red[tid + s];
        __syncthreads();
    }
    float sc = rsqrtf(red[0] / (float)DD + RMS_EPS);
#pragma unroll
    for (int r = 0; r < 4; r++) {
        int d = tid + r * 256;
        c[t * 3 * DD + d] = hv[r] * sc;
        c[t * 3 * DD + DD + d] = e[t * DD + d];
        c[t * 3 * DD + 2 * DD + d] = (t > 0) ? e[(t - 1) * DD + d] : 0.f;
    }
}

// ================= LM head GEMM (mma.sync tf32, 3-stage cp.async, k-pair layout) =================
// Inputs A (g_xn) and B (g_Btf) are tf32-rounded AND k-permuted: within each 8-group,
// order is 0,4,1,5,2,6,3,7 so fragment pairs (k, k+4) are adjacent -> 8B LDS.
#define GSTRIDE 40
#define A_STAGE_B (128 * GSTRIDE * 4)  // 20480
#define B_STAGE_B (256 * GSTRIDE * 4)  // 40960
#define NSTG 3
#define LM_SMEM (NSTG * (A_STAGE_B + B_STAGE_B))  // 184320

#define MMA_TF32(c, a, b)                                                              \
    asm volatile(                                                                      \
        "mma.sync.aligned.m16n8k8.row.col.f32.tf32.tf32.f32 "                          \
        "{%0,%1,%2,%3},{%4,%5,%6,%7},{%8,%9},{%0,%1,%2,%3};\n"                         \
        : "+f"(c[0]), "+f"(c[1]), "+f"(c[2]), "+f"(c[3])                               \
        : "r"(a[0]), "r"(a[1]), "r"(a[2]), "r"(a[3]), "r"(b[0]), "r"(b[1]))

__global__ void __launch_bounds__(256, 1)
lmhead_gemm(const float* __restrict__ A, const float* __restrict__ B, float* __restrict__ C) {
    extern __shared__ __align__(16) float smf[];
    const uint32_t smb = smem_u32(smf);
    const int tid = threadIdx.x;
    const int lane = tid & 31;
    const int warp = tid >> 5;
    const int M0 = blockIdx.x * 128;
    const int N0 = blockIdx.y * 256;
    const int nVal = (VV - N0 < 256) ? (VV - N0) : 256;
    const int wm = (warp >> 2) * 64;
    const int wn = (warp & 3) * 64;
    const int rr = lane >> 2;
    const int kc = lane & 3;

    float acc[4][8][4];
#pragma unroll
    for (int i = 0; i < 4; i++)
#pragma unroll
        for (int j = 0; j < 8; j++)
#pragma unroll
            for (int k = 0; k < 4; k++) acc[i][j][k] = 0.f;

#define LOAD_STAGE(s, kb)                                                              \
    {                                                                                  \
        _Pragma("unroll") for (int i = 0; i < 4; i++) {                                \
            int cch = tid + i * 256;                                                   \
            int m = cch >> 3, q = cch & 7;                                             \
            uint32_t dst = smb + (s) * A_STAGE_B + (uint32_t)(m * GSTRIDE + q * 4) * 4;\
            const float* src = A + (size_t)(M0 + m) * DD + (kb) * 32 + q * 4;          \
            cp16(dst, src, 16);                                                        \
        }                                                                              \
        _Pragma("unroll") for (int i = 0; i < 8; i++) {                                \
            int cch = tid + i * 256;                                                   \
            int n = cch >> 3, q = cch & 7;                                             \
            uint32_t dst = smb + NSTG * A_STAGE_B + (s) * B_STAGE_B +                  \
                           (uint32_t)(n * GSTRIDE + q * 4) * 4;                        \
            int ok = (n < nVal);                                                       \
            const float* src = B + (size_t)(N0 + (ok ? n : 0)) * DD + (kb) * 32 + q * 4;\
            cp16(dst, src, ok ? 16 : 0);                                               \
        }                                                                              \
        CP_COMMIT();                                                                   \
    }

    LOAD_STAGE(0, 0);
    LOAD_STAGE(1, 1);

    const int NKB = DD / 32;  // 32
    for (int kb = 0; kb < NKB; kb++) {
        const int s = kb % NSTG;
        if (kb + 1 < NKB) {
            asm volatile("cp.async.wait_group 1;" ::: "memory");
        } else {
            asm volatile("cp.async.wait_group 0;" ::: "memory");
        }
        __syncthreads();
        if (kb + 2 < NKB) LOAD_STAGE((kb + 2) % NSTG, kb + 2);

        const float* As = smf + s * (A_STAGE_B / 4);
        const float* Bs = smf + NSTG * (A_STAGE_B / 4) + s * (B_STAGE_B / 4);

#pragma unroll
        for (int ks = 0; ks < 32; ks += 8) {
            // pair position within permuted k: ks + 2*kc -> values (ks+kc, ks+kc+4)
            const int kp = ks + 2 * kc;
            unsigned af[4][4], bf[8][2];
#pragma unroll
            for (int mi = 0; mi < 4; mi++) {
                float2 pa = *(const float2*)&As[(wm + mi * 16 + rr) * GSTRIDE + kp];
                float2 pb = *(const float2*)&As[(wm + mi * 16 + rr + 8) * GSTRIDE + kp];
                af[mi][0] = __float_as_uint(pa.x);
                af[mi][1] = __float_as_uint(pb.x);
                af[mi][2] = __float_as_uint(pa.y);
                af[mi][3] = __float_as_uint(pb.y);
            }
#pragma unroll
            for (int nj = 0; nj < 8; nj++) {
                float2 qb = *(const float2*)&Bs[(wn + nj * 8 + rr) * GSTRIDE + kp];
                bf[nj][0] = __float_as_uint(qb.x);
                bf[nj][1] = __float_as_uint(qb.y);
            }
#pragma unroll
            for (int mi = 0; mi < 4; mi++)
#pragma unroll
                for (int nj = 0; nj < 8; nj++) MMA_TF32(acc[mi][nj], af[mi], bf[nj]);
        }
    }

    // epilogue
#pragma unroll
    for (int mi = 0; mi < 4; mi++) {
#pragma unroll
        for (int nj = 0; nj < 8; nj++) {
            int c0 = N0 + wn + nj * 8 + (kc << 1);
            if (c0 < VV) {
                size_t r0 = (size_t)(M0 + wm + mi * 16 + rr);
                *(float2*)(C + r0 * VV + c0) = make_float2(acc[mi][nj][0], acc[mi][nj][1]);
                *(float2*)(C + (r0 + 8) * VV + c0) = make_float2(acc[mi][nj][2], acc[mi][nj][3]);
            }
        }
    }
}

// ---------------- launcher ----------------
extern "C" void kernel_launch(void* const* d_in, const int* in_sizes, int n_in,
                              void* d_out, int out_size) {
    const int* idx = (const int*)d_in[0];
    const int* pK = (const int*)d_in[1];
    const float* wte = (const float*)d_in[2];
    const float* wpe = (const float*)d_in[3];
    const float* bseq_w = (const float*)d_in[4];
    const float* logA_seq = (const float*)d_in[5];
    const float* logdt_seq = (const float*)d_in[6];
    const float* bdepth_w = (const float*)d_in[7];
    const float* logA_depth = (const float*)d_in[8];
    const float* logdt_depth = (const float*)d_in[9];
    const float* wpost_w = (const float*)d_in[10];
    const float* wlocal_w = (const float*)d_in[11];
    const float* lowA = (const float*)d_in[12];
    const float* lowB = (const float*)d_in[13];
    const float* lm_head_w = (const float*)d_in[14];
    float* out = (float*)d_out;

    float *x, *e, *h, *ud, *c, *r, *tmp, *xn, *seg, *Btf;
    cudaGetSymbolAddress((void**)&x, g_x);
    cudaGetSymbolAddress((void**)&e, g_e);
    cudaGetSymbolAddress((void**)&h, g_h);
    cudaGetSymbolAddress((void**)&ud, g_ud);
    cudaGetSymbolAddress((void**)&c, g_c);
    cudaGetSymbolAddress((void**)&r, g_r);
    cudaGetSymbolAddress((void**)&tmp, g_tmp);
    cudaGetSymbolAddress((void**)&xn, g_xn);
    cudaGetSymbolAddress((void**)&seg, g_seg);
    cudaGetSymbolAddress((void**)&Btf, g_Btf);

    cudaFuncSetAttribute(lmhead_gemm, cudaFuncAttributeMaxDynamicSharedMemorySize, LM_SMEM);

    // tf32-round + k-pair-permute lm_head weights (one thread per 8 floats)
    tf32_convert_kernel<<<(VV * DD / 8) / 256, 256>>>(lm_head_w, Btf);

    embed_kernel<<<TT, 256>>>(idx, wte, wpe, x);

    for (int l = 0; l < LYR; l++) {
        const float* bseq_l = bseq_w + l * NBLK * 64 * 64;
        const float* lAs = logA_seq + l * HH;
        const float* lDs = logdt_seq + l * HH;
        const float* bdep_l = bdepth_w + l * NBLK * 64 * 64;
        const float* lAd = logA_depth + l * (HH - NMEM);
        const float* lDd = logdt_depth + l * (HH - NMEM);
        const float* wpost_l = wpost_w + l * NBLK * 64 * 192;
        const float* wlocal_l = wlocal_w + l * NBLK * 64 * 64;
        const float* lowA_l = lowA + l * DD * RANKK;
        const float* lowB_l = lowB + l * RANKK * HH;

        rmsnorm_kernel<<<TT, 256>>>(x, e);
        bd64_dual_kernel<<<dim3(TT / 64, NBLK), 256>>>(e, bseq_l, bdep_l, h, ud);
        scanA_kernel<<<dim3(32, 8), dim3(32, 8)>>>(h, lAs, lDs, seg);
        scanB_kernel<<<DD / 16, dim3(16, NSEG)>>>(seg, lAs, lDs);
        scanC_kernel<<<dim3(32, 8), dim3(32, 8)>>>(h, lAs, lDs, seg);
        combine_prep_kernel<<<TT, 256>>>(h, ud, e, lAd, lDd, pK, c);
        bd192_kernel<<<dim3(TT / 64, NBLK), 256>>>(c, wpost_l, r);
        lowrank1_kernel<<<TT / 16, 256>>>(r, lowB_l, tmp);
        update_kernel<<<dim3(TT / 64, NBLK), 256>>>(x, r, tmp, wlocal_l, lowA_l);
    }

    rmsnorm_tf32_kernel<<<TT, 256>>>(x, xn);
    lmhead_gemm<<<dim3(TT / 128, (VV + 255) / 256), 256, LM_SMEM>>>(xn, Btf, out);
}

// round 11
// speedup vs baseline: 2.1426x; 1.4314x over previous
#include <cuda_runtime.h>
#include <cuda_bf16.h>
#include <cuda_fp16.h>
#include <math.h>
#include <stdint.h>

#define TT 2048
#define DD 1024
#define HH 1024
#define NBLK 16
#define LYR 4
#define RANKK 64
#define NMEM 64
#define VV 50304
#define RMS_EPS 1.1920929e-7f
#define SEGLEN 32
#define NSEG 64
#define BSCALE 1024.0f
#define BSCALE_INV 0.0009765625f

// ---------------- scratch (static device arrays; no allocation) ----------------
__device__ float g_x[TT * DD];
__device__ float g_e[TT * DD];
__device__ float g_h[TT * DD];
__device__ float g_ud[TT * DD];
__device__ float g_c[TT * 3 * DD];
__device__ float g_r[TT * DD];
__device__ float g_tmp[TT * RANKK];
__device__ __half g_xh[TT * DD];            // final rmsnorm, fp16, k16-permuted
__device__ float g_seg[NSEG * DD];
__device__ __half g_Bh[(size_t)VV * DD];    // lm_head weights * 1024, fp16, k16-permuted

// ---------------- helpers ----------------
__device__ __forceinline__ float silu_f(float x) { return x / (1.0f + expf(-x)); }

__device__ __forceinline__ uint32_t smem_u32(const void* p) {
    uint32_t a;
    asm("{ .reg .u64 t; cvta.to.shared.u64 t, %1; cvt.u32.u64 %0, t; }" : "=r"(a) : "l"(p));
    return a;
}

__device__ __forceinline__ void cp16(uint32_t dst, const void* src, int sz) {
    asm volatile("cp.async.cg.shared.global [%0], [%1], 16, %2;"
                 :: "r"(dst), "l"(src), "r"(sz) : "memory");
}
#define CP_COMMIT() asm volatile("cp.async.commit_group;" ::: "memory")

// packed f32x2 helpers
__device__ __forceinline__ uint64_t pk2(float x, float y) {
    uint64_t r;
    asm("mov.b64 %0, {%1,%2};" : "=l"(r) : "f"(x), "f"(y));
    return r;
}
__device__ __forceinline__ void up2(float& x, float& y, uint64_t p) {
    asm("mov.b64 {%0,%1}, %2;" : "=f"(x), "=f"(y) : "l"(p));
}
__device__ __forceinline__ uint64_t fma2(uint64_t a, uint64_t b, uint64_t c) {
    uint64_t d;
    asm("fma.rn.f32x2 %0, %1, %2, %3;" : "=l"(d) : "l"(a), "l"(b), "l"(c));
    return d;
}
__device__ __forceinline__ void lds_b64x2(uint64_t& lo, uint64_t& hi, uint32_t addr) {
    asm volatile("ld.shared.v2.b64 {%0,%1}, [%2];" : "=l"(lo), "=l"(hi) : "r"(addr));
}
__device__ __forceinline__ void lds_f32x4(float4& v, uint32_t addr) {
    asm volatile("ld.shared.v4.f32 {%0,%1,%2,%3}, [%4];"
                 : "=f"(v.x), "=f"(v.y), "=f"(v.z), "=f"(v.w) : "r"(addr));
}

// XOR swizzle for layer kernels
__device__ __forceinline__ int swz(int k, int o) {
    return k * 64 + (o ^ (((k >> 2) & 7) << 2));
}

// ---------------- embedding ----------------
__global__ void embed_kernel(const int* __restrict__ idx, const float* __restrict__ wte,
                             const float* __restrict__ wpe, float* __restrict__ x) {
    int t = blockIdx.x;
    int row = idx[t];
    const float4* wrow = (const float4*)(wte + (long)row * DD);
    const float4* prow = (const float4*)(wpe + (long)t * DD);
    float4* xo = (float4*)(x + t * DD);
    for (int d = threadIdx.x; d < DD / 4; d += blockDim.x) {
        float4 a = wrow[d], b = prow[d];
        xo[d] = make_float4(a.x + b.x, a.y + b.y, a.z + b.z, a.w + b.w);
    }
}

// ---------------- rmsnorm ----------------
__global__ void rmsnorm_kernel(const float* __restrict__ in, float* __restrict__ out) {
    int t = blockIdx.x;
    int tid = threadIdx.x;
    float4 v = ((const float4*)(in + t * DD))[tid];
    float ss = v.x * v.x + v.y * v.y + v.z * v.z + v.w * v.w;
    __shared__ float red[256];
    red[tid] = ss;
    __syncthreads();
    for (int s = 128; s > 0; s >>= 1) {
        if (tid < s) red[tid] += red[tid + s];
        __syncthreads();
    }
    float sc = rsqrtf(red[0] / (float)DD + RMS_EPS);
    ((float4*)(out + t * DD))[tid] = make_float4(v.x * sc, v.y * sc, v.z * sc, v.w * sc);
}

// final rmsnorm -> fp16 with k16-group permutation: within each 16-group,
// permuted[4c+0,1]=orig[2c,2c+1], permuted[4c+2,3]=orig[2c+8,2c+9]
__global__ void rmsnorm_f16_kernel(const float* __restrict__ in, __half* __restrict__ out) {
    int t = blockIdx.x;
    int tid = threadIdx.x;
    __shared__ float buf[1024];
    __shared__ float red[256];
    float4 v = ((const float4*)(in + t * DD))[tid];
    *(float4*)&buf[tid * 4] = v;
    red[tid] = v.x * v.x + v.y * v.y + v.z * v.z + v.w * v.w;
    __syncthreads();
    for (int s = 128; s > 0; s >>= 1) {
        if (tid < s) red[tid] += red[tid + s];
        __syncthreads();
    }
    float sc = rsqrtf(red[0] / (float)DD + RMS_EPS);
    int g = tid >> 2, c = tid & 3;
    int base = g * 16 + c * 2;
    __half2 lo = __floats2half2_rn(buf[base] * sc, buf[base + 1] * sc);
    __half2 hi = __floats2half2_rn(buf[base + 8] * sc, buf[base + 9] * sc);
    *(__half2*)(out + t * DD + tid * 4) = lo;
    *(__half2*)(out + t * DD + tid * 4 + 2) = hi;
}

// lm_head weights: *1024, fp16, k16-permuted. One thread per 16-float group.
__global__ void f16_convert_kernel(const float* __restrict__ in, __half* __restrict__ out) {
    size_t i = (size_t)blockIdx.x * blockDim.x + threadIdx.x;  // 16-group index
    const float4* in4 = (const float4*)in + i * 4;
    float f[16];
    *(float4*)&f[0] = in4[0]; *(float4*)&f[4] = in4[1];
    *(float4*)&f[8] = in4[2]; *(float4*)&f[12] = in4[3];
    __half h[16];
#pragma unroll
    for (int c = 0; c < 4; c++) {
        h[4 * c + 0] = __float2half_rn(f[2 * c] * BSCALE);
        h[4 * c + 1] = __float2half_rn(f[2 * c + 1] * BSCALE);
        h[4 * c + 2] = __float2half_rn(f[2 * c + 8] * BSCALE);
        h[4 * c + 3] = __float2half_rn(f[2 * c + 9] * BSCALE);
    }
    uint4* o = (uint4*)(out + i * 16);
    o[0] = *(uint4*)&h[0];
    o[1] = *(uint4*)&h[8];
}

// ============ dual block-diagonal GEMM, K=64, silu (f32x2, swizzled smem) ============
__global__ void __launch_bounds__(256)
bd64_dual_kernel(const float* __restrict__ in, const float* __restrict__ W1,
                 const float* __restrict__ W2, float* __restrict__ out1,
                 float* __restrict__ out2) {
    __shared__ float As[64 * 64];
    __shared__ float Ws1[64 * 64];
    __shared__ float Ws2[64 * 64];
    const int t0 = blockIdx.x * 64;
    const int n = blockIdx.y;
    const int tid = threadIdx.x;
    const int tx = tid & 15, ty = tid >> 4;
    const uint32_t asb = smem_u32(As), w1b = smem_u32(Ws1), w2b = smem_u32(Ws2);

    for (int i = tid; i < 1024; i += 256) {
        int t = i >> 4, kc = (i & 15) << 2;
        float4 v = *(const float4*)&in[(t0 + t) * DD + n * 64 + kc];
        As[swz(kc + 0, t)] = v.x; As[swz(kc + 1, t)] = v.y;
        As[swz(kc + 2, t)] = v.z; As[swz(kc + 3, t)] = v.w;
        float4 w = *(const float4*)&W1[(n * 64 + t) * 64 + kc];
        Ws1[swz(kc + 0, t)] = w.x; Ws1[swz(kc + 1, t)] = w.y;
        Ws1[swz(kc + 2, t)] = w.z; Ws1[swz(kc + 3, t)] = w.w;
        float4 u = *(const float4*)&W2[(n * 64 + t) * 64 + kc];
        Ws2[swz(kc + 0, t)] = u.x; Ws2[swz(kc + 1, t)] = u.y;
        Ws2[swz(kc + 2, t)] = u.z; Ws2[swz(kc + 3, t)] = u.w;
    }
    __syncthreads();

    uint64_t acc1[4][2] = {}, acc2[4][2] = {};
    const int ty4 = ty * 4, tx4 = tx * 4;
#pragma unroll 4
    for (int k = 0; k < 64; k++) {
        const int co = ((k >> 2) & 7) << 2;
        float4 av;
        lds_f32x4(av, asb + (uint32_t)(k * 64 + (ty4 ^ co)) * 4);
        uint64_t a0 = pk2(av.x, av.x), a1 = pk2(av.y, av.y);
        uint64_t a2 = pk2(av.z, av.z), a3 = pk2(av.w, av.w);
        uint64_t b1l, b1h, b2l, b2h;
        lds_b64x2(b1l, b1h, w1b + (uint32_t)(k * 64 + (tx4 ^ co)) * 4);
        lds_b64x2(b2l, b2h, w2b + (uint32_t)(k * 64 + (tx4 ^ co)) * 4);
        acc1[0][0] = fma2(a0, b1l, acc1[0][0]); acc1[0][1] = fma2(a0, b1h, acc1[0][1]);
        acc1[1][0] = fma2(a1, b1l, acc1[1][0]); acc1[1][1] = fma2(a1, b1h, acc1[1][1]);
        acc1[2][0] = fma2(a2, b1l, acc1[2][0]); acc1[2][1] = fma2(a2, b1h, acc1[2][1]);
        acc1[3][0] = fma2(a3, b1l, acc1[3][0]); acc1[3][1] = fma2(a3, b1h, acc1[3][1]);
        acc2[0][0] = fma2(a0, b2l, acc2[0][0]); acc2[0][1] = fma2(a0, b2h, acc2[0][1]);
        acc2[1][0] = fma2(a1, b2l, acc2[1][0]); acc2[1][1] = fma2(a1, b2h, acc2[1][1]);
        acc2[2][0] = fma2(a2, b2l, acc2[2][0]); acc2[2][1] = fma2(a2, b2h, acc2[2][1]);
        acc2[3][0] = fma2(a3, b2l, acc2[3][0]); acc2[3][1] = fma2(a3, b2h, acc2[3][1]);
    }
#pragma unroll
    for (int q = 0; q < 4; q++) {
        int row = t0 + ty4 + q;
        float x0, x1, x2, x3;
        up2(x0, x1, acc1[q][0]); up2(x2, x3, acc1[q][1]);
        *(float4*)&out1[row * HH + n * 64 + tx4] =
            make_float4(silu_f(x0), silu_f(x1), silu_f(x2), silu_f(x3));
        up2(x0, x1, acc2[q][0]); up2(x2, x3, acc2[q][1]);
        *(float4*)&out2[row * HH + n * 64 + tx4] =
            make_float4(silu_f(x0), silu_f(x1), silu_f(x2), silu_f(x3));
    }
}

// ============ block-diagonal GEMM, K=192 (wpost), silu ============
__global__ void __launch_bounds__(256)
bd192_kernel(const float* __restrict__ in, const float* __restrict__ W,
             float* __restrict__ out) {
    __shared__ float As[64 * 64];
    __shared__ float Ws[64 * 64];
    const int t0 = blockIdx.x * 64;
    const int n = blockIdx.y;
    const int tid = threadIdx.x;
    const int tx = tid & 15, ty = tid >> 4;
    const uint32_t asb = smem_u32(As), wsb = smem_u32(Ws);
    const int ty4 = ty * 4, tx4 = tx * 4;

    uint64_t acc[4][2] = {};
    for (int c = 0; c < 3; c++) {
        for (int i = tid; i < 1024; i += 256) {
            int t = i >> 4, kc = (i & 15) << 2;
            float4 v = *(const float4*)&in[(t0 + t) * 3 * DD + n * 192 + c * 64 + kc];
            As[swz(kc + 0, t)] = v.x; As[swz(kc + 1, t)] = v.y;
            As[swz(kc + 2, t)] = v.z; As[swz(kc + 3, t)] = v.w;
            float4 w = *(const float4*)&W[(n * 64 + t) * 192 + c * 64 + kc];
            Ws[swz(kc + 0, t)] = w.x; Ws[swz(kc + 1, t)] = w.y;
            Ws[swz(kc + 2, t)] = w.z; Ws[swz(kc + 3, t)] = w.w;
        }
        __syncthreads();
#pragma unroll 4
        for (int k = 0; k < 64; k++) {
            const int co = ((k >> 2) & 7) << 2;
            float4 av;
            lds_f32x4(av, asb + (uint32_t)(k * 64 + (ty4 ^ co)) * 4);
            uint64_t a0 = pk2(av.x, av.x), a1 = pk2(av.y, av.y);
            uint64_t a2 = pk2(av.z, av.z), a3 = pk2(av.w, av.w);
            uint64_t bl, bh;
            lds_b64x2(bl, bh, wsb + (uint32_t)(k * 64 + (tx4 ^ co)) * 4);
            acc[0][0] = fma2(a0, bl, acc[0][0]); acc[0][1] = fma2(a0, bh, acc[0][1]);
            acc[1][0] = fma2(a1, bl, acc[1][0]); acc[1][1] = fma2(a1, bh, acc[1][1]);
            acc[2][0] = fma2(a2, bl, acc[2][0]); acc[2][1] = fma2(a2, bh, acc[2][1]);
            acc[3][0] = fma2(a3, bl, acc[3][0]); acc[3][1] = fma2(a3, bh, acc[3][1]);
        }
        __syncthreads();
    }
#pragma unroll
    for (int q = 0; q < 4; q++) {
        int row = t0 + ty4 + q;
        float x0, x1, x2, x3;
        up2(x0, x1, acc[q][0]); up2(x2, x3, acc[q][1]);
        *(float4*)&out[row * HH + n * 64 + tx4] =
            make_float4(silu_f(x0), silu_f(x1), silu_f(x2), silu_f(x3));
    }
}

// ============ residual update ============
__global__ void __launch_bounds__(256)
update_kernel(float* __restrict__ x, const float* __restrict__ r,
              const float* __restrict__ tmp, const float* __restrict__ wlocal,
              const float* __restrict__ lowA) {
    __shared__ float As[64 * 64];
    __shared__ float Ws[64 * 64];
    const int t0 = blockIdx.x * 64;
    const int n = blockIdx.y;
    const int tid = threadIdx.x;
    const int tx = tid & 15, ty = tid >> 4;
    const uint32_t asb = smem_u32(As), wsb = smem_u32(Ws);
    const int ty4 = ty * 4, tx4 = tx * 4;

    uint64_t acc[4][2] = {};
    for (int ph = 0; ph < 2; ph++) {
        for (int i = tid; i < 1024; i += 256) {
            int t = i >> 4, kc = (i & 15) << 2;
            float4 v = (ph == 0)
                           ? *(const float4*)&r[(t0 + t) * HH + n * 64 + kc]
                           : *(const float4*)&tmp[(t0 + t) * RANKK + kc];
            As[swz(kc + 0, t)] = v.x; As[swz(kc + 1, t)] = v.y;
            As[swz(kc + 2, t)] = v.z; As[swz(kc + 3, t)] = v.w;
            float4 w = (ph == 0)
                           ? *(const float4*)&wlocal[(n * 64 + t) * 64 + kc]
                           : *(const float4*)&lowA[(n * 64 + t) * RANKK + kc];
            Ws[swz(kc + 0, t)] = w.x; Ws[swz(kc + 1, t)] = w.y;
            Ws[swz(kc + 2, t)] = w.z; Ws[swz(kc + 3, t)] = w.w;
        }
        __syncthreads();
#pragma unroll 4
        for (int k = 0; k < 64; k++) {
            const int co = ((k >> 2) & 7) << 2;
            float4 av;
            lds_f32x4(av, asb + (uint32_t)(k * 64 + (ty4 ^ co)) * 4);
            uint64_t a0 = pk2(av.x, av.x), a1 = pk2(av.y, av.y);
            uint64_t a2 = pk2(av.z, av.z), a3 = pk2(av.w, av.w);
            uint64_t bl, bh;
            lds_b64x2(bl, bh, wsb + (uint32_t)(k * 64 + (tx4 ^ co)) * 4);
            acc[0][0] = fma2(a0, bl, acc[0][0]); acc[0][1] = fma2(a0, bh, acc[0][1]);
            acc[1][0] = fma2(a1, bl, acc[1][0]); acc[1][1] = fma2(a1, bh, acc[1][1]);
            acc[2][0] = fma2(a2, bl, acc[2][0]); acc[2][1] = fma2(a2, bh, acc[2][1]);
            acc[3][0] = fma2(a3, bl, acc[3][0]); acc[3][1] = fma2(a3, bh, acc[3][1]);
        }
        __syncthreads();
    }
#pragma unroll
    for (int q = 0; q < 4; q++) {
        int row = t0 + ty4 + q;
        float x0, x1, x2, x3;
        up2(x0, x1, acc[q][0]); up2(x2, x3, acc[q][1]);
        float4* px = (float4*)&x[row * DD + n * 64 + tx4];
        float4 v = *px;
        v.x += x0; v.y += x1; v.z += x2; v.w += x3;
        *px = v;
    }
}

// ============ lowrank stage 1 ============
__global__ void __launch_bounds__(256)
lowrank1_kernel(const float* __restrict__ r, const float* __restrict__ lowB,
                float* __restrict__ tmp) {
    __shared__ float As[16 * 64];
    __shared__ float Ws[64 * 64];
    const int t0 = blockIdx.x * 16;
    const int tid = threadIdx.x;
    const int tx = tid & 15, ty = tid >> 4;
    const uint32_t wsb = smem_u32(Ws);
    const int tx4 = tx * 4;
    uint64_t acc[2] = {};
    for (int c = 0; c < 16; c++) {
        {
            int t = tid >> 4, kc = (tid & 15) << 2;
            *(float4*)&As[t * 64 + kc] = *(const float4*)&r[(t0 + t) * HH + c * 64 + kc];
        }
        for (int i = tid; i < 1024; i += 256) {
            int o = i >> 4, kc = (i & 15) << 2;
            float4 w = *(const float4*)&lowB[o * HH + c * 64 + kc];
            Ws[swz(kc + 0, o)] = w.x; Ws[swz(kc + 1, o)] = w.y;
            Ws[swz(kc + 2, o)] = w.z; Ws[swz(kc + 3, o)] = w.w;
        }
        __syncthreads();
#pragma unroll 8
        for (int k = 0; k < 64; k++) {
            const int co = ((k >> 2) & 7) << 2;
            float a = As[ty * 64 + k];
            uint64_t ap = pk2(a, a);
            uint64_t bl, bh;
            lds_b64x2(bl, bh, wsb + (uint32_t)(k * 64 + (tx4 ^ co)) * 4);
            acc[0] = fma2(ap, bl, acc[0]);
            acc[1] = fma2(ap, bh, acc[1]);
        }
        __syncthreads();
    }
    float x0, x1, x2, x3;
    up2(x0, x1, acc[0]); up2(x2, x3, acc[1]);
    *(float4*)&tmp[(t0 + ty) * RANKK + tx4] = make_float4(x0, x1, x2, x3);
}

// ============ causal scan, 3-phase chunked ============
__global__ void scanA_kernel(float* __restrict__ buf, const float* __restrict__ logA,
                             const float* __restrict__ logdt, float* __restrict__ seg) {
    int d = blockIdx.x * 32 + threadIdx.x;
    int s = blockIdx.y * 8 + threadIdx.y;
    float a = expf(-expf(logA[d]) * expf(logdt[d]));
    float y = 0.f;
    int t0 = s * SEGLEN;
#pragma unroll 8
    for (int tt = 0; tt < SEGLEN; tt++) {
        int i = (t0 + tt) * DD + d;
        y = a * y + buf[i];
        buf[i] = y;
    }
    seg[s * DD + d] = y;
}

__global__ void scanB_kernel(float* __restrict__ seg, const float* __restrict__ logA,
                             const float* __restrict__ logdt) {
    int d = blockIdx.x * 16 + threadIdx.x;
    int j = threadIdx.y;
    float a = expf(-expf(logA[d]) * expf(logdt[d]));
    float a32 = a;
#pragma unroll
    for (int q = 0; q < 5; q++) a32 *= a32;
    __shared__ float s[NSEG][17];
    float cur = seg[j * DD + d];
    s[j][threadIdx.x] = cur;
    float m = a32;
    for (int st = 1; st < NSEG; st <<= 1) {
        __syncthreads();
        float prev = (j >= st) ? s[j - st][threadIdx.x] : 0.f;
        __syncthreads();
        cur += m * prev;
        s[j][threadIdx.x] = cur;
        m = m * m;
    }
    seg[j * DD + d] = cur;
}

__global__ void scanC_kernel(float* __restrict__ buf, const float* __restrict__ logA,
                             const float* __restrict__ logdt, const float* __restrict__ seg) {
    int d = blockIdx.x * 32 + threadIdx.x;
    int s = blockIdx.y * 8 + threadIdx.y;
    if (s == 0) return;
    float a = expf(-expf(logA[d]) * expf(logdt[d]));
    float carry = seg[(s - 1) * DD + d];
    float f = a;
    int t0 = s * SEGLEN;
#pragma unroll 8
    for (int tt = 0; tt < SEGLEN; tt++) {
        int i = (t0 + tt) * DD + d;
        buf[i] += f * carry;
        f *= a;
    }
}

// ---------------- combine + rmsnorm + concat ----------------
__global__ void combine_prep_kernel(const float* __restrict__ hseq, const float* __restrict__ udep,
                                    const float* __restrict__ e, const float* __restrict__ logAd,
                                    const float* __restrict__ logdtd, const int* __restrict__ pK,
                                    float* __restrict__ c) {
    int t = blockIdx.x;
    int tid = threadIdx.x;
    int K = *pK;
    float hv[4];
    float ss = 0.f;
#pragma unroll
    for (int r = 0; r < 4; r++) {
        int d = tid + r * 256;
        float g;
        if (d < NMEM) {
            g = (float)K;
        } else {
            float aD = expf(-expf(logAd[d - NMEM]) * expf(logdtd[d - NMEM]));
            float om = 1.f - aD;
            float safe = fmaxf(om, 1e-8f);
            float p = 1.f;
            for (int k = 0; k < K; k++) p *= aD;
            g = (fabsf(om) < 1e-6f) ? (float)K : (1.f - p) / safe;
        }
        float h = hseq[t * DD + d] + g * udep[t * DD + d];
        hv[r] = h;
        ss += h * h;
    }
    __shared__ float red[256];
    red[tid] = ss;
    __syncthreads();
    for (int s = 128; s > 0; s >>= 1) {
        if (tid < s) red[tid] += red[tid + s];
        __syncthreads();
    }
    float sc = rsqrtf(red[0] / (float)DD + RMS_EPS);
#pragma unroll
    for (int r = 0; r < 4; r++) {
        int d = tid + r * 256;
        c[t * 3 * DD + d] = hv[r] * sc;
        c[t * 3 * DD + DD + d] = e[t * DD + d];
        c[t * 3 * DD + 2 * DD + d] = (t > 0) ? e[(t - 1) * DD + d] : 0.f;
    }
}

// ================= LM head GEMM (mma.sync fp16 m16n8k16, 3-stage cp.async) =================
// A (g_xh) fp16 k16-permuted; B (g_Bh) fp16 * 1024, k16-permuted. C = (A@B^T)/1024.
// CTA tile 128(M) x 256(N), BK=64 halves, 3-stage cp.async.
// smem rows: 80 halves (160B) stride -> conflict-free LDS.64 fragments.
#define GSTR_H 80
#define A_ST (128 * GSTR_H * 2)  // 20480
#define B_ST (256 * GSTR_H * 2)  // 40960
#define NSTG 3
#define LM_SMEM (NSTG * (A_ST + B_ST))  // 184320

#define MMA_F16(c, a, b)                                                               \
    asm volatile(                                                                      \
        "mma.sync.aligned.m16n8k16.row.col.f32.f16.f16.f32 "                           \
        "{%0,%1,%2,%3},{%4,%5,%6,%7},{%8,%9},{%0,%1,%2,%3};\n"                         \
        : "+f"(c[0]), "+f"(c[1]), "+f"(c[2]), "+f"(c[3])                               \
        : "r"(a[0]), "r"(a[1]), "r"(a[2]), "r"(a[3]), "r"(b[0]), "r"(b[1]))

__global__ void __launch_bounds__(256, 1)
lmhead_gemm(const __half* __restrict__ A, const __half* __restrict__ B, float* __restrict__ C) {
    extern __shared__ __align__(16) char smc[];
    __half* smh = (__half*)smc;
    const uint32_t smb = smem_u32(smc);
    const int tid = threadIdx.x;
    const int lane = tid & 31;
    const int warp = tid >> 5;
    const int M0 = blockIdx.x * 128;
    const int N0 = blockIdx.y * 256;
    const int nVal = (VV - N0 < 256) ? (VV - N0) : 256;
    const int wm = (warp >> 2) * 64;
    const int wn = (warp & 3) * 64;
    const int rr = lane >> 2;
    const int kc = lane & 3;

    float acc[4][8][4];
#pragma unroll
    for (int i = 0; i < 4; i++)
#pragma unroll
        for (int j = 0; j < 8; j++)
#pragma unroll
            for (int k = 0; k < 4; k++) acc[i][j][k] = 0.f;

#define LOAD_STAGE(s, kb)                                                              \
    {                                                                                  \
        _Pragma("unroll") for (int i = 0; i < 4; i++) {                                \
            int cch = tid + i * 256;                                                   \
            int m = cch >> 3, q = cch & 7;                                             \
            uint32_t dst = smb + (s) * A_ST + (uint32_t)(m * GSTR_H + q * 8) * 2;      \
            const __half* src = A + (size_t)(M0 + m) * DD + (kb) * 64 + q * 8;         \
            cp16(dst, src, 16);                                                        \
        }                                                                              \
        _Pragma("unroll") for (int i = 0; i < 8; i++) {                                \
            int cch = tid + i * 256;                                                   \
            int n = cch >> 3, q = cch & 7;                                             \
            uint32_t dst = smb + NSTG * A_ST + (s) * B_ST +                            \
                           (uint32_t)(n * GSTR_H + q * 8) * 2;                         \
            int ok = (n < nVal);                                                       \
            const __half* src = B + (size_t)(N0 + (ok ? n : 0)) * DD + (kb) * 64 + q * 8;\
            cp16(dst, src, ok ? 16 : 0);                                               \
        }                                                                              \
        CP_COMMIT();                                                                   \
    }

    LOAD_STAGE(0, 0);
    LOAD_STAGE(1, 1);

    const int NKB = DD / 64;  // 16
    for (int kb = 0; kb < NKB; kb++) {
        const int s = kb % NSTG;
        if (kb + 1 < NKB) {
            asm volatile("cp.async.wait_group 1;" ::: "memory");
        } else {
            asm volatile("cp.async.wait_group 0;" ::: "memory");
        }
        __syncthreads();
        if (kb + 2 < NKB) LOAD_STAGE((kb + 2) % NSTG, kb + 2);

        const __half* As = smh + s * (A_ST / 2);
        const __half* Bs = smh + NSTG * (A_ST / 2) + s * (B_ST / 2);

#pragma unroll
        for (int ks = 0; ks < 4; ks++) {
            // permuted half offset: group ks, lane pair kc -> 8 bytes holding
            // (2kc,2kc+1) then (2kc+8,2kc+9)
            const int kp = ks * 16 + 4 * kc;
            unsigned af[4][4], bf[8][2];
#pragma unroll
            for (int mi = 0; mi < 4; mi++) {
                uint2 pa = *(const uint2*)&As[(wm + mi * 16 + rr) * GSTR_H + kp];
                uint2 pb = *(const uint2*)&As[(wm + mi * 16 + rr + 8) * GSTR_H + kp];
                af[mi][0] = pa.x;  // (r, 2kc..2kc+1)
                af[mi][1] = pb.x;  // (r+8, 2kc..2kc+1)
                af[mi][2] = pa.y;  // (r, 2kc+8..2kc+9)
                af[mi][3] = pb.y;  // (r+8, 2kc+8..2kc+9)
            }
#pragma unroll
            for (int nj = 0; nj < 8; nj++) {
                uint2 qb = *(const uint2*)&Bs[(wn + nj * 8 + rr) * GSTR_H + kp];
                bf[nj][0] = qb.x;
                bf[nj][1] = qb.y;
            }
#pragma unroll
            for (int mi = 0; mi < 4; mi++)
#pragma unroll
                for (int nj = 0; nj < 8; nj++) MMA_F16(acc[mi][nj], af[mi], bf[nj]);
        }
    }

    // epilogue (undo the 2^10 weight scale)
#pragma unroll
    for (int mi = 0; mi < 4; mi++) {
#pragma unroll
        for (int nj = 0; nj < 8; nj++) {
            int c0 = N0 + wn + nj * 8 + (kc << 1);
            if (c0 < VV) {
                size_t r0 = (size_t)(M0 + wm + mi * 16 + rr);
                *(float2*)(C + r0 * VV + c0) =
                    make_float2(acc[mi][nj][0] * BSCALE_INV, acc[mi][nj][1] * BSCALE_INV);
                *(float2*)(C + (r0 + 8) * VV + c0) =
                    make_float2(acc[mi][nj][2] * BSCALE_INV, acc[mi][nj][3] * BSCALE_INV);
            }
        }
    }
}

// ---------------- launcher ----------------
extern "C" void kernel_launch(void* const* d_in, const int* in_sizes, int n_in,
                              void* d_out, int out_size) {
    const int* idx = (const int*)d_in[0];
    const int* pK = (const int*)d_in[1];
    const float* wte = (const float*)d_in[2];
    const float* wpe = (const float*)d_in[3];
    const float* bseq_w = (const float*)d_in[4];
    const float* logA_seq = (const float*)d_in[5];
    const float* logdt_seq = (const float*)d_in[6];
    const float* bdepth_w = (const float*)d_in[7];
    const float* logA_depth = (const float*)d_in[8];
    const float* logdt_depth = (const float*)d_in[9];
    const float* wpost_w = (const float*)d_in[10];
    const float* wlocal_w = (const float*)d_in[11];
    const float* lowA = (const float*)d_in[12];
    const float* lowB = (const float*)d_in[13];
    const float* lm_head_w = (const float*)d_in[14];
    float* out = (float*)d_out;

    float *x, *e, *h, *ud, *c, *r, *tmp, *seg;
    __half *xh, *Bh;
    cudaGetSymbolAddress((void**)&x, g_x);
    cudaGetSymbolAddress((void**)&e, g_e);
    cudaGetSymbolAddress((void**)&h, g_h);
    cudaGetSymbolAddress((void**)&ud, g_ud);
    cudaGetSymbolAddress((void**)&c, g_c);
    cudaGetSymbolAddress((void**)&r, g_r);
    cudaGetSymbolAddress((void**)&tmp, g_tmp);
    cudaGetSymbolAddress((void**)&xh, g_xh);
    cudaGetSymbolAddress((void**)&seg, g_seg);
    cudaGetSymbolAddress((void**)&Bh, g_Bh);

    cudaFuncSetAttribute(lmhead_gemm, cudaFuncAttributeMaxDynamicSharedMemorySize, LM_SMEM);

    // lm_head weights -> fp16 (*1024), k16-permuted (one thread per 16 floats)
    f16_convert_kernel<<<(VV * DD / 16) / 256, 256>>>(lm_head_w, Bh);

    embed_kernel<<<TT, 256>>>(idx, wte, wpe, x);

    for (int l = 0; l < LYR; l++) {
        const float* bseq_l = bseq_w + l * NBLK * 64 * 64;
        const float* lAs = logA_seq + l * HH;
        const float* lDs = logdt_seq + l * HH;
        const float* bdep_l = bdepth_w + l * NBLK * 64 * 64;
        const float* lAd = logA_depth + l * (HH - NMEM);
        const float* lDd = logdt_depth + l * (HH - NMEM);
        const float* wpost_l = wpost_w + l * NBLK * 64 * 192;
        const float* wlocal_l = wlocal_w + l * NBLK * 64 * 64;
        const float* lowA_l = lowA + l * DD * RANKK;
        const float* lowB_l = lowB + l * RANKK * HH;

        rmsnorm_kernel<<<TT, 256>>>(x, e);
        bd64_dual_kernel<<<dim3(TT / 64, NBLK), 256>>>(e, bseq_l, bdep_l, h, ud);
        scanA_kernel<<<dim3(32, 8), dim3(32, 8)>>>(h, lAs, lDs, seg);
        scanB_kernel<<<DD / 16, dim3(16, NSEG)>>>(seg, lAs, lDs);
        scanC_kernel<<<dim3(32, 8), dim3(32, 8)>>>(h, lAs, lDs, seg);
        combine_prep_kernel<<<TT, 256>>>(h, ud, e, lAd, lDd, pK, c);
        bd192_kernel<<<dim3(TT / 64, NBLK), 256>>>(c, wpost_l, r);
        lowrank1_kernel<<<TT / 16, 256>>>(r, lowB_l, tmp);
        update_kernel<<<dim3(TT / 64, NBLK), 256>>>(x, r, tmp, wlocal_l, lowA_l);
    }

    rmsnorm_f16_kernel<<<TT, 256>>>(x, xh);
    lmhead_gemm<<<dim3(TT / 128, (VV + 255) / 256), 256, LM_SMEM>>>(xh, Bh, out);
}

// round 12
// speedup vs baseline: 2.2730x; 1.0608x over previous
#include <cuda_runtime.h>
#include <cuda_bf16.h>
#include <cuda_fp16.h>
#include <math.h>
#include <stdint.h>

#define TT 2048
#define DD 1024
#define HH 1024
#define NBLK 16
#define LYR 4
#define RANKK 64
#define NMEM 64
#define VV 50304
#define RMS_EPS 1.1920929e-7f
#define SEGLEN 32
#define NSEG 64
#define BSCALE 1024.0f
#define BSCALE_INV 0.0009765625f

// ---------------- scratch (static device arrays; no allocation) ----------------
__device__ float g_x[TT * DD];
__device__ float g_e[TT * DD];
__device__ float g_h[TT * DD];
__device__ float g_ud[TT * DD];
__device__ float g_c[TT * 3 * DD];
__device__ float g_r[TT * DD];
__device__ float g_tmp[TT * RANKK];
__device__ __half g_xh[TT * DD];            // final rmsnorm, fp16, natural layout
__device__ float g_seg[NSEG * DD];
__device__ __half g_Bh[(size_t)VV * DD];    // lm_head weights * 1024, fp16, natural layout

// ---------------- helpers ----------------
__device__ __forceinline__ float silu_f(float x) { return x / (1.0f + expf(-x)); }

__device__ __forceinline__ uint32_t smem_u32(const void* p) {
    uint32_t a;
    asm("{ .reg .u64 t; cvta.to.shared.u64 t, %1; cvt.u32.u64 %0, t; }" : "=r"(a) : "l"(p));
    return a;
}

__device__ __forceinline__ void cp16(uint32_t dst, const void* src, int sz) {
    asm volatile("cp.async.cg.shared.global [%0], [%1], 16, %2;"
                 :: "r"(dst), "l"(src), "r"(sz) : "memory");
}
#define CP_COMMIT() asm volatile("cp.async.commit_group;" ::: "memory")

__device__ __forceinline__ void ldsm_x4(unsigned& r0, unsigned& r1, unsigned& r2, unsigned& r3,
                                        uint32_t addr) {
    asm volatile("ldmatrix.sync.aligned.m8n8.x4.shared.b16 {%0,%1,%2,%3}, [%4];"
                 : "=r"(r0), "=r"(r1), "=r"(r2), "=r"(r3) : "r"(addr));
}

// packed f32x2 helpers
__device__ __forceinline__ uint64_t pk2(float x, float y) {
    uint64_t r;
    asm("mov.b64 %0, {%1,%2};" : "=l"(r) : "f"(x), "f"(y));
    return r;
}
__device__ __forceinline__ void up2(float& x, float& y, uint64_t p) {
    asm("mov.b64 {%0,%1}, %2;" : "=f"(x), "=f"(y) : "l"(p));
}
__device__ __forceinline__ uint64_t fma2(uint64_t a, uint64_t b, uint64_t c) {
    uint64_t d;
    asm("fma.rn.f32x2 %0, %1, %2, %3;" : "=l"(d) : "l"(a), "l"(b), "l"(c));
    return d;
}
__device__ __forceinline__ void lds_b64x2(uint64_t& lo, uint64_t& hi, uint32_t addr) {
    asm volatile("ld.shared.v2.b64 {%0,%1}, [%2];" : "=l"(lo), "=l"(hi) : "r"(addr));
}
__device__ __forceinline__ void lds_f32x4(float4& v, uint32_t addr) {
    asm volatile("ld.shared.v4.f32 {%0,%1,%2,%3}, [%4];"
                 : "=f"(v.x), "=f"(v.y), "=f"(v.z), "=f"(v.w) : "r"(addr));
}

// XOR swizzle for layer kernels
__device__ __forceinline__ int swz(int k, int o) {
    return k * 64 + (o ^ (((k >> 2) & 7) << 2));
}

// ---------------- embedding ----------------
__global__ void embed_kernel(const int* __restrict__ idx, const float* __restrict__ wte,
                             const float* __restrict__ wpe, float* __restrict__ x) {
    int t = blockIdx.x;
    int row = idx[t];
    const float4* wrow = (const float4*)(wte + (long)row * DD);
    const float4* prow = (const float4*)(wpe + (long)t * DD);
    float4* xo = (float4*)(x + t * DD);
    for (int d = threadIdx.x; d < DD / 4; d += blockDim.x) {
        float4 a = wrow[d], b = prow[d];
        xo[d] = make_float4(a.x + b.x, a.y + b.y, a.z + b.z, a.w + b.w);
    }
}

// ---------------- rmsnorm ----------------
__global__ void rmsnorm_kernel(const float* __restrict__ in, float* __restrict__ out) {
    int t = blockIdx.x;
    int tid = threadIdx.x;
    float4 v = ((const float4*)(in + t * DD))[tid];
    float ss = v.x * v.x + v.y * v.y + v.z * v.z + v.w * v.w;
    __shared__ float red[256];
    red[tid] = ss;
    __syncthreads();
    for (int s = 128; s > 0; s >>= 1) {
        if (tid < s) red[tid] += red[tid + s];
        __syncthreads();
    }
    float sc = rsqrtf(red[0] / (float)DD + RMS_EPS);
    ((float4*)(out + t * DD))[tid] = make_float4(v.x * sc, v.y * sc, v.z * sc, v.w * sc);
}

// final rmsnorm -> fp16, natural order
__global__ void rmsnorm_f16_kernel(const float* __restrict__ in, __half* __restrict__ out) {
    int t = blockIdx.x;
    int tid = threadIdx.x;
    float4 v = ((const float4*)(in + t * DD))[tid];
    float ss = v.x * v.x + v.y * v.y + v.z * v.z + v.w * v.w;
    __shared__ float red[256];
    red[tid] = ss;
    __syncthreads();
    for (int s = 128; s > 0; s >>= 1) {
        if (tid < s) red[tid] += red[tid + s];
        __syncthreads();
    }
    float sc = rsqrtf(red[0] / (float)DD + RMS_EPS);
    __half2 h0 = __floats2half2_rn(v.x * sc, v.y * sc);
    __half2 h1 = __floats2half2_rn(v.z * sc, v.w * sc);
    ((__half2*)(out + t * DD))[tid * 2] = h0;
    ((__half2*)(out + t * DD))[tid * 2 + 1] = h1;
}

// lm_head weights: *1024, fp16, natural order. One thread per 8 floats.
__global__ void f16_convert_kernel(const float* __restrict__ in, __half* __restrict__ out) {
    size_t i = (size_t)blockIdx.x * blockDim.x + threadIdx.x;  // 8-float group
    const float4* in4 = (const float4*)in + i * 2;
    float4 a = in4[0], b = in4[1];
    __half h[8];
    h[0] = __float2half_rn(a.x * BSCALE); h[1] = __float2half_rn(a.y * BSCALE);
    h[2] = __float2half_rn(a.z * BSCALE); h[3] = __float2half_rn(a.w * BSCALE);
    h[4] = __float2half_rn(b.x * BSCALE); h[5] = __float2half_rn(b.y * BSCALE);
    h[6] = __float2half_rn(b.z * BSCALE); h[7] = __float2half_rn(b.w * BSCALE);
    ((uint4*)(out + i * 8))[0] = *(uint4*)&h[0];
}

// ============ dual block-diagonal GEMM, K=64, silu (f32x2, swizzled smem) ============
__global__ void __launch_bounds__(256)
bd64_dual_kernel(const float* __restrict__ in, const float* __restrict__ W1,
                 const float* __restrict__ W2, float* __restrict__ out1,
                 float* __restrict__ out2) {
    __shared__ float As[64 * 64];
    __shared__ float Ws1[64 * 64];
    __shared__ float Ws2[64 * 64];
    const int t0 = blockIdx.x * 64;
    const int n = blockIdx.y;
    const int tid = threadIdx.x;
    const int tx = tid & 15, ty = tid >> 4;
    const uint32_t asb = smem_u32(As), w1b = smem_u32(Ws1), w2b = smem_u32(Ws2);

    for (int i = tid; i < 1024; i += 256) {
        int t = i >> 4, kc = (i & 15) << 2;
        float4 v = *(const float4*)&in[(t0 + t) * DD + n * 64 + kc];
        As[swz(kc + 0, t)] = v.x; As[swz(kc + 1, t)] = v.y;
        As[swz(kc + 2, t)] = v.z; As[swz(kc + 3, t)] = v.w;
        float4 w = *(const float4*)&W1[(n * 64 + t) * 64 + kc];
        Ws1[swz(kc + 0, t)] = w.x; Ws1[swz(kc + 1, t)] = w.y;
        Ws1[swz(kc + 2, t)] = w.z; Ws1[swz(kc + 3, t)] = w.w;
        float4 u = *(const float4*)&W2[(n * 64 + t) * 64 + kc];
        Ws2[swz(kc + 0, t)] = u.x; Ws2[swz(kc + 1, t)] = u.y;
        Ws2[swz(kc + 2, t)] = u.z; Ws2[swz(kc + 3, t)] = u.w;
    }
    __syncthreads();

    uint64_t acc1[4][2] = {}, acc2[4][2] = {};
    const int ty4 = ty * 4, tx4 = tx * 4;
#pragma unroll 4
    for (int k = 0; k < 64; k++) {
        const int co = ((k >> 2) & 7) << 2;
        float4 av;
        lds_f32x4(av, asb + (uint32_t)(k * 64 + (ty4 ^ co)) * 4);
        uint64_t a0 = pk2(av.x, av.x), a1 = pk2(av.y, av.y);
        uint64_t a2 = pk2(av.z, av.z), a3 = pk2(av.w, av.w);
        uint64_t b1l, b1h, b2l, b2h;
        lds_b64x2(b1l, b1h, w1b + (uint32_t)(k * 64 + (tx4 ^ co)) * 4);
        lds_b64x2(b2l, b2h, w2b + (uint32_t)(k * 64 + (tx4 ^ co)) * 4);
        acc1[0][0] = fma2(a0, b1l, acc1[0][0]); acc1[0][1] = fma2(a0, b1h, acc1[0][1]);
        acc1[1][0] = fma2(a1, b1l, acc1[1][0]); acc1[1][1] = fma2(a1, b1h, acc1[1][1]);
        acc1[2][0] = fma2(a2, b1l, acc1[2][0]); acc1[2][1] = fma2(a2, b1h, acc1[2][1]);
        acc1[3][0] = fma2(a3, b1l, acc1[3][0]); acc1[3][1] = fma2(a3, b1h, acc1[3][1]);
        acc2[0][0] = fma2(a0, b2l, acc2[0][0]); acc2[0][1] = fma2(a0, b2h, acc2[0][1]);
        acc2[1][0] = fma2(a1, b2l, acc2[1][0]); acc2[1][1] = fma2(a1, b2h, acc2[1][1]);
        acc2[2][0] = fma2(a2, b2l, acc2[2][0]); acc2[2][1] = fma2(a2, b2h, acc2[2][1]);
        acc2[3][0] = fma2(a3, b2l, acc2[3][0]); acc2[3][1] = fma2(a3, b2h, acc2[3][1]);
    }
#pragma unroll
    for (int q = 0; q < 4; q++) {
        int row = t0 + ty4 + q;
        float x0, x1, x2, x3;
        up2(x0, x1, acc1[q][0]); up2(x2, x3, acc1[q][1]);
        *(float4*)&out1[row * HH + n * 64 + tx4] =
            make_float4(silu_f(x0), silu_f(x1), silu_f(x2), silu_f(x3));
        up2(x0, x1, acc2[q][0]); up2(x2, x3, acc2[q][1]);
        *(float4*)&out2[row * HH + n * 64 + tx4] =
            make_float4(silu_f(x0), silu_f(x1), silu_f(x2), silu_f(x3));
    }
}

// ============ block-diagonal GEMM, K=192 (wpost), silu ============
__global__ void __launch_bounds__(256)
bd192_kernel(const float* __restrict__ in, const float* __restrict__ W,
             float* __restrict__ out) {
    __shared__ float As[64 * 64];
    __shared__ float Ws[64 * 64];
    const int t0 = blockIdx.x * 64;
    const int n = blockIdx.y;
    const int tid = threadIdx.x;
    const int tx = tid & 15, ty = tid >> 4;
    const uint32_t asb = smem_u32(As), wsb = smem_u32(Ws);
    const int ty4 = ty * 4, tx4 = tx * 4;

    uint64_t acc[4][2] = {};
    for (int c = 0; c < 3; c++) {
        for (int i = tid; i < 1024; i += 256) {
            int t = i >> 4, kc = (i & 15) << 2;
            float4 v = *(const float4*)&in[(t0 + t) * 3 * DD + n * 192 + c * 64 + kc];
            As[swz(kc + 0, t)] = v.x; As[swz(kc + 1, t)] = v.y;
            As[swz(kc + 2, t)] = v.z; As[swz(kc + 3, t)] = v.w;
            float4 w = *(const float4*)&W[(n * 64 + t) * 192 + c * 64 + kc];
            Ws[swz(kc + 0, t)] = w.x; Ws[swz(kc + 1, t)] = w.y;
            Ws[swz(kc + 2, t)] = w.z; Ws[swz(kc + 3, t)] = w.w;
        }
        __syncthreads();
#pragma unroll 4
        for (int k = 0; k < 64; k++) {
            const int co = ((k >> 2) & 7) << 2;
            float4 av;
            lds_f32x4(av, asb + (uint32_t)(k * 64 + (ty4 ^ co)) * 4);
            uint64_t a0 = pk2(av.x, av.x), a1 = pk2(av.y, av.y);
            uint64_t a2 = pk2(av.z, av.z), a3 = pk2(av.w, av.w);
            uint64_t bl, bh;
            lds_b64x2(bl, bh, wsb + (uint32_t)(k * 64 + (tx4 ^ co)) * 4);
            acc[0][0] = fma2(a0, bl, acc[0][0]); acc[0][1] = fma2(a0, bh, acc[0][1]);
            acc[1][0] = fma2(a1, bl, acc[1][0]); acc[1][1] = fma2(a1, bh, acc[1][1]);
            acc[2][0] = fma2(a2, bl, acc[2][0]); acc[2][1] = fma2(a2, bh, acc[2][1]);
            acc[3][0] = fma2(a3, bl, acc[3][0]); acc[3][1] = fma2(a3, bh, acc[3][1]);
        }
        __syncthreads();
    }
#pragma unroll
    for (int q = 0; q < 4; q++) {
        int row = t0 + ty4 + q;
        float x0, x1, x2, x3;
        up2(x0, x1, acc[q][0]); up2(x2, x3, acc[q][1]);
        *(float4*)&out[row * HH + n * 64 + tx4] =
            make_float4(silu_f(x0), silu_f(x1), silu_f(x2), silu_f(x3));
    }
}

// ============ residual update ============
__global__ void __launch_bounds__(256)
update_kernel(float* __restrict__ x, const float* __restrict__ r,
              const float* __restrict__ tmp, const float* __restrict__ wlocal,
              const float* __restrict__ lowA) {
    __shared__ float As[64 * 64];
    __shared__ float Ws[64 * 64];
    const int t0 = blockIdx.x * 64;
    const int n = blockIdx.y;
    const int tid = threadIdx.x;
    const int tx = tid & 15, ty = tid >> 4;
    const uint32_t asb = smem_u32(As), wsb = smem_u32(Ws);
    const int ty4 = ty * 4, tx4 = tx * 4;

    uint64_t acc[4][2] = {};
    for (int ph = 0; ph < 2; ph++) {
        for (int i = tid; i < 1024; i += 256) {
            int t = i >> 4, kc = (i & 15) << 2;
            float4 v = (ph == 0)
                           ? *(const float4*)&r[(t0 + t) * HH + n * 64 + kc]
                           : *(const float4*)&tmp[(t0 + t) * RANKK + kc];
            As[swz(kc + 0, t)] = v.x; As[swz(kc + 1, t)] = v.y;
            As[swz(kc + 2, t)] = v.z; As[swz(kc + 3, t)] = v.w;
            float4 w = (ph == 0)
                           ? *(const float4*)&wlocal[(n * 64 + t) * 64 + kc]
                           : *(const float4*)&lowA[(n * 64 + t) * RANKK + kc];
            Ws[swz(kc + 0, t)] = w.x; Ws[swz(kc + 1, t)] = w.y;
            Ws[swz(kc + 2, t)] = w.z; Ws[swz(kc + 3, t)] = w.w;
        }
        __syncthreads();
#pragma unroll 4
        for (int k = 0; k < 64; k++) {
            const int co = ((k >> 2) & 7) << 2;
            float4 av;
            lds_f32x4(av, asb + (uint32_t)(k * 64 + (ty4 ^ co)) * 4);
            uint64_t a0 = pk2(av.x, av.x), a1 = pk2(av.y, av.y);
            uint64_t a2 = pk2(av.z, av.z), a3 = pk2(av.w, av.w);
            uint64_t bl, bh;
            lds_b64x2(bl, bh, wsb + (uint32_t)(k * 64 + (tx4 ^ co)) * 4);
            acc[0][0] = fma2(a0, bl, acc[0][0]); acc[0][1] = fma2(a0, bh, acc[0][1]);
            acc[1][0] = fma2(a1, bl, acc[1][0]); acc[1][1] = fma2(a1, bh, acc[1][1]);
            acc[2][0] = fma2(a2, bl, acc[2][0]); acc[2][1] = fma2(a2, bh, acc[2][1]);
            acc[3][0] = fma2(a3, bl, acc[3][0]); acc[3][1] = fma2(a3, bh, acc[3][1]);
        }
        __syncthreads();
    }
#pragma unroll
    for (int q = 0; q < 4; q++) {
        int row = t0 + ty4 + q;
        float x0, x1, x2, x3;
        up2(x0, x1, acc[q][0]); up2(x2, x3, acc[q][1]);
        float4* px = (float4*)&x[row * DD + n * 64 + tx4];
        float4 v = *px;
        v.x += x0; v.y += x1; v.z += x2; v.w += x3;
        *px = v;
    }
}

// ============ lowrank stage 1 ============
__global__ void __launch_bounds__(256)
lowrank1_kernel(const float* __restrict__ r, const float* __restrict__ lowB,
                float* __restrict__ tmp) {
    __shared__ float As[16 * 64];
    __shared__ float Ws[64 * 64];
    const int t0 = blockIdx.x * 16;
    const int tid = threadIdx.x;
    const int tx = tid & 15, ty = tid >> 4;
    const uint32_t wsb = smem_u32(Ws);
    const int tx4 = tx * 4;
    uint64_t acc[2] = {};
    for (int c = 0; c < 16; c++) {
        {
            int t = tid >> 4, kc = (tid & 15) << 2;
            *(float4*)&As[t * 64 + kc] = *(const float4*)&r[(t0 + t) * HH + c * 64 + kc];
        }
        for (int i = tid; i < 1024; i += 256) {
            int o = i >> 4, kc = (i & 15) << 2;
            float4 w = *(const float4*)&lowB[o * HH + c * 64 + kc];
            Ws[swz(kc + 0, o)] = w.x; Ws[swz(kc + 1, o)] = w.y;
            Ws[swz(kc + 2, o)] = w.z; Ws[swz(kc + 3, o)] = w.w;
        }
        __syncthreads();
#pragma unroll 8
        for (int k = 0; k < 64; k++) {
            const int co = ((k >> 2) & 7) << 2;
            float a = As[ty * 64 + k];
            uint64_t ap = pk2(a, a);
            uint64_t bl, bh;
            lds_b64x2(bl, bh, wsb + (uint32_t)(k * 64 + (tx4 ^ co)) * 4);
            acc[0] = fma2(ap, bl, acc[0]);
            acc[1] = fma2(ap, bh, acc[1]);
        }
        __syncthreads();
    }
    float x0, x1, x2, x3;
    up2(x0, x1, acc[0]); up2(x2, x3, acc[1]);
    *(float4*)&tmp[(t0 + ty) * RANKK + tx4] = make_float4(x0, x1, x2, x3);
}

// ============ causal scan, 3-phase chunked ============
__global__ void scanA_kernel(float* __restrict__ buf, const float* __restrict__ logA,
                             const float* __restrict__ logdt, float* __restrict__ seg) {
    int d = blockIdx.x * 32 + threadIdx.x;
    int s = blockIdx.y * 8 + threadIdx.y;
    float a = expf(-expf(logA[d]) * expf(logdt[d]));
    float y = 0.f;
    int t0 = s * SEGLEN;
#pragma unroll 8
    for (int tt = 0; tt < SEGLEN; tt++) {
        int i = (t0 + tt) * DD + d;
        y = a * y + buf[i];
        buf[i] = y;
    }
    seg[s * DD + d] = y;
}

__global__ void scanB_kernel(float* __restrict__ seg, const float* __restrict__ logA,
                             const float* __restrict__ logdt) {
    int d = blockIdx.x * 16 + threadIdx.x;
    int j = threadIdx.y;
    float a = expf(-expf(logA[d]) * expf(logdt[d]));
    float a32 = a;
#pragma unroll
    for (int q = 0; q < 5; q++) a32 *= a32;
    __shared__ float s[NSEG][17];
    float cur = seg[j * DD + d];
    s[j][threadIdx.x] = cur;
    float m = a32;
    for (int st = 1; st < NSEG; st <<= 1) {
        __syncthreads();
        float prev = (j >= st) ? s[j - st][threadIdx.x] : 0.f;
        __syncthreads();
        cur += m * prev;
        s[j][threadIdx.x] = cur;
        m = m * m;
    }
    seg[j * DD + d] = cur;
}

__global__ void scanC_kernel(float* __restrict__ buf, const float* __restrict__ logA,
                             const float* __restrict__ logdt, const float* __restrict__ seg) {
    int d = blockIdx.x * 32 + threadIdx.x;
    int s = blockIdx.y * 8 + threadIdx.y;
    if (s == 0) return;
    float a = expf(-expf(logA[d]) * expf(logdt[d]));
    float carry = seg[(s - 1) * DD + d];
    float f = a;
    int t0 = s * SEGLEN;
#pragma unroll 8
    for (int tt = 0; tt < SEGLEN; tt++) {
        int i = (t0 + tt) * DD + d;
        buf[i] += f * carry;
        f *= a;
    }
}

// ---------------- combine + rmsnorm + concat ----------------
__global__ void combine_prep_kernel(const float* __restrict__ hseq, const float* __restrict__ udep,
                                    const float* __restrict__ e, const float* __restrict__ logAd,
                                    const float* __restrict__ logdtd, const int* __restrict__ pK,
                                    float* __restrict__ c) {
    int t = blockIdx.x;
    int tid = threadIdx.x;
    int K = *pK;
    float hv[4];
    float ss = 0.f;
#pragma unroll
    for (int r = 0; r < 4; r++) {
        int d = tid + r * 256;
        float g;
        if (d < NMEM) {
            g = (float)K;
        } else {
            float aD = expf(-expf(logAd[d - NMEM]) * expf(logdtd[d - NMEM]));
            float om = 1.f - aD;
            float safe = fmaxf(om, 1e-8f);
            float p = 1.f;
            for (int k = 0; k < K; k++) p *= aD;
            g = (fabsf(om) < 1e-6f) ? (float)K : (1.f - p) / safe;
        }
        float h = hseq[t * DD + d] + g * udep[t * DD + d];
        hv[r] = h;
        ss += h * h;
    }
    __shared__ float red[256];
    red[tid] = ss;
    __syncthreads();
    for (int s = 128; s > 0; s >>= 1) {
        if (tid < s) red[tid] += red[tid + s];
        __syncthreads();
    }
    float sc = rsqrtf(red[0] / (float)DD + RMS_EPS);
#pragma unroll
    for (int r = 0; r < 4; r++) {
        int d = tid + r * 256;
        c[t * 3 * DD + d] = hv[r] * sc;
        c[t * 3 * DD + DD + d] = e[t * DD + d];
        c[t * 3 * DD + 2 * DD + d] = (t > 0) ? e[(t - 1) * DD + d] : 0.f;
    }
}

// ================= LM head GEMM (fp16 m16n8k16, ldmatrix + SW128, 4-stage cp.async) =====
// A (g_xh) fp16 natural; B (g_Bh) fp16 * 1024, natural. C = (A@B^T)/1024.
// CTA tile 128(M) x 256(N), BK=64 halves (128B rows = one SW128 atom).
#define A_ST 16384   // 128 rows * 128B
#define B_ST 32768   // 256 rows * 128B
#define NSTG 4
#define LM_SMEM (NSTG * (A_ST + B_ST))  // 196608

#define MMA_F16(c, a, b)                                                               \
    asm volatile(                                                                      \
        "mma.sync.aligned.m16n8k16.row.col.f32.f16.f16.f32 "                           \
        "{%0,%1,%2,%3},{%4,%5,%6,%7},{%8,%9},{%0,%1,%2,%3};\n"                         \
        : "+f"(c[0]), "+f"(c[1]), "+f"(c[2]), "+f"(c[3])                               \
        : "r"(a[0]), "r"(a[1]), "r"(a[2]), "r"(a[3]), "r"(b[0]), "r"(b[1]))

__global__ void __launch_bounds__(256, 1)
lmhead_gemm(const __half* __restrict__ A, const __half* __restrict__ B, float* __restrict__ C) {
    extern __shared__ __align__(16) char smc[];
    const uint32_t smb = smem_u32(smc);
    const int tid = threadIdx.x;
    const int lane = tid & 31;
    const int warp = tid >> 5;
    const int M0 = blockIdx.x * 128;
    const int N0 = blockIdx.y * 256;
    const int nVal = (VV - N0 < 256) ? (VV - N0) : 256;
    const int wm = (warp >> 2) * 64;
    const int wn = (warp & 3) * 64;
    const int rr = lane >> 2;
    const int kc = lane & 3;
    const int l7 = lane & 7;

    float acc[4][8][4];
#pragma unroll
    for (int i = 0; i < 4; i++)
#pragma unroll
        for (int j = 0; j < 8; j++)
#pragma unroll
            for (int k = 0; k < 4; k++) acc[i][j][k] = 0.f;

    // cp.async stage load: SW128 within each 128B row (chunk q at q^(row&7))
#define LOAD_STAGE(s, kb)                                                              \
    {                                                                                  \
        _Pragma("unroll") for (int i = 0; i < 4; i++) {                                \
            int cch = tid + i * 256;                                                   \
            int m = cch >> 3, q = cch & 7;                                             \
            uint32_t dst = smb + (s) * A_ST + (uint32_t)(m * 128 + ((q ^ (m & 7)) << 4));\
            const __half* src = A + (size_t)(M0 + m) * DD + (kb) * 64 + q * 8;         \
            cp16(dst, src, 16);                                                        \
        }                                                                              \
        _Pragma("unroll") for (int i = 0; i < 8; i++) {                                \
            int cch = tid + i * 256;                                                   \
            int n = cch >> 3, q = cch & 7;                                             \
            uint32_t dst = smb + NSTG * A_ST + (s) * B_ST +                            \
                           (uint32_t)(n * 128 + ((q ^ (n & 7)) << 4));                 \
            int ok = (n < nVal);                                                       \
            const __half* src = B + (size_t)(N0 + (ok ? n : 0)) * DD + (kb) * 64 + q * 8;\
            cp16(dst, src, ok ? 16 : 0);                                               \
        }                                                                              \
        CP_COMMIT();                                                                   \
    }

    LOAD_STAGE(0, 0);
    LOAD_STAGE(1, 1);
    LOAD_STAGE(2, 2);

    // ldmatrix per-lane row components (row&7 == lane&7 for both A and B patterns)
    const int a_row = (lane & 15);            // + wm + mi*16
    const int a_kh = lane >> 4;               // k-half selector
    const int b_row = (lane & 7) + ((lane >> 4) & 1) * 8;  // + wn + njp*16
    const int b_kh = (lane >> 3) & 1;

    const int NKB = DD / 64;  // 16
    for (int kb = 0; kb < NKB; kb++) {
        const int s = kb & 3;
        if (kb < NKB - 2) {
            asm volatile("cp.async.wait_group 2;" ::: "memory");
        } else if (kb == NKB - 2) {
            asm volatile("cp.async.wait_group 1;" ::: "memory");
        } else {
            asm volatile("cp.async.wait_group 0;" ::: "memory");
        }
        __syncthreads();
        if (kb + 3 < NKB) LOAD_STAGE((kb + 3) & 3, kb + 3);

        const uint32_t Ab = smb + s * A_ST;
        const uint32_t Bb = smb + NSTG * A_ST + s * B_ST;

#pragma unroll
        for (int ks = 0; ks < 4; ks++) {
            unsigned af[4][4], bf[8][2];
#pragma unroll
            for (int mi = 0; mi < 4; mi++) {
                int row = wm + mi * 16 + a_row;
                int chunk = (ks * 2 + a_kh) ^ l7;
                ldsm_x4(af[mi][0], af[mi][1], af[mi][2], af[mi][3],
                        Ab + (uint32_t)(row * 128 + (chunk << 4)));
            }
#pragma unroll
            for (int njp = 0; njp < 4; njp++) {
                int row = wn + njp * 16 + b_row;
                int chunk = (ks * 2 + b_kh) ^ l7;
                ldsm_x4(bf[2 * njp][0], bf[2 * njp][1], bf[2 * njp + 1][0], bf[2 * njp + 1][1],
                        Bb + (uint32_t)(row * 128 + (chunk << 4)));
            }
#pragma unroll
            for (int mi = 0; mi < 4; mi++)
#pragma unroll
                for (int nj = 0; nj < 8; nj++) MMA_F16(acc[mi][nj], af[mi], bf[nj]);
        }
    }

    // epilogue (undo the 2^10 weight scale)
#pragma unroll
    for (int mi = 0; mi < 4; mi++) {
#pragma unroll
        for (int nj = 0; nj < 8; nj++) {
            int c0 = N0 + wn + nj * 8 + (kc << 1);
            if (c0 < VV) {
                size_t r0 = (size_t)(M0 + wm + mi * 16 + rr);
                *(float2*)(C + r0 * VV + c0) =
                    make_float2(acc[mi][nj][0] * BSCALE_INV, acc[mi][nj][1] * BSCALE_INV);
                *(float2*)(C + (r0 + 8) * VV + c0) =
                    make_float2(acc[mi][nj][2] * BSCALE_INV, acc[mi][nj][3] * BSCALE_INV);
            }
        }
    }
}

// ---------------- launcher ----------------
extern "C" void kernel_launch(void* const* d_in, const int* in_sizes, int n_in,
                              void* d_out, int out_size) {
    const int* idx = (const int*)d_in[0];
    const int* pK = (const int*)d_in[1];
    const float* wte = (const float*)d_in[2];
    const float* wpe = (const float*)d_in[3];
    const float* bseq_w = (const float*)d_in[4];
    const float* logA_seq = (const float*)d_in[5];
    const float* logdt_seq = (const float*)d_in[6];
    const float* bdepth_w = (const float*)d_in[7];
    const float* logA_depth = (const float*)d_in[8];
    const float* logdt_depth = (const float*)d_in[9];
    const float* wpost_w = (const float*)d_in[10];
    const float* wlocal_w = (const float*)d_in[11];
    const float* lowA = (const float*)d_in[12];
    const float* lowB = (const float*)d_in[13];
    const float* lm_head_w = (const float*)d_in[14];
    float* out = (float*)d_out;

    float *x, *e, *h, *ud, *c, *r, *tmp, *seg;
    __half *xh, *Bh;
    cudaGetSymbolAddress((void**)&x, g_x);
    cudaGetSymbolAddress((void**)&e, g_e);
    cudaGetSymbolAddress((void**)&h, g_h);
    cudaGetSymbolAddress((void**)&ud, g_ud);
    cudaGetSymbolAddress((void**)&c, g_c);
    cudaGetSymbolAddress((void**)&r, g_r);
    cudaGetSymbolAddress((void**)&tmp, g_tmp);
    cudaGetSymbolAddress((void**)&xh, g_xh);
    cudaGetSymbolAddress((void**)&seg, g_seg);
    cudaGetSymbolAddress((void**)&Bh, g_Bh);

    cudaFuncSetAttribute(lmhead_gemm, cudaFuncAttributeMaxDynamicSharedMemorySize, LM_SMEM);

    // lm_head weights -> fp16 (*1024), natural layout (one thread per 8 floats)
    f16_convert_kernel<<<(VV * DD / 8) / 256, 256>>>(lm_head_w, Bh);

    embed_kernel<<<TT, 256>>>(idx, wte, wpe, x);

    for (int l = 0; l < LYR; l++) {
        const float* bseq_l = bseq_w + l * NBLK * 64 * 64;
        const float* lAs = logA_seq + l * HH;
        const float* lDs = logdt_seq + l * HH;
        const float* bdep_l = bdepth_w + l * NBLK * 64 * 64;
        const float* lAd = logA_depth + l * (HH - NMEM);
        const float* lDd = logdt_depth + l * (HH - NMEM);
        const float* wpost_l = wpost_w + l * NBLK * 64 * 192;
        const float* wlocal_l = wlocal_w + l * NBLK * 64 * 64;
        const float* lowA_l = lowA + l * DD * RANKK;
        const float* lowB_l = lowB + l * RANKK * HH;

        rmsnorm_kernel<<<TT, 256>>>(x, e);
        bd64_dual_kernel<<<dim3(TT / 64, NBLK), 256>>>(e, bseq_l, bdep_l, h, ud);
        scanA_kernel<<<dim3(32, 8), dim3(32, 8)>>>(h, lAs, lDs, seg);
        scanB_kernel<<<DD / 16, dim3(16, NSEG)>>>(seg, lAs, lDs);
        scanC_kernel<<<dim3(32, 8), dim3(32, 8)>>>(h, lAs, lDs, seg);
        combine_prep_kernel<<<TT, 256>>>(h, ud, e, lAd, lDd, pK, c);
        bd192_kernel<<<dim3(TT / 64, NBLK), 256>>>(c, wpost_l, r);
        lowrank1_kernel<<<TT / 16, 256>>>(r, lowB_l, tmp);
        update_kernel<<<dim3(TT / 64, NBLK), 256>>>(x, r, tmp, wlocal_l, lowA_l);
    }

    rmsnorm_f16_kernel<<<TT, 256>>>(x, xh);
    lmhead_gemm<<<dim3(TT / 128, (VV + 255) / 256), 256, LM_SMEM>>>(xh, Bh, out);
}